// round 4
// baseline (speedup 1.0000x reference)
#include <cuda_runtime.h>
#include <math.h>

// ---------------- problem constants ----------------
#define N1 4096
#define N2 2048
#define PD 256
#define DZ 128
#define PD2 258
#define FD 772
#define EPSF 1e-12f
#define INV_TEMP 0.08838834764831843f   // 1/sqrt(128)

// ---------------- device scratch ----------------
__device__ float g_k[N1 * DZ];
__device__ float g_q[N2 * DZ];
__device__ float g_q2[N2 * DZ];
__device__ float g_S[(size_t)N2 * N1];
__device__ float g_lmf[N1 * PD2];     // exact (for colmean/routerp)
__device__ float g_lmfr[N1 * PD2];    // tf32-rounded (GEMM B operand)
__device__ float g_P[N2 * PD2];       // always tf32-rounded (GEMM-only)
__device__ float g_f1[N2 * PD2];      // exact (output path)
__device__ float g_f2[N2 * PD2];      // exact (output path)
__device__ float g_part[8 * 2048 * 268];
__device__ float g_lmXr[N1 * PD];     // rounded inputs
__device__ float g_tgXr[N2 * PD];
__device__ float g_ffr[N2 * FD];      // rounded final features
__device__ float g_wr[2 * DZ * PD + 2 * PD2 * PD2 + DZ * FD + DZ * PD]; // rounded weights
__device__ float g_router0[PD2];
__device__ float g_routerp[PD2];
__device__ float g_router1[PD2];
__device__ float g_delay[N1];
__device__ float g_dsum;
__device__ float g_rou0[N2];
__device__ float g_rou1[N2];
__device__ float g_asum[N2];
__device__ float g_v2[N1 * 2];

// weight offsets inside g_wr
#define OFF_AKW 0
#define OFF_AQW (OFF_AKW + DZ * PD)
#define OFF_W1W (OFF_AQW + DZ * PD)
#define OFF_W2W (OFF_W1W + PD2 * PD2)
#define OFF_PQW (OFF_W2W + PD2 * PD2)
#define OFF_PKW (OFF_PQW + DZ * FD)

// ---------------- helpers ----------------
__device__ __forceinline__ float fexp(float x) {
    float y;
    asm("ex2.approx.f32 %0, %1;" : "=f"(y) : "f"(x * 1.4426950408889634f));
    return y;
}
__device__ __forceinline__ float rtf32(float x) {
    unsigned r;
    asm("cvt.rna.tf32.f32 %0, %1;" : "=r"(r) : "f"(x));
    return __uint_as_float(r);
}
__device__ __forceinline__ void cp16(float* dst, const float* src, bool valid) {
    unsigned d = (unsigned)__cvta_generic_to_shared(dst);
    int sz = valid ? 16 : 0;
    asm volatile("cp.async.cg.shared.global [%0], [%1], 16, %2;" :: "r"(d), "l"(src), "r"(sz));
}
__device__ __forceinline__ void cp4(float* dst, const float* src, bool valid) {
    unsigned d = (unsigned)__cvta_generic_to_shared(dst);
    int sz = valid ? 4 : 0;
    asm volatile("cp.async.ca.shared.global [%0], [%1], 4, %2;" :: "r"(d), "l"(src), "r"(sz));
}
__device__ __forceinline__ void cp_commit() { asm volatile("cp.async.commit_group;"); }
template<int N_>
__device__ __forceinline__ void cp_wait() {
    asm volatile("cp.async.wait_group %0;" :: "n"(N_));
}

__device__ __forceinline__ float blk_sum(float v, float* red) {
    int t = threadIdx.x;
    red[t] = v; __syncthreads();
    for (int s = blockDim.x >> 1; s > 0; s >>= 1) {
        if (t < s) red[t] += red[t + s];
        __syncthreads();
    }
    float r = red[0]; __syncthreads();
    return r;
}
__device__ __forceinline__ float blk_max(float v, float* red) {
    int t = threadIdx.x;
    red[t] = v; __syncthreads();
    for (int s = blockDim.x >> 1; s > 0; s >>= 1) {
        if (t < s) red[t] = fmaxf(red[t], red[t + s]);
        __syncthreads();
    }
    float r = red[0]; __syncthreads();
    return r;
}

// ---------------- rounding / prep kernels ----------------
__global__ void k_round(const float* __restrict__ src, float* __restrict__ dst, int n) {
    int i = blockIdx.x * blockDim.x + threadIdx.x;
    int i4 = i * 4;
    if (i4 + 3 < n) {
        float4 v = *(const float4*)(src + i4);
        v.x = rtf32(v.x); v.y = rtf32(v.y); v.z = rtf32(v.z); v.w = rtf32(v.w);
        *(float4*)(dst + i4) = v;
    } else {
        for (int j = i4; j < n; j++) dst[j] = rtf32(src[j]);
    }
}

__global__ void k_lmfeat(const float* __restrict__ lm_X, const float* __restrict__ lm_Y) {
    int i = blockIdx.x * blockDim.x + threadIdx.x;
    if (i < N1 * PD2) {
        int r = i / PD2, c = i - r * PD2;
        float v = (c < PD) ? lm_X[r * PD + c] : lm_Y[r * 2 + (c - PD)];
        g_lmf[i] = v;
        g_lmfr[i] = rtf32(v);
    }
}

__global__ void k_colmean() {
    __shared__ float red[256];
    int c = blockIdx.x;
    float s = 0.f;
    for (int r = threadIdx.x; r < N1; r += 256) s += g_lmf[r * PD2 + c];
    s = blk_sum(s, red);
    if (threadIdx.x == 0) g_router0[c] = s * (1.0f / N1);
}

__global__ void k_prep(const float* __restrict__ lm_delay, const float* __restrict__ tg_delay,
                       const float* g1p, const float* g2p, const float* g3p,
                       const float* ap, const float* bp) {
    __shared__ float red[1024];
    float a = ap[0], b = bp[0], g1 = g1p[0], g2 = g2p[0], g3 = g3p[0];
    float local = 0.f;
    for (int i = threadIdx.x; i < N1; i += 1024) {
        float d = fexp(-g1 * (a * lm_delay[i] + b));
        g_delay[i] = d;
        local += d;
    }
    local = blk_sum(local, red);
    if (threadIdx.x == 0) g_dsum = local;
    for (int i = threadIdx.x; i < N2; i += 1024) {
        float t = a * tg_delay[i] + b;
        g_rou0[i] = fexp(-g2 * t);
        g_rou1[i] = fexp(-g3 * t);
    }
}

// ---------------- tf32 GEMM (operands pre-rounded), 3-stage cp.async, split-K ----
#define BM 128
#define BN 128
#define BKT 16
#define AST 20
#define BSTN 132
#define STAGES 3

template<bool BTRANS, bool AVEC16>
__global__ void __launch_bounds__(256)
mma_gemm(const float* __restrict__ A, const float* __restrict__ B,
         const float* __restrict__ bias, float* __restrict__ C,
         int M, int N, int K, float scale)
{
    extern __shared__ float smem_dyn[];
    float* AsB = smem_dyn;
    float* BsB = smem_dyn + STAGES * BM * AST;

    const int tid = threadIdx.x;
    const int warp = tid >> 5, lane = tid & 31;
    const int g = lane >> 2, tig = lane & 3;
    const int wm = (warp & 1) * 64;
    const int wn = (warp >> 1) * 32;
    const int m0 = blockIdx.y * BM, n0 = blockIdx.x * BN;

    const int KT = (K + BKT - 1) / BKT;
    const int SPLIT = gridDim.z;
    const int KTs = (KT + SPLIT - 1) / SPLIT;
    const int kt0 = blockIdx.z * KTs;
    const int kt1 = min(KT, kt0 + KTs);
    const int nk = kt1 - kt0;

    float acc[4][4][4];
#pragma unroll
    for (int i = 0; i < 4; i++)
#pragma unroll
        for (int j = 0; j < 4; j++)
#pragma unroll
            for (int c = 0; c < 4; c++) acc[i][j][c] = 0.f;

    auto loadStage = [&](int kt, int st) {
        int k0 = kt * BKT;
        float* as = AsB + st * BM * AST;
        if (AVEC16) {
#pragma unroll
            for (int p = 0; p < 2; p++) {
                int c = tid + 256 * p;
                int row = c >> 2, kq = (c & 3) * 4;
                cp16(as + row * AST + kq, A + (size_t)(m0 + row) * K + k0 + kq,
                     (k0 + kq) < K);
            }
        } else {
#pragma unroll
            for (int p = 0; p < 8; p++) {
                int e = tid + 256 * p;
                int row = e >> 4, kk = e & 15;
                cp4(as + row * AST + kk, A + (size_t)(m0 + row) * K + k0 + kk,
                    (k0 + kk) < K);
            }
        }
        if (BTRANS) {
            float* bs = BsB + st * BN * AST;
            if (AVEC16) {
#pragma unroll
                for (int p = 0; p < 2; p++) {
                    int c = tid + 256 * p;
                    int row = c >> 2, kq = (c & 3) * 4;
                    bool v = (n0 + row) < N && (k0 + kq) < K;
                    cp16(bs + row * AST + kq, B + (size_t)(n0 + row) * K + k0 + kq, v);
                }
            } else {
#pragma unroll
                for (int p = 0; p < 8; p++) {
                    int e = tid + 256 * p;
                    int row = e >> 4, kk = e & 15;
                    bool v = (n0 + row) < N && (k0 + kk) < K;
                    cp4(bs + row * AST + kk, B + (size_t)(n0 + row) * K + k0 + kk, v);
                }
            }
        } else {
            float* bs = BsB + st * BKT * BSTN;
#pragma unroll
            for (int p = 0; p < 8; p++) {
                int e = tid + 256 * p;
                int kk = e >> 7, n = e & 127;
                bool v = (k0 + kk) < K && (n0 + n) < N;
                cp4(bs + kk * BSTN + n, B + (size_t)(k0 + kk) * N + n0 + n, v);
            }
        }
        cp_commit();
    };

#pragma unroll
    for (int s = 0; s < STAGES - 1; s++) {
        if (s < nk) loadStage(kt0 + s, s);
        else cp_commit();
    }

    int st = 0;
    for (int i = 0; i < nk; i++) {
        cp_wait<STAGES - 2>();
        __syncthreads();

        int j = i + STAGES - 1;
        if (j < nk) loadStage(kt0 + j, (st + STAGES - 1) % STAGES);
        else cp_commit();

        const float* as = AsB + st * BM * AST;
        const float* bsT = BsB + st * BN * AST;
        const float* bsN = BsB + st * BKT * BSTN;
        st = (st + 1) % STAGES;

#pragma unroll
        for (int ks = 0; ks < 2; ks++) {
            unsigned af[4][4], bf[4][2];
#pragma unroll
            for (int mi = 0; mi < 4; mi++) {
                const float* pa = as + (wm + mi * 16 + g) * AST + ks * 8 + tig;
                af[mi][0] = __float_as_uint(pa[0]);
                af[mi][1] = __float_as_uint(pa[8 * AST]);
                af[mi][2] = __float_as_uint(pa[4]);
                af[mi][3] = __float_as_uint(pa[8 * AST + 4]);
            }
#pragma unroll
            for (int ni = 0; ni < 4; ni++) {
                if (BTRANS) {
                    const float* pb = bsT + (wn + ni * 8 + g) * AST + ks * 8 + tig;
                    bf[ni][0] = __float_as_uint(pb[0]);
                    bf[ni][1] = __float_as_uint(pb[4]);
                } else {
                    const float* pb = bsN + (ks * 8 + tig) * BSTN + wn + ni * 8 + g;
                    bf[ni][0] = __float_as_uint(pb[0]);
                    bf[ni][1] = __float_as_uint(pb[4 * BSTN]);
                }
            }
#pragma unroll
            for (int mi = 0; mi < 4; mi++)
#pragma unroll
                for (int ni = 0; ni < 4; ni++) {
                    asm volatile(
                        "mma.sync.aligned.m16n8k8.row.col.f32.tf32.tf32.f32 "
                        "{%0,%1,%2,%3}, {%4,%5,%6,%7}, {%8,%9}, {%0,%1,%2,%3};"
                        : "+f"(acc[mi][ni][0]), "+f"(acc[mi][ni][1]),
                          "+f"(acc[mi][ni][2]), "+f"(acc[mi][ni][3])
                        : "r"(af[mi][0]), "r"(af[mi][1]), "r"(af[mi][2]), "r"(af[mi][3]),
                          "r"(bf[ni][0]), "r"(bf[ni][1]));
                }
        }
    }

    const bool split = (gridDim.z > 1);
    float* outp = split ? (C + (size_t)blockIdx.z * M * N) : C;
#pragma unroll
    for (int mi = 0; mi < 4; mi++) {
        int mrow0 = m0 + wm + mi * 16 + g;
#pragma unroll
        for (int ni = 0; ni < 4; ni++) {
            int ncol = n0 + wn + ni * 8 + 2 * tig;
#pragma unroll
            for (int h = 0; h < 2; h++) {
                int mr = mrow0 + h * 8;
                if (split) {
                    if (ncol < N)     outp[(size_t)mr * N + ncol]     = acc[mi][ni][h*2+0];
                    if (ncol + 1 < N) outp[(size_t)mr * N + ncol + 1] = acc[mi][ni][h*2+1];
                } else {
                    if (ncol < N) {
                        float bv = bias ? bias[ncol] : 0.f;
                        outp[(size_t)mr * N + ncol] = acc[mi][ni][h*2+0] * scale + bv;
                    }
                    if (ncol + 1 < N) {
                        float bv = bias ? bias[ncol + 1] : 0.f;
                        outp[(size_t)mr * N + ncol + 1] = acc[mi][ni][h*2+1] * scale + bv;
                    }
                }
            }
        }
    }
}

// deterministic split-K reduce; optional tf32 rounding of result
__global__ void k_reduce(const float* __restrict__ part, const float* __restrict__ bias,
                         float* __restrict__ C, int M, int N, int S, float scale, int rnd) {
    int i = blockIdx.x * blockDim.x + threadIdx.x;
    if (i < M * N) {
        int n = i % N;
        float s = 0.f;
        for (int z = 0; z < S; z++) s += part[(size_t)z * M * N + i];
        float v = s * scale + (bias ? bias[n] : 0.f);
        C[i] = rnd ? rtf32(v) : v;
    }
}

// ---------------- attention 1 ----------------
__global__ void k_attr() {
    __shared__ float red[256];
    int r = blockIdx.x;
    float* s = g_S + (size_t)r * N1;
    int t = threadIdx.x;
    float e[16];
    float m = -1e30f;
#pragma unroll
    for (int i = 0; i < 16; i++) { e[i] = s[t + i * 256]; m = fmaxf(m, e[i]); }
    m = blk_max(m, red);
    float z = 0.f;
#pragma unroll
    for (int i = 0; i < 16; i++) { e[i] = fexp(e[i] - m); z += e[i]; }
    z = blk_sum(z, red);
    float inv = 1.f / z;
    float rs = 0.f;
#pragma unroll
    for (int i = 0; i < 16; i++) {
        float v = fexp(e[i] * inv);
        s[t + i * 256] = rtf32(v);
        rs += v;
    }
    rs = blk_sum(rs, red);
    if (t == 0) g_asum[r] = rs;
}

// ---------------- propagation elementwise ----------------
__global__ void k_prop0(const float* __restrict__ tg_X) {
    int i = blockIdx.x * blockDim.x + threadIdx.x;
    if (i < N2 * PD2) {
        int r = i / PD2, c = i - r * PD2;
        float num = g_P[i] + (c < PD ? tg_X[r * PD + c] : 0.f) + g_rou0[r] * g_router0[c];
        g_P[i] = rtf32(num / (1.f + g_asum[r] + g_rou0[r] + EPSF));
    }
}

__global__ void k_routerp() {
    __shared__ float red[256];
    int c = blockIdx.x;
    float s = 0.f;
    for (int r = threadIdx.x; r < N1; r += 256) s += g_delay[r] * g_lmf[r * PD2 + c];
    s = blk_sum(s, red);
    if (threadIdx.x == 0)
        g_routerp[c] = (s + g_router0[c]) / (1.f + g_dsum + EPSF);
}

__global__ void k_router1(const float* __restrict__ w1_w, const float* __restrict__ w1_b) {
    int j = threadIdx.x;
    if (j < PD2) {
        float s = w1_b[j];
        for (int k = 0; k < PD2; k++) s += g_routerp[k] * w1_w[j * PD2 + k];
        g_router1[j] = s;
    }
}

__global__ void k_prop1() {
    int i = blockIdx.x * blockDim.x + threadIdx.x;
    if (i < N2 * PD2) {
        int r = i / PD2, c = i - r * PD2;
        g_P[i] = rtf32((g_f1[i] + g_rou1[r] * g_router1[c]) / (1.f + g_rou1[r] + EPSF));
    }
}

__global__ void k_final(const float* __restrict__ tg_X, float* __restrict__ out) {
    int i = blockIdx.x * blockDim.x + threadIdx.x;
    if (i < N2 * FD) {
        int r = i / FD, c = i - r * FD;
        float v;
        if (c < PD)             v = tg_X[r * PD + c];
        else if (c < PD + PD2)  v = g_f1[r * PD2 + (c - PD)];
        else                    v = g_f2[r * PD2 + (c - PD - PD2)];
        out[N2 * 2 + i] = v;
        g_ffr[i] = rtf32(v);
    }
}

__global__ void k_v2(const float* __restrict__ lm_Y,
                     const float* __restrict__ pv_w, const float* __restrict__ pv_b) {
    int i = blockIdx.x * blockDim.x + threadIdx.x;
    if (i < N1) {
        float y0 = lm_Y[2 * i], y1 = lm_Y[2 * i + 1];
        g_v2[2 * i]     = pv_w[0] * y0 + pv_w[1] * y1 + pv_b[0];
        g_v2[2 * i + 1] = pv_w[2] * y0 + pv_w[3] * y1 + pv_b[1];
    }
}

__global__ void k_attn2(float* __restrict__ out) {
    __shared__ float red[256];
    int r = blockIdx.x;
    const float* s = g_S + (size_t)r * N1;
    int t = threadIdx.x;
    float e[16];
    float m = -1e30f;
#pragma unroll
    for (int i = 0; i < 16; i++) { e[i] = s[t + i * 256]; m = fmaxf(m, e[i]); }
    m = blk_max(m, red);
    float sw = 0.f, s0 = 0.f, s1 = 0.f;
#pragma unroll
    for (int i = 0; i < 16; i++) {
        int idx = t + i * 256;
        float w = fexp(e[i] - m);
        sw += w;
        s0 += w * g_v2[2 * idx];
        s1 += w * g_v2[2 * idx + 1];
    }
    sw = blk_sum(sw, red);
    s0 = blk_sum(s0, red);
    s1 = blk_sum(s1, red);
    if (t == 0) {
        out[2 * r]     = s0 / sw;
        out[2 * r + 1] = s1 / sw;
    }
}

// ---------------- host launch ----------------
static float* sym_addr(const void* s) {
    void* p = nullptr;
    cudaGetSymbolAddress(&p, s);
    return (float*)p;
}

#define SMEM_TT ((STAGES * BM * AST + STAGES * BN * AST) * 4)
#define SMEM_FF ((STAGES * BM * AST + STAGES * BKT * BSTN) * 4)

extern "C" void kernel_launch(void* const* d_in, const int* in_sizes, int n_in,
                              void* d_out, int out_size) {
    const float* lm_X    = (const float*)d_in[0];
    const float* lm_Y    = (const float*)d_in[1];
    const float* tg_X    = (const float*)d_in[2];
    const float* lm_delay= (const float*)d_in[4];
    const float* tg_delay= (const float*)d_in[5];
    const float* aq_w    = (const float*)d_in[6];
    const float* aq_b    = (const float*)d_in[7];
    const float* ak_w    = (const float*)d_in[8];
    const float* ak_b    = (const float*)d_in[9];
    const float* w1_w    = (const float*)d_in[10];
    const float* w1_b    = (const float*)d_in[11];
    const float* w2_w    = (const float*)d_in[12];
    const float* w2_b    = (const float*)d_in[13];
    const float* pq_w    = (const float*)d_in[14];
    const float* pq_b    = (const float*)d_in[15];
    const float* pk_w    = (const float*)d_in[16];
    const float* pk_b    = (const float*)d_in[17];
    const float* pv_w    = (const float*)d_in[18];
    const float* pv_b    = (const float*)d_in[19];
    const float* gamma1  = (const float*)d_in[20];
    const float* gamma2  = (const float*)d_in[21];
    const float* gamma3  = (const float*)d_in[22];
    const float* alpha   = (const float*)d_in[23];
    const float* beta    = (const float*)d_in[24];
    float* out = (float*)d_out;

    float* pk    = sym_addr(g_k);
    float* pq    = sym_addr(g_q);
    float* pq2   = sym_addr(g_q2);
    float* pS    = sym_addr(g_S);
    float* plmfr = sym_addr(g_lmfr);
    float* pP    = sym_addr(g_P);
    float* pf1   = sym_addr(g_f1);
    float* pf2   = sym_addr(g_f2);
    float* pPart = sym_addr(g_part);
    float* plmXr = sym_addr(g_lmXr);
    float* ptgXr = sym_addr(g_tgXr);
    float* pffr  = sym_addr(g_ffr);
    float* pwr   = sym_addr(g_wr);

    cudaFuncSetAttribute(mma_gemm<true, true>,  cudaFuncAttributeMaxDynamicSharedMemorySize, SMEM_TT);
    cudaFuncSetAttribute(mma_gemm<true, false>, cudaFuncAttributeMaxDynamicSharedMemorySize, SMEM_TT);
    cudaFuncSetAttribute(mma_gemm<false, true>, cudaFuncAttributeMaxDynamicSharedMemorySize, SMEM_FF);

    dim3 blk(256);
    auto grd = [](int M, int N, int S) {
        return dim3((N + BN - 1) / BN, (M + BM - 1) / BM, S);
    };
    auto rnd = [&](const float* src, float* dst, int n) {
        k_round<<<(n / 4 + 255) / 256, blk>>>(src, dst, n);
    };
    auto redu = [&](float* dst, const float* bias, int M, int N, int S, float scale, int r) {
        k_reduce<<<(M * N + 255) / 256, blk>>>(pPart, bias, dst, M, N, S, scale, r);
    };

    // prep + rounded operand copies
    k_lmfeat<<<(N1 * PD2 + 255) / 256, blk>>>(lm_X, lm_Y);
    k_colmean<<<PD2, blk>>>();
    k_prep<<<1, 1024>>>(lm_delay, tg_delay, gamma1, gamma2, gamma3, alpha, beta);
    rnd(lm_X, plmXr, N1 * PD);
    rnd(tg_X, ptgXr, N2 * PD);
    rnd(ak_w, pwr + OFF_AKW, DZ * PD);
    rnd(aq_w, pwr + OFF_AQW, DZ * PD);
    rnd(w1_w, pwr + OFF_W1W, PD2 * PD2);
    rnd(w2_w, pwr + OFF_W2W, PD2 * PD2);
    rnd(pq_w, pwr + OFF_PQW, DZ * FD);
    rnd(pk_w, pwr + OFF_PKW, DZ * PD);

    // attention 1
    mma_gemm<true, true><<<grd(N1, DZ, 4), blk, SMEM_TT>>>(plmXr, pwr + OFF_AKW, nullptr, pPart, N1, DZ, PD, 1.f);
    redu(pk, ak_b, N1, DZ, 4, 1.f, 1);
    mma_gemm<true, true><<<grd(N2, DZ, 8), blk, SMEM_TT>>>(ptgXr, pwr + OFF_AQW, nullptr, pPart, N2, DZ, PD, 1.f);
    redu(pq, aq_b, N2, DZ, 8, 1.f, 1);
    mma_gemm<true, true><<<grd(N2, N1, 1), blk, SMEM_TT>>>(pq, pk, nullptr, pS, N2, N1, DZ, INV_TEMP);
    k_attr<<<N2, blk>>>();

    // propagation 0
    mma_gemm<false, true><<<grd(N2, PD2, 4), blk, SMEM_FF>>>(pS, plmfr, nullptr, pPart, N2, PD2, N1, 1.f);
    redu(pP, nullptr, N2, PD2, 4, 1.f, 0);
    k_prop0<<<(N2 * PD2 + 255) / 256, blk>>>(tg_X);
    k_routerp<<<PD2, blk>>>();
    k_router1<<<1, PD2>>>(w1_w, w1_b);

    // layer 1 + propagation 1 + layer 2
    mma_gemm<true, false><<<grd(N2, PD2, 4), blk, SMEM_TT>>>(pP, pwr + OFF_W1W, nullptr, pPart, N2, PD2, PD2, 1.f);
    redu(pf1, w1_b, N2, PD2, 4, 1.f, 0);
    k_prop1<<<(N2 * PD2 + 255) / 256, blk>>>();
    mma_gemm<true, false><<<grd(N2, PD2, 4), blk, SMEM_TT>>>(pP, pwr + OFF_W2W, nullptr, pPart, N2, PD2, PD2, 1.f);
    redu(pf2, w2_b, N2, PD2, 4, 1.f, 0);

    // final features + attention 2
    k_final<<<(N2 * FD + 255) / 256, blk>>>(tg_X, out);
    mma_gemm<true, true><<<grd(N2, DZ, 8), blk, SMEM_TT>>>(pffr, pwr + OFF_PQW, nullptr, pPart, N2, DZ, FD, 1.f);
    redu(pq2, pq_b, N2, DZ, 8, 1.f, 1);
    mma_gemm<true, true><<<grd(N1, DZ, 4), blk, SMEM_TT>>>(plmXr, pwr + OFF_PKW, nullptr, pPart, N1, DZ, PD, 1.f);
    redu(pk, pk_b, N1, DZ, 4, 1.f, 1);
    k_v2<<<(N1 + 255) / 256, blk>>>(lm_Y, pv_w, pv_b);
    mma_gemm<true, true><<<grd(N2, N1, 1), blk, SMEM_TT>>>(pq2, pk, nullptr, pS, N2, N1, DZ, INV_TEMP);
    k_attn2<<<N2, blk>>>(out);
}

// round 5
// speedup vs baseline: 1.0664x; 1.0664x over previous
#include <cuda_runtime.h>
#include <math.h>

// ---------------- problem constants ----------------
#define N1 4096
#define N2 2048
#define PD 256
#define DZ 128
#define PD2 258
#define FD 772
#define EPSF 1e-12f
#define INV_TEMP 0.08838834764831843f   // 1/sqrt(128)

// ---------------- device scratch ----------------
__device__ float g_k12[N1 * 2 * DZ];   // [k1 | k2] projections, row stride 256
__device__ float g_q[N2 * DZ];
__device__ float g_q2[N2 * DZ];
__device__ float g_S[(size_t)N2 * N1];
__device__ float g_lmf[N1 * PD2];
__device__ float g_P[N2 * PD2];
__device__ float g_part[8 * 2048 * 268];   // split-K partials (17.6 MB)
__device__ float g_wcat[2 * DZ * PD];      // [ak_w ; pk_w]
__device__ float g_bcat[2 * DZ];           // [ak_b ; pk_b]
__device__ float g_router0[PD2];
__device__ float g_routerp[PD2];
__device__ float g_router1[PD2];
__device__ float g_delay[N1];
__device__ float g_dsum;
__device__ float g_rou0[N2];
__device__ float g_rou1[N2];
__device__ float g_asum[N2];
__device__ float g_v2[N1 * 2];

// ---------------- helpers ----------------
__device__ __forceinline__ float fexp(float x) {
    float y;
    asm("ex2.approx.f32 %0, %1;" : "=f"(y) : "f"(x * 1.4426950408889634f));
    return y;
}
__device__ __forceinline__ unsigned f2tf32(float x) {
    unsigned r;
    asm("cvt.rna.tf32.f32 %0, %1;" : "=r"(r) : "f"(x));
    return r;
}
__device__ __forceinline__ void cp16(float* dst, const float* src, bool valid) {
    unsigned d = (unsigned)__cvta_generic_to_shared(dst);
    int sz = valid ? 16 : 0;
    asm volatile("cp.async.cg.shared.global [%0], [%1], 16, %2;" :: "r"(d), "l"(src), "r"(sz));
}
__device__ __forceinline__ void cp4(float* dst, const float* src, bool valid) {
    unsigned d = (unsigned)__cvta_generic_to_shared(dst);
    int sz = valid ? 4 : 0;
    asm volatile("cp.async.ca.shared.global [%0], [%1], 4, %2;" :: "r"(d), "l"(src), "r"(sz));
}
__device__ __forceinline__ void cp_commit() { asm volatile("cp.async.commit_group;"); }
template<int N_>
__device__ __forceinline__ void cp_wait() {
    asm volatile("cp.async.wait_group %0;" :: "n"(N_));
}

__device__ __forceinline__ float blk_sum(float v, float* red) {
    int t = threadIdx.x;
    red[t] = v; __syncthreads();
    for (int s = blockDim.x >> 1; s > 0; s >>= 1) {
        if (t < s) red[t] += red[t + s];
        __syncthreads();
    }
    float r = red[0]; __syncthreads();
    return r;
}
__device__ __forceinline__ float blk_max(float v, float* red) {
    int t = threadIdx.x;
    red[t] = v; __syncthreads();
    for (int s = blockDim.x >> 1; s > 0; s >>= 1) {
        if (t < s) red[t] = fmaxf(red[t], red[t + s]);
        __syncthreads();
    }
    float r = red[0]; __syncthreads();
    return r;
}

// ---------------- prep kernels ----------------
// lm_feature assembly + tg_X copy into d_out feature block
__global__ void k_misc(const float* __restrict__ lm_X, const float* __restrict__ lm_Y,
                       const float* __restrict__ tg_X, float* __restrict__ out) {
    int i = blockIdx.x * blockDim.x + threadIdx.x;
    if (i < N1 * PD2) {
        int r = i / PD2, c = i - r * PD2;
        g_lmf[i] = (c < PD) ? lm_X[r * PD + c] : lm_Y[r * 2 + (c - PD)];
    } else {
        int j = i - N1 * PD2;
        if (j < N2 * PD) {
            int r = j / PD, c = j - r * PD;
            out[N2 * 2 + r * FD + c] = tg_X[j];
        }
    }
}

__global__ void k_colmean(const float* __restrict__ lm_X, const float* __restrict__ lm_Y) {
    __shared__ float red[256];
    int c = blockIdx.x;
    float s = 0.f;
    if (c < PD) {
        for (int r = threadIdx.x; r < N1; r += 256) s += lm_X[r * PD + c];
    } else {
        for (int r = threadIdx.x; r < N1; r += 256) s += lm_Y[r * 2 + (c - PD)];
    }
    s = blk_sum(s, red);
    if (threadIdx.x == 0) g_router0[c] = s * (1.0f / N1);
}

__global__ void k_prep(const float* __restrict__ lm_delay, const float* __restrict__ tg_delay,
                       const float* g1p, const float* g2p, const float* g3p,
                       const float* ap, const float* bp) {
    __shared__ float red[1024];
    float a = ap[0], b = bp[0], g1 = g1p[0], g2 = g2p[0], g3 = g3p[0];
    float local = 0.f;
    for (int i = threadIdx.x; i < N1; i += 1024) {
        float d = fexp(-g1 * (a * lm_delay[i] + b));
        g_delay[i] = d;
        local += d;
    }
    local = blk_sum(local, red);
    if (threadIdx.x == 0) g_dsum = local;
    for (int i = threadIdx.x; i < N2; i += 1024) {
        float t = a * tg_delay[i] + b;
        g_rou0[i] = fexp(-g2 * t);
        g_rou1[i] = fexp(-g3 * t);
    }
}

// concat [ak_w ; pk_w] and biases
__global__ void k_wcat(const float* __restrict__ ak_w, const float* __restrict__ pk_w,
                       const float* __restrict__ ak_b, const float* __restrict__ pk_b) {
    int i = blockIdx.x * blockDim.x + threadIdx.x;
    if (i < DZ * PD) g_wcat[i] = ak_w[i];
    else if (i < 2 * DZ * PD) g_wcat[i] = pk_w[i - DZ * PD];
    if (i < DZ) g_bcat[i] = ak_b[i];
    else if (i < 2 * DZ) g_bcat[i] = pk_b[i - DZ];
}

// ---------------- tf32 GEMM, 4-stage cp.async, split-K, strided operands ------
#define BM 128
#define BN 128
#define BKT 16
#define AST 20
#define BSTN 132
#define STAGES 4

template<bool BTRANS, bool AVEC16>
__global__ void __launch_bounds__(256)
mma_gemm(const float* __restrict__ A, int lda,
         const float* __restrict__ B, int ldb,
         const float* __restrict__ bias, float* __restrict__ C,
         int M, int N, int K, float scale)
{
    extern __shared__ float smem_dyn[];
    float* AsB = smem_dyn;
    float* BsB = smem_dyn + STAGES * BM * AST;

    const int tid = threadIdx.x;
    const int warp = tid >> 5, lane = tid & 31;
    const int g = lane >> 2, tig = lane & 3;
    const int wm = (warp & 1) * 64;
    const int wn = (warp >> 1) * 32;
    const int m0 = blockIdx.y * BM, n0 = blockIdx.x * BN;

    const int KT = (K + BKT - 1) / BKT;
    const int SPLIT = gridDim.z;
    const int KTs = (KT + SPLIT - 1) / SPLIT;
    const int kt0 = blockIdx.z * KTs;
    const int kt1 = min(KT, kt0 + KTs);
    const int nk = kt1 - kt0;

    float acc[4][4][4];
#pragma unroll
    for (int i = 0; i < 4; i++)
#pragma unroll
        for (int j = 0; j < 4; j++)
#pragma unroll
            for (int c = 0; c < 4; c++) acc[i][j][c] = 0.f;

    auto loadStage = [&](int kt, int st) {
        int k0 = kt * BKT;
        float* as = AsB + st * BM * AST;
        if (AVEC16) {
#pragma unroll
            for (int p = 0; p < 2; p++) {
                int c = tid + 256 * p;
                int row = c >> 2, kq = (c & 3) * 4;
                cp16(as + row * AST + kq, A + (size_t)(m0 + row) * lda + k0 + kq,
                     (k0 + kq) < K);
            }
        } else {
#pragma unroll
            for (int p = 0; p < 8; p++) {
                int e = tid + 256 * p;
                int row = e >> 4, kk = e & 15;
                cp4(as + row * AST + kk, A + (size_t)(m0 + row) * lda + k0 + kk,
                    (k0 + kk) < K);
            }
        }
        if (BTRANS) {
            float* bs = BsB + st * BN * AST;
            if (AVEC16) {
#pragma unroll
                for (int p = 0; p < 2; p++) {
                    int c = tid + 256 * p;
                    int row = c >> 2, kq = (c & 3) * 4;
                    bool v = (n0 + row) < N && (k0 + kq) < K;
                    cp16(bs + row * AST + kq, B + (size_t)(n0 + row) * ldb + k0 + kq, v);
                }
            } else {
#pragma unroll
                for (int p = 0; p < 8; p++) {
                    int e = tid + 256 * p;
                    int row = e >> 4, kk = e & 15;
                    bool v = (n0 + row) < N && (k0 + kk) < K;
                    cp4(bs + row * AST + kk, B + (size_t)(n0 + row) * ldb + k0 + kk, v);
                }
            }
        } else {
            float* bs = BsB + st * BKT * BSTN;
#pragma unroll
            for (int p = 0; p < 8; p++) {
                int e = tid + 256 * p;
                int kk = e >> 7, n = e & 127;
                bool v = (k0 + kk) < K && (n0 + n) < N;
                cp4(bs + kk * BSTN + n, B + (size_t)(k0 + kk) * ldb + n0 + n, v);
            }
        }
        cp_commit();
    };

#pragma unroll
    for (int s = 0; s < STAGES - 1; s++) {
        if (s < nk) loadStage(kt0 + s, s);
        else cp_commit();
    }

    for (int i = 0; i < nk; i++) {
        cp_wait<STAGES - 2>();
        __syncthreads();

        int j = i + STAGES - 1;
        if (j < nk) loadStage(kt0 + j, j & (STAGES - 1));
        else cp_commit();

        const int st = i & (STAGES - 1);
        const float* as = AsB + st * BM * AST;
        const float* bsT = BsB + st * BN * AST;
        const float* bsN = BsB + st * BKT * BSTN;

#pragma unroll
        for (int ks = 0; ks < 2; ks++) {
            unsigned af[4][4], bf[4][2];
#pragma unroll
            for (int mi = 0; mi < 4; mi++) {
                const float* pa = as + (wm + mi * 16 + g) * AST + ks * 8 + tig;
                af[mi][0] = f2tf32(pa[0]);
                af[mi][1] = f2tf32(pa[8 * AST]);
                af[mi][2] = f2tf32(pa[4]);
                af[mi][3] = f2tf32(pa[8 * AST + 4]);
            }
#pragma unroll
            for (int ni = 0; ni < 4; ni++) {
                if (BTRANS) {
                    const float* pb = bsT + (wn + ni * 8 + g) * AST + ks * 8 + tig;
                    bf[ni][0] = f2tf32(pb[0]);
                    bf[ni][1] = f2tf32(pb[4]);
                } else {
                    const float* pb = bsN + (ks * 8 + tig) * BSTN + wn + ni * 8 + g;
                    bf[ni][0] = f2tf32(pb[0]);
                    bf[ni][1] = f2tf32(pb[4 * BSTN]);
                }
            }
#pragma unroll
            for (int mi = 0; mi < 4; mi++)
#pragma unroll
                for (int ni = 0; ni < 4; ni++) {
                    asm volatile(
                        "mma.sync.aligned.m16n8k8.row.col.f32.tf32.tf32.f32 "
                        "{%0,%1,%2,%3}, {%4,%5,%6,%7}, {%8,%9}, {%0,%1,%2,%3};"
                        : "+f"(acc[mi][ni][0]), "+f"(acc[mi][ni][1]),
                          "+f"(acc[mi][ni][2]), "+f"(acc[mi][ni][3])
                        : "r"(af[mi][0]), "r"(af[mi][1]), "r"(af[mi][2]), "r"(af[mi][3]),
                          "r"(bf[ni][0]), "r"(bf[ni][1]));
                }
        }
    }

    const bool split = (gridDim.z > 1);
    float* outp = split ? (C + (size_t)blockIdx.z * M * N) : C;
#pragma unroll
    for (int mi = 0; mi < 4; mi++) {
        int mrow0 = m0 + wm + mi * 16 + g;
#pragma unroll
        for (int ni = 0; ni < 4; ni++) {
            int ncol = n0 + wn + ni * 8 + 2 * tig;
#pragma unroll
            for (int h = 0; h < 2; h++) {
                int mr = mrow0 + h * 8;
                if (split) {
                    if (ncol < N)     outp[(size_t)mr * N + ncol]     = acc[mi][ni][h*2+0];
                    if (ncol + 1 < N) outp[(size_t)mr * N + ncol + 1] = acc[mi][ni][h*2+1];
                } else {
                    if (ncol < N) {
                        float bv = bias ? bias[ncol] : 0.f;
                        outp[(size_t)mr * N + ncol] = acc[mi][ni][h*2+0] * scale + bv;
                    }
                    if (ncol + 1 < N) {
                        float bv = bias ? bias[ncol + 1] : 0.f;
                        outp[(size_t)mr * N + ncol + 1] = acc[mi][ni][h*2+1] * scale + bv;
                    }
                }
            }
        }
    }
}

// plain split-K reduce (+bias)
__global__ void k_reduce(const float* __restrict__ part, const float* __restrict__ bias,
                         float* __restrict__ C, int M, int N, int S) {
    int i = blockIdx.x * blockDim.x + threadIdx.x;
    if (i < M * N) {
        int n = i % N;
        float s = 0.f;
        for (int z = 0; z < S; z++) s += part[(size_t)z * M * N + i];
        C[i] = s + (bias ? bias[n] : 0.f);
    }
}

// fused reduce(attr@lmf) + propagation-0
__global__ void k_fuse1(const float* __restrict__ part, const float* __restrict__ tg_X) {
    int i = blockIdx.x * blockDim.x + threadIdx.x;
    if (i < N2 * PD2) {
        int r = i / PD2, c = i - r * PD2;
        float s = 0.f;
#pragma unroll
        for (int z = 0; z < 4; z++) s += part[(size_t)z * N2 * PD2 + i];
        float num = s + (c < PD ? tg_X[r * PD + c] : 0.f) + g_rou0[r] * g_router0[c];
        g_P[i] = num / (1.f + g_asum[r] + g_rou0[r] + EPSF);
    }
}

// fused reduce(f1) + write f1 into out + propagation-1
__global__ void k_fuse2(const float* __restrict__ part, const float* __restrict__ w1_b,
                        float* __restrict__ out) {
    int i = blockIdx.x * blockDim.x + threadIdx.x;
    if (i < N2 * PD2) {
        int r = i / PD2, c = i - r * PD2;
        float s = w1_b[c];
#pragma unroll
        for (int z = 0; z < 4; z++) s += part[(size_t)z * N2 * PD2 + i];
        out[N2 * 2 + r * FD + PD + c] = s;
        g_P[i] = (s + g_rou1[r] * g_router1[c]) / (1.f + g_rou1[r] + EPSF);
    }
}

// fused reduce(f2) + write f2 into out
__global__ void k_fuse3(const float* __restrict__ part, const float* __restrict__ w2_b,
                        float* __restrict__ out) {
    int i = blockIdx.x * blockDim.x + threadIdx.x;
    if (i < N2 * PD2) {
        int r = i / PD2, c = i - r * PD2;
        float s = w2_b[c];
#pragma unroll
        for (int z = 0; z < 4; z++) s += part[(size_t)z * N2 * PD2 + i];
        out[N2 * 2 + r * FD + PD + PD2 + c] = s;
    }
}

// ---------------- attention 1 ----------------
__global__ void k_attr() {
    __shared__ float red[256];
    int r = blockIdx.x;
    float* s = g_S + (size_t)r * N1;
    int t = threadIdx.x;
    float e[16];
    float m = -1e30f;
#pragma unroll
    for (int i = 0; i < 16; i++) { e[i] = s[t + i * 256]; m = fmaxf(m, e[i]); }
    m = blk_max(m, red);
    float z = 0.f;
#pragma unroll
    for (int i = 0; i < 16; i++) { e[i] = fexp(e[i] - m); z += e[i]; }
    z = blk_sum(z, red);
    float inv = 1.f / z;
    float rs = 0.f;
#pragma unroll
    for (int i = 0; i < 16; i++) {
        float v = fexp(e[i] * inv);
        s[t + i * 256] = v;
        rs += v;
    }
    rs = blk_sum(rs, red);
    if (t == 0) g_asum[r] = rs;
}

// ---------------- router chain ----------------
__global__ void k_routerp() {
    __shared__ float red[256];
    int c = blockIdx.x;
    float s = 0.f;
    for (int r = threadIdx.x; r < N1; r += 256) s += g_delay[r] * g_lmf[r * PD2 + c];
    s = blk_sum(s, red);
    if (threadIdx.x == 0)
        g_routerp[c] = (s + g_router0[c]) / (1.f + g_dsum + EPSF);
}

__global__ void k_router1(const float* __restrict__ w1_w, const float* __restrict__ w1_b) {
    int j = threadIdx.x;
    if (j < PD2) {
        float s = w1_b[j];
        for (int k = 0; k < PD2; k++) s += g_routerp[k] * w1_w[j * PD2 + k];
        g_router1[j] = s;
    }
}

__global__ void k_v2(const float* __restrict__ lm_Y,
                     const float* __restrict__ pv_w, const float* __restrict__ pv_b) {
    int i = blockIdx.x * blockDim.x + threadIdx.x;
    if (i < N1) {
        float y0 = lm_Y[2 * i], y1 = lm_Y[2 * i + 1];
        g_v2[2 * i]     = pv_w[0] * y0 + pv_w[1] * y1 + pv_b[0];
        g_v2[2 * i + 1] = pv_w[2] * y0 + pv_w[3] * y1 + pv_b[1];
    }
}

__global__ void k_attn2(float* __restrict__ out) {
    __shared__ float red[256];
    int r = blockIdx.x;
    const float* s = g_S + (size_t)r * N1;
    int t = threadIdx.x;
    float e[16];
    float m = -1e30f;
#pragma unroll
    for (int i = 0; i < 16; i++) { e[i] = s[t + i * 256]; m = fmaxf(m, e[i]); }
    m = blk_max(m, red);
    float sw = 0.f, s0 = 0.f, s1 = 0.f;
#pragma unroll
    for (int i = 0; i < 16; i++) {
        int idx = t + i * 256;
        float w = fexp(e[i] - m);
        sw += w;
        s0 += w * g_v2[2 * idx];
        s1 += w * g_v2[2 * idx + 1];
    }
    sw = blk_sum(sw, red);
    s0 = blk_sum(s0, red);
    s1 = blk_sum(s1, red);
    if (t == 0) {
        out[2 * r]     = s0 / sw;
        out[2 * r + 1] = s1 / sw;
    }
}

// ---------------- host launch ----------------
static float* sym_addr(const void* s) {
    void* p = nullptr;
    cudaGetSymbolAddress(&p, s);
    return (float*)p;
}

#define SMEM_TT ((STAGES * BM * AST + STAGES * BN * AST) * 4)
#define SMEM_FF ((STAGES * BM * AST + STAGES * BKT * BSTN) * 4)

extern "C" void kernel_launch(void* const* d_in, const int* in_sizes, int n_in,
                              void* d_out, int out_size) {
    const float* lm_X    = (const float*)d_in[0];
    const float* lm_Y    = (const float*)d_in[1];
    const float* tg_X    = (const float*)d_in[2];
    const float* lm_delay= (const float*)d_in[4];
    const float* tg_delay= (const float*)d_in[5];
    const float* aq_w    = (const float*)d_in[6];
    const float* aq_b    = (const float*)d_in[7];
    const float* ak_w    = (const float*)d_in[8];
    const float* ak_b    = (const float*)d_in[9];
    const float* w1_w    = (const float*)d_in[10];
    const float* w1_b    = (const float*)d_in[11];
    const float* w2_w    = (const float*)d_in[12];
    const float* w2_b    = (const float*)d_in[13];
    const float* pq_w    = (const float*)d_in[14];
    const float* pq_b    = (const float*)d_in[15];
    const float* pk_w    = (const float*)d_in[16];
    const float* pk_b    = (const float*)d_in[17];
    const float* pv_w    = (const float*)d_in[18];
    const float* pv_b    = (const float*)d_in[19];
    const float* gamma1  = (const float*)d_in[20];
    const float* gamma2  = (const float*)d_in[21];
    const float* gamma3  = (const float*)d_in[22];
    const float* alpha   = (const float*)d_in[23];
    const float* beta    = (const float*)d_in[24];
    float* out = (float*)d_out;

    float* pk12  = sym_addr(g_k12);
    float* pq    = sym_addr(g_q);
    float* pq2   = sym_addr(g_q2);
    float* pS    = sym_addr(g_S);
    float* plmf  = sym_addr(g_lmf);
    float* pP    = sym_addr(g_P);
    float* pPart = sym_addr(g_part);
    float* pwcat = sym_addr(g_wcat);
    float* pbcat = sym_addr(g_bcat);

    cudaFuncSetAttribute(mma_gemm<true, true>,  cudaFuncAttributeMaxDynamicSharedMemorySize, SMEM_TT);
    cudaFuncSetAttribute(mma_gemm<true, false>, cudaFuncAttributeMaxDynamicSharedMemorySize, SMEM_TT);
    cudaFuncSetAttribute(mma_gemm<false, true>, cudaFuncAttributeMaxDynamicSharedMemorySize, SMEM_FF);

    dim3 blk(256);
    auto grd = [](int M, int N, int S) {
        return dim3((N + BN - 1) / BN, (M + BM - 1) / BM, S);
    };

    // prep
    k_misc<<<(N1 * PD2 + N2 * PD + 255) / 256, blk>>>(lm_X, lm_Y, tg_X, out);
    k_colmean<<<PD2, blk>>>(lm_X, lm_Y);
    k_prep<<<1, 1024>>>(lm_delay, tg_delay, gamma1, gamma2, gamma3, alpha, beta);
    k_wcat<<<(2 * DZ * PD + 255) / 256, blk>>>(ak_w, pk_w, ak_b, pk_b);
    k_routerp<<<PD2, blk>>>();
    k_router1<<<1, PD2>>>(w1_w, w1_b);
    k_v2<<<(N1 + 255) / 256, blk>>>(lm_Y, pv_w, pv_b);

    // combined k1|k2 projection: lm_X @ [ak_w;pk_w]^T, N=256, split-4
    mma_gemm<true, true><<<grd(N1, 2 * DZ, 4), blk, SMEM_TT>>>(lm_X, PD, pwcat, PD, nullptr, pPart, N1, 2 * DZ, PD, 1.f);
    k_reduce<<<(N1 * 2 * DZ + 255) / 256, blk>>>(pPart, pbcat, pk12, N1, 2 * DZ, 4);

    // q projection: tg_X @ aq_w^T, split-8
    mma_gemm<true, true><<<grd(N2, DZ, 8), blk, SMEM_TT>>>(tg_X, PD, aq_w, PD, nullptr, pPart, N2, DZ, PD, 1.f);
    k_reduce<<<(N2 * DZ + 255) / 256, blk>>>(pPart, aq_b, pq, N2, DZ, 8);

    // scores1 = q @ k1^T (k1 = g_k12 cols 0..127, ldb=256)
    mma_gemm<true, true><<<grd(N2, N1, 1), blk, SMEM_TT>>>(pq, DZ, pk12, 2 * DZ, nullptr, pS, N2, N1, DZ, INV_TEMP);
    k_attr<<<N2, blk>>>();

    // propagation 0: attr @ lm_feature, split-4, then fused reduce+prop0
    mma_gemm<false, true><<<grd(N2, PD2, 4), blk, SMEM_FF>>>(pS, N1, plmf, PD2, nullptr, pPart, N2, PD2, N1, 1.f);
    k_fuse1<<<(N2 * PD2 + 255) / 256, blk>>>(pPart, tg_X);

    // f1 = P @ w1^T (K=258), fused reduce + out-write + prop1
    mma_gemm<true, false><<<grd(N2, PD2, 4), blk, SMEM_TT>>>(pP, PD2, w1_w, PD2, nullptr, pPart, N2, PD2, PD2, 1.f);
    k_fuse2<<<(N2 * PD2 + 255) / 256, blk>>>(pPart, w1_b, out);

    // f2 = P @ w2^T, fused reduce + out-write
    mma_gemm<true, false><<<grd(N2, PD2, 4), blk, SMEM_TT>>>(pP, PD2, w2_w, PD2, nullptr, pPart, N2, PD2, PD2, 1.f);
    k_fuse3<<<(N2 * PD2 + 255) / 256, blk>>>(pPart, w2_b, out);

    // q2 = final_features @ pq_w^T (A = out feature block, lda=772), split-8
    mma_gemm<true, true><<<grd(N2, DZ, 8), blk, SMEM_TT>>>(out + N2 * 2, FD, pq_w, FD, nullptr, pPart, N2, DZ, FD, 1.f);
    k_reduce<<<(N2 * DZ + 255) / 256, blk>>>(pPart, pq_b, pq2, N2, DZ, 8);

    // scores2 = q2 @ k2^T (k2 = g_k12 cols 128..255)
    mma_gemm<true, true><<<grd(N2, N1, 1), blk, SMEM_TT>>>(pq2, DZ, pk12 + DZ, 2 * DZ, nullptr, pS, N2, N1, DZ, INV_TEMP);
    k_attn2<<<N2, blk>>>(out);
}

// round 6
// speedup vs baseline: 1.1210x; 1.0512x over previous
#include <cuda_runtime.h>
#include <math.h>

// ---------------- problem constants ----------------
#define N1 4096
#define N2 2048
#define PD 256
#define DZ 128
#define PD2 258
#define FD 772
#define EPSF 1e-12f
#define INV_TEMP 0.08838834764831843f   // 1/sqrt(128)

// ---------------- device scratch ----------------
__device__ float g_k12[N1 * 2 * DZ];   // [k1 | k2], row stride 256
__device__ float g_q[N2 * DZ];
__device__ float g_q2[N2 * DZ];
__device__ float g_S[(size_t)N2 * N1];
__device__ float g_lmf[N1 * PD2];
__device__ float g_P[N2 * PD2];
__device__ float g_part[4 * 2048 * 258];   // split-K partials (attr@lmf only)
__device__ float g_wcat[2 * DZ * PD];      // [ak_w ; pk_w]
__device__ float g_bcat[2 * DZ];
__device__ float g_router0[PD2];
__device__ float g_routerp[PD2];
__device__ float g_router1[PD2];
__device__ float g_delay[N1];
__device__ float g_dsum;
__device__ float g_rou0[N2];
__device__ float g_rou1[N2];
__device__ float g_asum[N2];
__device__ float g_v2[N1 * 2];

// ---------------- helpers ----------------
__device__ __forceinline__ float fexp(float x) {
    float y;
    asm("ex2.approx.f32 %0, %1;" : "=f"(y) : "f"(x * 1.4426950408889634f));
    return y;
}
__device__ __forceinline__ unsigned f2tf32(float x) {
    unsigned r;
    asm("cvt.rna.tf32.f32 %0, %1;" : "=r"(r) : "f"(x));
    return r;
}
__device__ __forceinline__ void cp16(float* dst, const float* src, bool valid) {
    unsigned d = (unsigned)__cvta_generic_to_shared(dst);
    int sz = valid ? 16 : 0;
    asm volatile("cp.async.cg.shared.global [%0], [%1], 16, %2;" :: "r"(d), "l"(src), "r"(sz));
}
__device__ __forceinline__ void cp4(float* dst, const float* src, bool valid) {
    unsigned d = (unsigned)__cvta_generic_to_shared(dst);
    int sz = valid ? 4 : 0;
    asm volatile("cp.async.ca.shared.global [%0], [%1], 4, %2;" :: "r"(d), "l"(src), "r"(sz));
}
__device__ __forceinline__ void cp_commit() { asm volatile("cp.async.commit_group;"); }
template<int N_>
__device__ __forceinline__ void cp_wait() {
    asm volatile("cp.async.wait_group %0;" :: "n"(N_));
}

template<int TB>
__device__ __forceinline__ float blk_sum(float v, float* red) {
    int t = threadIdx.x;
    red[t] = v; __syncthreads();
    for (int s = TB >> 1; s > 0; s >>= 1) {
        if (t < s) red[t] += red[t + s];
        __syncthreads();
    }
    float r = red[0]; __syncthreads();
    return r;
}
template<int TB>
__device__ __forceinline__ float blk_max(float v, float* red) {
    int t = threadIdx.x;
    red[t] = v; __syncthreads();
    for (int s = TB >> 1; s > 0; s >>= 1) {
        if (t < s) red[t] = fmaxf(red[t], red[t + s]);
        __syncthreads();
    }
    float r = red[0]; __syncthreads();
    return r;
}

// ---------------- fused prep kernel (block-role dispatch) ----------------
#define B_LMF  4128   // N1*PD2/256
#define B_TGX  2048   // N2*PD/256
#define B_WCAT 256    // 2*DZ*PD/256
#define B_V2   16     // N1/256
#define B_CM   258    // PD2 columns
#define B_DEL  1
#define B_ROU  8      // N2/256
#define B_PREP_TOT (B_LMF + B_TGX + B_WCAT + B_V2 + B_CM + B_DEL + B_ROU)

__global__ void k_prep_all(const float* __restrict__ lm_X, const float* __restrict__ lm_Y,
                           const float* __restrict__ tg_X,
                           const float* __restrict__ ak_w, const float* __restrict__ pk_w,
                           const float* __restrict__ ak_b, const float* __restrict__ pk_b,
                           const float* __restrict__ lm_delay, const float* __restrict__ tg_delay,
                           const float* g1p, const float* g2p, const float* g3p,
                           const float* ap, const float* bp,
                           const float* __restrict__ pv_w, const float* __restrict__ pv_b,
                           float* __restrict__ out) {
    __shared__ float red[256];
    int bid = blockIdx.x, t = threadIdx.x;

    if (bid < B_LMF) {                                    // lm_feature assembly
        int i = bid * 256 + t;
        int r = i / PD2, c = i - r * PD2;
        g_lmf[i] = (c < PD) ? lm_X[r * PD + c] : lm_Y[r * 2 + (c - PD)];
        return;
    }
    bid -= B_LMF;
    if (bid < B_TGX) {                                    // tg_X -> out feature block
        int j = bid * 256 + t;
        int r = j / PD, c = j - r * PD;
        out[N2 * 2 + r * FD + c] = tg_X[j];
        return;
    }
    bid -= B_TGX;
    if (bid < B_WCAT) {                                   // weight concat
        int i = bid * 256 + t;
        g_wcat[i] = (i < DZ * PD) ? ak_w[i] : pk_w[i - DZ * PD];
        if (i < DZ) g_bcat[i] = ak_b[i];
        else if (i < 2 * DZ) g_bcat[i] = pk_b[i - DZ];
        return;
    }
    bid -= B_WCAT;
    if (bid < B_V2) {                                     // v2 projection
        int i = bid * 256 + t;
        float y0 = lm_Y[2 * i], y1 = lm_Y[2 * i + 1];
        g_v2[2 * i]     = pv_w[0] * y0 + pv_w[1] * y1 + pv_b[0];
        g_v2[2 * i + 1] = pv_w[2] * y0 + pv_w[3] * y1 + pv_b[1];
        return;
    }
    bid -= B_V2;
    if (bid < B_CM) {                                     // column mean (router_0)
        int c = bid;
        float s = 0.f;
        if (c < PD) for (int r = t; r < N1; r += 256) s += lm_X[r * PD + c];
        else        for (int r = t; r < N1; r += 256) s += lm_Y[r * 2 + (c - PD)];
        s = blk_sum<256>(s, red);
        if (t == 0) g_router0[c] = s * (1.0f / N1);
        return;
    }
    bid -= B_CM;
    if (bid < B_DEL) {                                    // delay_score + sum
        float a = ap[0], b = bp[0], g1 = g1p[0];
        float local = 0.f;
        for (int i = t; i < N1; i += 256) {
            float d = fexp(-g1 * (a * lm_delay[i] + b));
            g_delay[i] = d;
            local += d;
        }
        local = blk_sum<256>(local, red);
        if (t == 0) g_dsum = local;
        return;
    }
    bid -= B_DEL;
    {                                                     // rou0 / rou1
        int i = bid * 256 + t;
        float a = ap[0], b = bp[0], g2 = g2p[0], g3 = g3p[0];
        float x = a * tg_delay[i] + b;
        g_rou0[i] = fexp(-g2 * x);
        g_rou1[i] = fexp(-g3 * x);
    }
}

// ---------------- 128x128 tf32 GEMM, 4-stage cp.async, optional split-K ------
#define BM 128
#define BN 128
#define BKT 16
#define AST 20
#define BSTN 132
#define STAGES 4

template<bool BTRANS, bool AVEC16>
__global__ void __launch_bounds__(256)
mma_gemm(const float* __restrict__ A, int lda,
         const float* __restrict__ B, int ldb,
         const float* __restrict__ bias, float* __restrict__ C, int ldc,
         int M, int N, int K, float scale)
{
    extern __shared__ float smem_dyn[];
    float* AsB = smem_dyn;
    float* BsB = smem_dyn + STAGES * BM * AST;

    const int tid = threadIdx.x;
    const int warp = tid >> 5, lane = tid & 31;
    const int g = lane >> 2, tig = lane & 3;
    const int wm = (warp & 1) * 64;
    const int wn = (warp >> 1) * 32;
    const int m0 = blockIdx.y * BM, n0 = blockIdx.x * BN;

    const int KT = (K + BKT - 1) / BKT;
    const int SPLIT = gridDim.z;
    const int KTs = (KT + SPLIT - 1) / SPLIT;
    const int kt0 = blockIdx.z * KTs;
    const int kt1 = min(KT, kt0 + KTs);
    const int nk = kt1 - kt0;

    float acc[4][4][4];
#pragma unroll
    for (int i = 0; i < 4; i++)
#pragma unroll
        for (int j = 0; j < 4; j++)
#pragma unroll
            for (int c = 0; c < 4; c++) acc[i][j][c] = 0.f;

    auto loadStage = [&](int kt, int st) {
        int k0 = kt * BKT;
        float* as = AsB + st * BM * AST;
        if (AVEC16) {
#pragma unroll
            for (int p = 0; p < 2; p++) {
                int c = tid + 256 * p;
                int row = c >> 2, kq = (c & 3) * 4;
                cp16(as + row * AST + kq, A + (size_t)(m0 + row) * lda + k0 + kq,
                     (k0 + kq) < K);
            }
        } else {
#pragma unroll
            for (int p = 0; p < 8; p++) {
                int e = tid + 256 * p;
                int row = e >> 4, kk = e & 15;
                cp4(as + row * AST + kk, A + (size_t)(m0 + row) * lda + k0 + kk,
                    (k0 + kk) < K);
            }
        }
        if (BTRANS) {
            float* bs = BsB + st * BN * AST;
            if (AVEC16) {
#pragma unroll
                for (int p = 0; p < 2; p++) {
                    int c = tid + 256 * p;
                    int row = c >> 2, kq = (c & 3) * 4;
                    bool v = (n0 + row) < N && (k0 + kq) < K;
                    cp16(bs + row * AST + kq, B + (size_t)(n0 + row) * ldb + k0 + kq, v);
                }
            } else {
#pragma unroll
                for (int p = 0; p < 8; p++) {
                    int e = tid + 256 * p;
                    int row = e >> 4, kk = e & 15;
                    bool v = (n0 + row) < N && (k0 + kk) < K;
                    cp4(bs + row * AST + kk, B + (size_t)(n0 + row) * ldb + k0 + kk, v);
                }
            }
        } else {
            float* bs = BsB + st * BKT * BSTN;
#pragma unroll
            for (int p = 0; p < 8; p++) {
                int e = tid + 256 * p;
                int kk = e >> 7, n = e & 127;
                bool v = (k0 + kk) < K && (n0 + n) < N;
                cp4(bs + kk * BSTN + n, B + (size_t)(k0 + kk) * ldb + n0 + n, v);
            }
        }
        cp_commit();
    };

#pragma unroll
    for (int s = 0; s < STAGES - 1; s++) {
        if (s < nk) loadStage(kt0 + s, s);
        else cp_commit();
    }

    for (int i = 0; i < nk; i++) {
        cp_wait<STAGES - 2>();
        __syncthreads();

        int j = i + STAGES - 1;
        if (j < nk) loadStage(kt0 + j, j & (STAGES - 1));
        else cp_commit();

        const int st = i & (STAGES - 1);
        const float* as = AsB + st * BM * AST;
        const float* bsT = BsB + st * BN * AST;
        const float* bsN = BsB + st * BKT * BSTN;

#pragma unroll
        for (int ks = 0; ks < 2; ks++) {
            unsigned af[4][4], bf[4][2];
#pragma unroll
            for (int mi = 0; mi < 4; mi++) {
                const float* pa = as + (wm + mi * 16 + g) * AST + ks * 8 + tig;
                af[mi][0] = f2tf32(pa[0]);
                af[mi][1] = f2tf32(pa[8 * AST]);
                af[mi][2] = f2tf32(pa[4]);
                af[mi][3] = f2tf32(pa[8 * AST + 4]);
            }
#pragma unroll
            for (int ni = 0; ni < 4; ni++) {
                if (BTRANS) {
                    const float* pb = bsT + (wn + ni * 8 + g) * AST + ks * 8 + tig;
                    bf[ni][0] = f2tf32(pb[0]);
                    bf[ni][1] = f2tf32(pb[4]);
                } else {
                    const float* pb = bsN + (ks * 8 + tig) * BSTN + wn + ni * 8 + g;
                    bf[ni][0] = f2tf32(pb[0]);
                    bf[ni][1] = f2tf32(pb[4 * BSTN]);
                }
            }
#pragma unroll
            for (int mi = 0; mi < 4; mi++)
#pragma unroll
                for (int ni = 0; ni < 4; ni++) {
                    asm volatile(
                        "mma.sync.aligned.m16n8k8.row.col.f32.tf32.tf32.f32 "
                        "{%0,%1,%2,%3}, {%4,%5,%6,%7}, {%8,%9}, {%0,%1,%2,%3};"
                        : "+f"(acc[mi][ni][0]), "+f"(acc[mi][ni][1]),
                          "+f"(acc[mi][ni][2]), "+f"(acc[mi][ni][3])
                        : "r"(af[mi][0]), "r"(af[mi][1]), "r"(af[mi][2]), "r"(af[mi][3]),
                          "r"(bf[ni][0]), "r"(bf[ni][1]));
                }
        }
    }

    const bool split = (gridDim.z > 1);
    float* outp = split ? (C + (size_t)blockIdx.z * M * N) : C;
#pragma unroll
    for (int mi = 0; mi < 4; mi++) {
        int mrow0 = m0 + wm + mi * 16 + g;
#pragma unroll
        for (int ni = 0; ni < 4; ni++) {
            int ncol = n0 + wn + ni * 8 + 2 * tig;
#pragma unroll
            for (int h = 0; h < 2; h++) {
                int mr = mrow0 + h * 8;
                if (split) {
                    if (ncol < N)     outp[(size_t)mr * ldc + ncol]     = acc[mi][ni][h*2+0];
                    if (ncol + 1 < N) outp[(size_t)mr * ldc + ncol + 1] = acc[mi][ni][h*2+1];
                } else {
                    if (ncol < N) {
                        float bv = bias ? bias[ncol] : 0.f;
                        outp[(size_t)mr * ldc + ncol] = acc[mi][ni][h*2+0] * scale + bv;
                    }
                    if (ncol + 1 < N) {
                        float bv = bias ? bias[ncol + 1] : 0.f;
                        outp[(size_t)mr * ldc + ncol + 1] = acc[mi][ni][h*2+1] * scale + bv;
                    }
                }
            }
        }
    }
}

// ---------------- 64x64 tf32 GEMM (A B^T only), no split-K -------------------
#define BM6 64
#define BN6 64

template<bool AVEC16>
__global__ void __launch_bounds__(128)
mma_gemm64(const float* __restrict__ A, int lda,
           const float* __restrict__ B, int ldb,
           const float* __restrict__ bias, float* __restrict__ C, int ldc,
           int M, int N, int K, float scale)
{
    extern __shared__ float smem_dyn[];
    float* AsB = smem_dyn;                               // STAGES*64*AST
    float* BsB = smem_dyn + STAGES * BM6 * AST;

    const int tid = threadIdx.x;
    const int warp = tid >> 5, lane = tid & 31;
    const int g = lane >> 2, tig = lane & 3;
    const int wm = (warp & 1) * 32;
    const int wn = (warp >> 1) * 32;
    const int m0 = blockIdx.y * BM6, n0 = blockIdx.x * BN6;

    const int KT = (K + BKT - 1) / BKT;

    float acc[2][4][4];
#pragma unroll
    for (int i = 0; i < 2; i++)
#pragma unroll
        for (int j = 0; j < 4; j++)
#pragma unroll
            for (int c = 0; c < 4; c++) acc[i][j][c] = 0.f;

    auto loadStage = [&](int kt, int st) {
        int k0 = kt * BKT;
        float* as = AsB + st * BM6 * AST;
        float* bs = BsB + st * BN6 * AST;
        if (AVEC16) {
#pragma unroll
            for (int p = 0; p < 2; p++) {
                int c = tid + 128 * p;
                int row = c >> 2, kq = (c & 3) * 4;
                cp16(as + row * AST + kq, A + (size_t)(m0 + row) * lda + k0 + kq,
                     (k0 + kq) < K);
            }
#pragma unroll
            for (int p = 0; p < 2; p++) {
                int c = tid + 128 * p;
                int row = c >> 2, kq = (c & 3) * 4;
                bool v = (n0 + row) < N && (k0 + kq) < K;
                cp16(bs + row * AST + kq, B + (size_t)(n0 + row) * ldb + k0 + kq, v);
            }
        } else {
#pragma unroll
            for (int p = 0; p < 8; p++) {
                int e = tid + 128 * p;
                int row = e >> 4, kk = e & 15;
                cp4(as + row * AST + kk, A + (size_t)(m0 + row) * lda + k0 + kk,
                    (k0 + kk) < K);
            }
#pragma unroll
            for (int p = 0; p < 8; p++) {
                int e = tid + 128 * p;
                int row = e >> 4, kk = e & 15;
                bool v = (n0 + row) < N && (k0 + kk) < K;
                cp4(bs + row * AST + kk, B + (size_t)(n0 + row) * ldb + k0 + kk, v);
            }
        }
        cp_commit();
    };

#pragma unroll
    for (int s = 0; s < STAGES - 1; s++) {
        if (s < KT) loadStage(s, s);
        else cp_commit();
    }

    for (int i = 0; i < KT; i++) {
        cp_wait<STAGES - 2>();
        __syncthreads();

        int j = i + STAGES - 1;
        if (j < KT) loadStage(j, j & (STAGES - 1));
        else cp_commit();

        const int st = i & (STAGES - 1);
        const float* as = AsB + st * BM6 * AST;
        const float* bs = BsB + st * BN6 * AST;

#pragma unroll
        for (int ks = 0; ks < 2; ks++) {
            unsigned af[2][4], bf[4][2];
#pragma unroll
            for (int mi = 0; mi < 2; mi++) {
                const float* pa = as + (wm + mi * 16 + g) * AST + ks * 8 + tig;
                af[mi][0] = f2tf32(pa[0]);
                af[mi][1] = f2tf32(pa[8 * AST]);
                af[mi][2] = f2tf32(pa[4]);
                af[mi][3] = f2tf32(pa[8 * AST + 4]);
            }
#pragma unroll
            for (int ni = 0; ni < 4; ni++) {
                const float* pb = bs + (wn + ni * 8 + g) * AST + ks * 8 + tig;
                bf[ni][0] = f2tf32(pb[0]);
                bf[ni][1] = f2tf32(pb[4]);
            }
#pragma unroll
            for (int mi = 0; mi < 2; mi++)
#pragma unroll
                for (int ni = 0; ni < 4; ni++) {
                    asm volatile(
                        "mma.sync.aligned.m16n8k8.row.col.f32.tf32.tf32.f32 "
                        "{%0,%1,%2,%3}, {%4,%5,%6,%7}, {%8,%9}, {%0,%1,%2,%3};"
                        : "+f"(acc[mi][ni][0]), "+f"(acc[mi][ni][1]),
                          "+f"(acc[mi][ni][2]), "+f"(acc[mi][ni][3])
                        : "r"(af[mi][0]), "r"(af[mi][1]), "r"(af[mi][2]), "r"(af[mi][3]),
                          "r"(bf[ni][0]), "r"(bf[ni][1]));
                }
        }
    }

#pragma unroll
    for (int mi = 0; mi < 2; mi++) {
        int mrow0 = m0 + wm + mi * 16 + g;
#pragma unroll
        for (int ni = 0; ni < 4; ni++) {
            int ncol = n0 + wn + ni * 8 + 2 * tig;
#pragma unroll
            for (int h = 0; h < 2; h++) {
                int mr = mrow0 + h * 8;
                if (ncol < N) {
                    float bv = bias ? bias[ncol] : 0.f;
                    C[(size_t)mr * ldc + ncol] = acc[mi][ni][h*2+0] * scale + bv;
                }
                if (ncol + 1 < N) {
                    float bv = bias ? bias[ncol + 1] : 0.f;
                    C[(size_t)mr * ldc + ncol + 1] = acc[mi][ni][h*2+1] * scale + bv;
                }
            }
        }
    }
}

// ---------------- fused reduce(attr@lmf) + propagation-0 ----------------
__global__ void k_fuse1(const float* __restrict__ part, const float* __restrict__ tg_X) {
    int i = blockIdx.x * blockDim.x + threadIdx.x;
    if (i < N2 * PD2) {
        int r = i / PD2, c = i - r * PD2;
        float s = 0.f;
#pragma unroll
        for (int z = 0; z < 4; z++) s += part[(size_t)z * N2 * PD2 + i];
        float num = s + (c < PD ? tg_X[r * PD + c] : 0.f) + g_rou0[r] * g_router0[c];
        g_P[i] = num / (1.f + g_asum[r] + g_rou0[r] + EPSF);
    }
}

// propagation-1 reading f1 from out
__global__ void k_fuse2(const float* __restrict__ out) {
    int i = blockIdx.x * blockDim.x + threadIdx.x;
    if (i < N2 * PD2) {
        int r = i / PD2, c = i - r * PD2;
        float s = out[N2 * 2 + r * FD + PD + c];
        g_P[i] = (s + g_rou1[r] * g_router1[c]) / (1.f + g_rou1[r] + EPSF);
    }
}

// ---------------- attention 1 ----------------
__global__ void k_attr() {
    __shared__ float red[256];
    int r = blockIdx.x;
    float* s = g_S + (size_t)r * N1;
    int t = threadIdx.x;
    float e[16];
    float m = -1e30f;
#pragma unroll
    for (int i = 0; i < 16; i++) { e[i] = s[t + i * 256]; m = fmaxf(m, e[i]); }
    m = blk_max<256>(m, red);
    float z = 0.f;
#pragma unroll
    for (int i = 0; i < 16; i++) { e[i] = fexp(e[i] - m); z += e[i]; }
    z = blk_sum<256>(z, red);
    float inv = 1.f / z;
    float rs = 0.f;
#pragma unroll
    for (int i = 0; i < 16; i++) {
        float v = fexp(e[i] * inv);
        s[t + i * 256] = v;
        rs += v;
    }
    rs = blk_sum<256>(rs, red);
    if (t == 0) g_asum[r] = rs;
}

// ---------------- router chain ----------------
__global__ void k_routerp() {
    __shared__ float red[256];
    int c = blockIdx.x;
    float s = 0.f;
    for (int r = threadIdx.x; r < N1; r += 256) s += g_delay[r] * g_lmf[r * PD2 + c];
    s = blk_sum<256>(s, red);
    if (threadIdx.x == 0)
        g_routerp[c] = (s + g_router0[c]) / (1.f + g_dsum + EPSF);
}

__global__ void k_router1(const float* __restrict__ w1_w, const float* __restrict__ w1_b) {
    int j = threadIdx.x;
    if (j < PD2) {
        float s = w1_b[j];
        for (int k = 0; k < PD2; k++) s += g_routerp[k] * w1_w[j * PD2 + k];
        g_router1[j] = s;
    }
}

__global__ void k_attn2(float* __restrict__ out) {
    __shared__ float red[256];
    int r = blockIdx.x;
    const float* s = g_S + (size_t)r * N1;
    int t = threadIdx.x;
    float e[16];
    float m = -1e30f;
#pragma unroll
    for (int i = 0; i < 16; i++) { e[i] = s[t + i * 256]; m = fmaxf(m, e[i]); }
    m = blk_max<256>(m, red);
    float sw = 0.f, s0 = 0.f, s1 = 0.f;
#pragma unroll
    for (int i = 0; i < 16; i++) {
        int idx = t + i * 256;
        float w = fexp(e[i] - m);
        sw += w;
        s0 += w * g_v2[2 * idx];
        s1 += w * g_v2[2 * idx + 1];
    }
    sw = blk_sum<256>(sw, red);
    s0 = blk_sum<256>(s0, red);
    s1 = blk_sum<256>(s1, red);
    if (t == 0) {
        out[2 * r]     = s0 / sw;
        out[2 * r + 1] = s1 / sw;
    }
}

// ---------------- host launch ----------------
static float* sym_addr(const void* s) {
    void* p = nullptr;
    cudaGetSymbolAddress(&p, s);
    return (float*)p;
}

#define SMEM_TT ((STAGES * BM * AST + STAGES * BN * AST) * 4)
#define SMEM_FF ((STAGES * BM * AST + STAGES * BKT * BSTN) * 4)
#define SMEM_64 ((STAGES * BM6 * AST * 2) * 4)

extern "C" void kernel_launch(void* const* d_in, const int* in_sizes, int n_in,
                              void* d_out, int out_size) {
    const float* lm_X    = (const float*)d_in[0];
    const float* lm_Y    = (const float*)d_in[1];
    const float* tg_X    = (const float*)d_in[2];
    const float* lm_delay= (const float*)d_in[4];
    const float* tg_delay= (const float*)d_in[5];
    const float* aq_w    = (const float*)d_in[6];
    const float* aq_b    = (const float*)d_in[7];
    const float* ak_w    = (const float*)d_in[8];
    const float* ak_b    = (const float*)d_in[9];
    const float* w1_w    = (const float*)d_in[10];
    const float* w1_b    = (const float*)d_in[11];
    const float* w2_w    = (const float*)d_in[12];
    const float* w2_b    = (const float*)d_in[13];
    const float* pq_w    = (const float*)d_in[14];
    const float* pq_b    = (const float*)d_in[15];
    const float* pk_w    = (const float*)d_in[16];
    const float* pk_b    = (const float*)d_in[17];
    const float* pv_w    = (const float*)d_in[18];
    const float* pv_b    = (const float*)d_in[19];
    const float* gamma1  = (const float*)d_in[20];
    const float* gamma2  = (const float*)d_in[21];
    const float* gamma3  = (const float*)d_in[22];
    const float* alpha   = (const float*)d_in[23];
    const float* beta    = (const float*)d_in[24];
    float* out = (float*)d_out;

    float* pk12  = sym_addr(g_k12);
    float* pq    = sym_addr(g_q);
    float* pq2   = sym_addr(g_q2);
    float* pS    = sym_addr(g_S);
    float* plmf  = sym_addr(g_lmf);
    float* pP    = sym_addr(g_P);
    float* pPart = sym_addr(g_part);
    float* pwcat = sym_addr(g_wcat);
    float* pbcat = sym_addr(g_bcat);

    cudaFuncSetAttribute(mma_gemm<true, true>,  cudaFuncAttributeMaxDynamicSharedMemorySize, SMEM_TT);
    cudaFuncSetAttribute(mma_gemm<false, true>, cudaFuncAttributeMaxDynamicSharedMemorySize, SMEM_FF);
    cudaFuncSetAttribute(mma_gemm64<true>,  cudaFuncAttributeMaxDynamicSharedMemorySize, SMEM_64);
    cudaFuncSetAttribute(mma_gemm64<false>, cudaFuncAttributeMaxDynamicSharedMemorySize, SMEM_64);

    dim3 blk(256), blk64(128);
    auto grd = [](int M, int N, int S) {
        return dim3((N + BN - 1) / BN, (M + BM - 1) / BM, S);
    };
    auto grd64 = [](int M, int N) {
        return dim3((N + BN6 - 1) / BN6, (M + BM6 - 1) / BM6, 1);
    };

    // fused prep (lmf, tgX->out, wcat, v2, colmean, delay, rou)
    k_prep_all<<<B_PREP_TOT, blk>>>(lm_X, lm_Y, tg_X, ak_w, pk_w, ak_b, pk_b,
                                    lm_delay, tg_delay, gamma1, gamma2, gamma3,
                                    alpha, beta, pv_w, pv_b, out);
    k_routerp<<<PD2, blk>>>();
    k_router1<<<1, PD2>>>(w1_w, w1_b);

    // projections (64x64 tiles, no split-K)
    mma_gemm64<true><<<grd64(N1, 2 * DZ), blk64, SMEM_64>>>(lm_X, PD, pwcat, PD, pbcat, pk12, 2 * DZ, N1, 2 * DZ, PD, 1.f);
    mma_gemm64<true><<<grd64(N2, DZ), blk64, SMEM_64>>>(tg_X, PD, aq_w, PD, aq_b, pq, DZ, N2, DZ, PD, 1.f);

    // scores1 = q @ k1^T
    mma_gemm<true, true><<<grd(N2, N1, 1), blk, SMEM_TT>>>(pq, DZ, pk12, 2 * DZ, nullptr, pS, N1, N2, N1, DZ, INV_TEMP);
    k_attr<<<N2, blk>>>();

    // propagation 0: attr @ lm_feature, split-4 + fused reduce/prop0
    mma_gemm<false, true><<<grd(N2, PD2, 4), blk, SMEM_FF>>>(pS, N1, plmf, PD2, nullptr, pPart, PD2, N2, PD2, N1, 1.f);
    k_fuse1<<<(N2 * PD2 + 255) / 256, blk>>>(pPart, tg_X);

    // f1 = P @ w1^T -> straight into out (ldc = FD), then prop1
    mma_gemm64<false><<<grd64(N2, PD2), blk64, SMEM_64>>>(pP, PD2, w1_w, PD2, w1_b, out + N2 * 2 + PD, FD, N2, PD2, PD2, 1.f);
    k_fuse2<<<(N2 * PD2 + 255) / 256, blk>>>(out);

    // f2 = P @ w2^T -> straight into out
    mma_gemm64<false><<<grd64(N2, PD2), blk64, SMEM_64>>>(pP, PD2, w2_w, PD2, w2_b, out + N2 * 2 + PD + PD2, FD, N2, PD2, PD2, 1.f);

    // q2 = final_features @ pq_w^T
    mma_gemm64<true><<<grd64(N2, DZ), blk64, SMEM_64>>>(out + N2 * 2, FD, pq_w, FD, pq_b, pq2, DZ, N2, DZ, FD, 1.f);

    // scores2 = q2 @ k2^T, then fused softmax@v2
    mma_gemm<true, true><<<grd(N2, N1, 1), blk, SMEM_TT>>>(pq2, DZ, pk12 + DZ, 2 * DZ, nullptr, pS, N1, N2, N1, DZ, INV_TEMP);
    k_attn2<<<N2, blk>>>(out);
}

// round 7
// speedup vs baseline: 1.1368x; 1.0141x over previous
#include <cuda_runtime.h>
#include <math.h>

// ---------------- problem constants ----------------
#define N1 4096
#define N2 2048
#define PD 256
#define DZ 128
#define PD2 258
#define FD 772
#define EPSF 1e-12f
#define INV_TEMP 0.08838834764831843f   // 1/sqrt(128)

// ---------------- device scratch ----------------
__device__ float g_k12[N1 * 2 * DZ];   // [k1 | k2], row stride 256
__device__ float g_q[N2 * DZ];
__device__ float g_q2[N2 * DZ];
__device__ float g_S[(size_t)N2 * N1];
__device__ float g_lmf[N1 * PD2];
__device__ float g_P[N2 * PD2];
__device__ float g_part[4 * 2048 * 258];   // split-K partials / attn2 partials alias
__device__ float g_wcat[2 * DZ * PD];
__device__ float g_bcat[2 * DZ];
__device__ float g_router0[PD2];
__device__ float g_routerp[PD2];
__device__ float g_router1[PD2];
__device__ float g_delay[N1];
__device__ float g_dsum;
__device__ float g_rou0[N2];
__device__ float g_rou1[N2];
__device__ float g_asum[N2];
__device__ float g_v2[N1 * 2];

// ---------------- helpers ----------------
__device__ __forceinline__ float fexp(float x) {
    float y;
    asm("ex2.approx.f32 %0, %1;" : "=f"(y) : "f"(x * 1.4426950408889634f));
    return y;
}
__device__ __forceinline__ unsigned f2tf32(float x) {
    unsigned r;
    asm("cvt.rna.tf32.f32 %0, %1;" : "=r"(r) : "f"(x));
    return r;
}
__device__ __forceinline__ void cp16(float* dst, const float* src, bool valid) {
    unsigned d = (unsigned)__cvta_generic_to_shared(dst);
    int sz = valid ? 16 : 0;
    asm volatile("cp.async.cg.shared.global [%0], [%1], 16, %2;" :: "r"(d), "l"(src), "r"(sz));
}
__device__ __forceinline__ void cp4(float* dst, const float* src, bool valid) {
    unsigned d = (unsigned)__cvta_generic_to_shared(dst);
    int sz = valid ? 4 : 0;
    asm volatile("cp.async.ca.shared.global [%0], [%1], 4, %2;" :: "r"(d), "l"(src), "r"(sz));
}
__device__ __forceinline__ void cp_commit() { asm volatile("cp.async.commit_group;"); }
template<int N_>
__device__ __forceinline__ void cp_wait() {
    asm volatile("cp.async.wait_group %0;" :: "n"(N_));
}

template<int TB>
__device__ __forceinline__ float blk_sum(float v, float* red) {
    int t = threadIdx.x;
    red[t] = v; __syncthreads();
    for (int s = TB >> 1; s > 0; s >>= 1) {
        if (t < s) red[t] += red[t + s];
        __syncthreads();
    }
    float r = red[0]; __syncthreads();
    return r;
}
template<int TB>
__device__ __forceinline__ float blk_max(float v, float* red) {
    int t = threadIdx.x;
    red[t] = v; __syncthreads();
    for (int s = TB >> 1; s > 0; s >>= 1) {
        if (t < s) red[t] = fmaxf(red[t], red[t + s]);
        __syncthreads();
    }
    float r = red[0]; __syncthreads();
    return r;
}

// ---------------- fused prep kernel (block-role dispatch) ----------------
#define B_LMF  4128
#define B_TGX  2048
#define B_WCAT 256
#define B_V2   16
#define B_CM   258
#define B_DEL  1
#define B_ROU  8
#define B_PREP_TOT (B_LMF + B_TGX + B_WCAT + B_V2 + B_CM + B_DEL + B_ROU)

__global__ void k_prep_all(const float* __restrict__ lm_X, const float* __restrict__ lm_Y,
                           const float* __restrict__ tg_X,
                           const float* __restrict__ ak_w, const float* __restrict__ pk_w,
                           const float* __restrict__ ak_b, const float* __restrict__ pk_b,
                           const float* __restrict__ lm_delay, const float* __restrict__ tg_delay,
                           const float* g1p, const float* g2p, const float* g3p,
                           const float* ap, const float* bp,
                           const float* __restrict__ pv_w, const float* __restrict__ pv_b,
                           float* __restrict__ out) {
    __shared__ float red[256];
    int bid = blockIdx.x, t = threadIdx.x;

    if (bid < B_LMF) {
        int i = bid * 256 + t;
        int r = i / PD2, c = i - r * PD2;
        g_lmf[i] = (c < PD) ? lm_X[r * PD + c] : lm_Y[r * 2 + (c - PD)];
        return;
    }
    bid -= B_LMF;
    if (bid < B_TGX) {
        int j = bid * 256 + t;
        int r = j / PD, c = j - r * PD;
        out[N2 * 2 + r * FD + c] = tg_X[j];
        return;
    }
    bid -= B_TGX;
    if (bid < B_WCAT) {
        int i = bid * 256 + t;
        g_wcat[i] = (i < DZ * PD) ? ak_w[i] : pk_w[i - DZ * PD];
        if (i < DZ) g_bcat[i] = ak_b[i];
        else if (i < 2 * DZ) g_bcat[i] = pk_b[i - DZ];
        return;
    }
    bid -= B_WCAT;
    if (bid < B_V2) {
        int i = bid * 256 + t;
        float y0 = lm_Y[2 * i], y1 = lm_Y[2 * i + 1];
        g_v2[2 * i]     = pv_w[0] * y0 + pv_w[1] * y1 + pv_b[0];
        g_v2[2 * i + 1] = pv_w[2] * y0 + pv_w[3] * y1 + pv_b[1];
        return;
    }
    bid -= B_V2;
    if (bid < B_CM) {
        int c = bid;
        float s = 0.f;
        if (c < PD) for (int r = t; r < N1; r += 256) s += lm_X[r * PD + c];
        else        for (int r = t; r < N1; r += 256) s += lm_Y[r * 2 + (c - PD)];
        s = blk_sum<256>(s, red);
        if (t == 0) g_router0[c] = s * (1.0f / N1);
        return;
    }
    bid -= B_CM;
    if (bid < B_DEL) {
        float a = ap[0], b = bp[0], g1 = g1p[0];
        float local = 0.f;
        for (int i = t; i < N1; i += 256) {
            float d = fexp(-g1 * (a * lm_delay[i] + b));
            g_delay[i] = d;
            local += d;
        }
        local = blk_sum<256>(local, red);
        if (t == 0) g_dsum = local;
        return;
    }
    bid -= B_DEL;
    {
        int i = bid * 256 + t;
        float a = ap[0], b = bp[0], g2 = g2p[0], g3 = g3p[0];
        float x = a * tg_delay[i] + b;
        g_rou0[i] = fexp(-g2 * x);
        g_rou1[i] = fexp(-g3 * x);
    }
}

// ---------------- GEMM tile config ----------------
#define BM 128
#define BN 128
#define BKT 16
#define AST 20
#define BSTN 132
#define STAGES 4

// load one k-tile stage (A + B^T variant), shared by 128-tile kernels
template<bool BTRANS, bool AVEC16>
__device__ __forceinline__ void load_stage128(
    const float* __restrict__ A, int lda, const float* __restrict__ B, int ldb,
    float* AsB, float* BsB, int m0, int n0, int N, int K, int kt, int st, int tid)
{
    int k0 = kt * BKT;
    float* as = AsB + st * BM * AST;
    if (AVEC16) {
#pragma unroll
        for (int p = 0; p < 2; p++) {
            int c = tid + 256 * p;
            int row = c >> 2, kq = (c & 3) * 4;
            cp16(as + row * AST + kq, A + (size_t)(m0 + row) * lda + k0 + kq, (k0 + kq) < K);
        }
    } else {
#pragma unroll
        for (int p = 0; p < 8; p++) {
            int e = tid + 256 * p;
            int row = e >> 4, kk = e & 15;
            cp4(as + row * AST + kk, A + (size_t)(m0 + row) * lda + k0 + kk, (k0 + kk) < K);
        }
    }
    if (BTRANS) {
        float* bs = BsB + st * BN * AST;
        if (AVEC16) {
#pragma unroll
            for (int p = 0; p < 2; p++) {
                int c = tid + 256 * p;
                int row = c >> 2, kq = (c & 3) * 4;
                bool v = (n0 + row) < N && (k0 + kq) < K;
                cp16(bs + row * AST + kq, B + (size_t)(n0 + row) * ldb + k0 + kq, v);
            }
        } else {
#pragma unroll
            for (int p = 0; p < 8; p++) {
                int e = tid + 256 * p;
                int row = e >> 4, kk = e & 15;
                bool v = (n0 + row) < N && (k0 + kk) < K;
                cp4(bs + row * AST + kk, B + (size_t)(n0 + row) * ldb + k0 + kk, v);
            }
        }
    } else {
        float* bs = BsB + st * BKT * BSTN;
#pragma unroll
        for (int p = 0; p < 8; p++) {
            int e = tid + 256 * p;
            int kk = e >> 7, n = e & 127;
            bool v = (k0 + kk) < K && (n0 + n) < N;
            cp4(bs + kk * BSTN + n, B + (size_t)(k0 + kk) * ldb + n0 + n, v);
        }
    }
    cp_commit();
}

// mainloop body: one k-tile of MMAs
template<bool BTRANS>
__device__ __forceinline__ void mma_ktile(
    const float* as, const float* bsT, const float* bsN,
    int wm, int wn, int g, int tig, float acc[4][4][4])
{
#pragma unroll
    for (int ks = 0; ks < 2; ks++) {
        unsigned af[4][4], bf[4][2];
#pragma unroll
        for (int mi = 0; mi < 4; mi++) {
            const float* pa = as + (wm + mi * 16 + g) * AST + ks * 8 + tig;
            af[mi][0] = f2tf32(pa[0]);
            af[mi][1] = f2tf32(pa[8 * AST]);
            af[mi][2] = f2tf32(pa[4]);
            af[mi][3] = f2tf32(pa[8 * AST + 4]);
        }
#pragma unroll
        for (int ni = 0; ni < 4; ni++) {
            if (BTRANS) {
                const float* pb = bsT + (wn + ni * 8 + g) * AST + ks * 8 + tig;
                bf[ni][0] = f2tf32(pb[0]);
                bf[ni][1] = f2tf32(pb[4]);
            } else {
                const float* pb = bsN + (ks * 8 + tig) * BSTN + wn + ni * 8 + g;
                bf[ni][0] = f2tf32(pb[0]);
                bf[ni][1] = f2tf32(pb[4 * BSTN]);
            }
        }
#pragma unroll
        for (int mi = 0; mi < 4; mi++)
#pragma unroll
            for (int ni = 0; ni < 4; ni++) {
                asm volatile(
                    "mma.sync.aligned.m16n8k8.row.col.f32.tf32.tf32.f32 "
                    "{%0,%1,%2,%3}, {%4,%5,%6,%7}, {%8,%9}, {%0,%1,%2,%3};"
                    : "+f"(acc[mi][ni][0]), "+f"(acc[mi][ni][1]),
                      "+f"(acc[mi][ni][2]), "+f"(acc[mi][ni][3])
                    : "r"(af[mi][0]), "r"(af[mi][1]), "r"(af[mi][2]), "r"(af[mi][3]),
                      "r"(bf[ni][0]), "r"(bf[ni][1]));
            }
    }
}

// ---------------- 128x128 tf32 GEMM ----------------
template<bool BTRANS, bool AVEC16>
__global__ void __launch_bounds__(256)
mma_gemm(const float* __restrict__ A, int lda,
         const float* __restrict__ B, int ldb,
         const float* __restrict__ bias, float* __restrict__ C, int ldc,
         int M, int N, int K, float scale)
{
    extern __shared__ float smem_dyn[];
    float* AsB = smem_dyn;
    float* BsB = smem_dyn + STAGES * BM * AST;

    const int tid = threadIdx.x;
    const int warp = tid >> 5, lane = tid & 31;
    const int g = lane >> 2, tig = lane & 3;
    const int wm = (warp & 1) * 64;
    const int wn = (warp >> 1) * 32;
    const int m0 = blockIdx.y * BM, n0 = blockIdx.x * BN;

    const int KT = (K + BKT - 1) / BKT;
    const int SPLIT = gridDim.z;
    const int KTs = (KT + SPLIT - 1) / SPLIT;
    const int kt0 = blockIdx.z * KTs;
    const int kt1 = min(KT, kt0 + KTs);
    const int nk = kt1 - kt0;

    float acc[4][4][4];
#pragma unroll
    for (int i = 0; i < 4; i++)
#pragma unroll
        for (int j = 0; j < 4; j++)
#pragma unroll
            for (int c = 0; c < 4; c++) acc[i][j][c] = 0.f;

#pragma unroll
    for (int s = 0; s < STAGES - 1; s++) {
        if (s < nk) load_stage128<BTRANS, AVEC16>(A, lda, B, ldb, AsB, BsB, m0, n0, N, K, kt0 + s, s, tid);
        else cp_commit();
    }

    for (int i = 0; i < nk; i++) {
        cp_wait<STAGES - 2>();
        __syncthreads();
        int j = i + STAGES - 1;
        if (j < nk) load_stage128<BTRANS, AVEC16>(A, lda, B, ldb, AsB, BsB, m0, n0, N, K, kt0 + j, j & (STAGES - 1), tid);
        else cp_commit();
        const int st = i & (STAGES - 1);
        mma_ktile<BTRANS>(AsB + st * BM * AST, BsB + st * BN * AST, BsB + st * BKT * BSTN,
                          wm, wn, g, tig, acc);
    }

    const bool split = (gridDim.z > 1);
    float* outp = split ? (C + (size_t)blockIdx.z * M * N) : C;
#pragma unroll
    for (int mi = 0; mi < 4; mi++) {
        int mrow0 = m0 + wm + mi * 16 + g;
#pragma unroll
        for (int ni = 0; ni < 4; ni++) {
            int ncol = n0 + wn + ni * 8 + 2 * tig;
#pragma unroll
            for (int h = 0; h < 2; h++) {
                int mr = mrow0 + h * 8;
                if (split) {
                    if (ncol < N)     outp[(size_t)mr * ldc + ncol]     = acc[mi][ni][h*2+0];
                    if (ncol + 1 < N) outp[(size_t)mr * ldc + ncol + 1] = acc[mi][ni][h*2+1];
                } else {
                    if (ncol < N) {
                        float bv = bias ? bias[ncol] : 0.f;
                        outp[(size_t)mr * ldc + ncol] = acc[mi][ni][h*2+0] * scale + bv;
                    }
                    if (ncol + 1 < N) {
                        float bv = bias ? bias[ncol + 1] : 0.f;
                        outp[(size_t)mr * ldc + ncol + 1] = acc[mi][ni][h*2+1] * scale + bv;
                    }
                }
            }
        }
    }
}

// ---------------- scores2 GEMM + split softmax*v epilogue ----------------
// partial[colblock][row][4] = (rowmax, sum e, sum e*v0, sum e*v1) over 128 cols
__global__ void __launch_bounds__(256)
k_score2(const float* __restrict__ A, int lda,
         const float* __restrict__ B, int ldb,
         float* __restrict__ part, int K)
{
    extern __shared__ float smem_dyn[];
    float* AsB = smem_dyn;
    float* BsB = smem_dyn + STAGES * BM * AST;

    const int tid = threadIdx.x;
    const int warp = tid >> 5, lane = tid & 31;
    const int g = lane >> 2, tig = lane & 3;
    const int wm = (warp & 1) * 64;
    const int wn = (warp >> 1) * 32;
    const int m0 = blockIdx.y * BM, n0 = blockIdx.x * BN;
    const int KT = K / BKT;

    float acc[4][4][4];
#pragma unroll
    for (int i = 0; i < 4; i++)
#pragma unroll
        for (int j = 0; j < 4; j++)
#pragma unroll
            for (int c = 0; c < 4; c++) acc[i][j][c] = 0.f;

#pragma unroll
    for (int s = 0; s < STAGES - 1; s++) {
        if (s < KT) load_stage128<true, true>(A, lda, B, ldb, AsB, BsB, m0, n0, N1, K, s, s, tid);
        else cp_commit();
    }
    for (int i = 0; i < KT; i++) {
        cp_wait<STAGES - 2>();
        __syncthreads();
        int j = i + STAGES - 1;
        if (j < KT) load_stage128<true, true>(A, lda, B, ldb, AsB, BsB, m0, n0, N1, K, j, j & (STAGES - 1), tid);
        else cp_commit();
        const int st = i & (STAGES - 1);
        mma_ktile<true>(AsB + st * BM * AST, BsB + st * BN * AST, nullptr, wm, wn, g, tig, acc);
    }

    // v2 values for this thread's 8 columns
    float v2x[4][2], v2y[4][2];
#pragma unroll
    for (int ni = 0; ni < 4; ni++) {
#pragma unroll
        for (int w = 0; w < 2; w++) {
            int gc = n0 + wn + ni * 8 + 2 * tig + w;
            v2x[ni][w] = g_v2[2 * gc];
            v2y[ni][w] = g_v2[2 * gc + 1];
        }
    }

    __syncthreads();            // smem reuse for reduction
    float* sred = smem_dyn;     // [4 warpgroups][128 rows][4]

    const int w2 = warp >> 1;
#pragma unroll
    for (int mi = 0; mi < 4; mi++) {
#pragma unroll
        for (int h = 0; h < 2; h++) {
            int rloc = wm + mi * 16 + g + 8 * h;
            // thread-local over 8 cols
            float m = -1e30f;
#pragma unroll
            for (int ni = 0; ni < 4; ni++)
#pragma unroll
                for (int w = 0; w < 2; w++)
                    m = fmaxf(m, acc[mi][ni][h * 2 + w] * INV_TEMP);
            float sw = 0.f, s0 = 0.f, s1 = 0.f;
#pragma unroll
            for (int ni = 0; ni < 4; ni++)
#pragma unroll
                for (int w = 0; w < 2; w++) {
                    float e = fexp(acc[mi][ni][h * 2 + w] * INV_TEMP - m);
                    sw += e;
                    s0 += e * v2x[ni][w];
                    s1 += e * v2y[ni][w];
                }
            // butterfly over the 4 tig lanes
#pragma unroll
            for (int off = 1; off < 4; off <<= 1) {
                float om  = __shfl_xor_sync(0xffffffff, m,  off);
                float osw = __shfl_xor_sync(0xffffffff, sw, off);
                float os0 = __shfl_xor_sync(0xffffffff, s0, off);
                float os1 = __shfl_xor_sync(0xffffffff, s1, off);
                float nm = fmaxf(m, om);
                float ea = fexp(m - nm), eb = fexp(om - nm);
                sw = sw * ea + osw * eb;
                s0 = s0 * ea + os0 * eb;
                s1 = s1 * ea + os1 * eb;
                m = nm;
            }
            if (tig == 0) {
                float* p = sred + ((w2 * BM) + rloc) * 4;
                p[0] = m; p[1] = sw; p[2] = s0; p[3] = s1;
            }
        }
    }
    __syncthreads();

    // combine 4 warp-groups per row, write global partial
    if (tid < BM) {
        float m = -1e30f, sw = 0.f, s0 = 0.f, s1 = 0.f;
#pragma unroll
        for (int w = 0; w < 4; w++) {
            const float* p = sred + ((w * BM) + tid) * 4;
            float om = p[0], osw = p[1], os0 = p[2], os1 = p[3];
            float nm = fmaxf(m, om);
            float ea = fexp(m - nm), eb = fexp(om - nm);
            sw = sw * ea + osw * eb;
            s0 = s0 * ea + os0 * eb;
            s1 = s1 * ea + os1 * eb;
            m = nm;
        }
        float* p = part + ((size_t)blockIdx.x * N2 + (m0 + tid)) * 4;
        p[0] = m; p[1] = sw; p[2] = s0; p[3] = s1;
    }
}

// combine 32 column-block partials -> y_pred
__global__ void k_comb2(const float* __restrict__ part, float* __restrict__ out) {
    int r = blockIdx.x * blockDim.x + threadIdx.x;
    if (r < N2) {
        float m = -1e30f, sw = 0.f, s0 = 0.f, s1 = 0.f;
        for (int cb = 0; cb < 32; cb++) {
            const float* p = part + ((size_t)cb * N2 + r) * 4;
            float om = p[0], osw = p[1], os0 = p[2], os1 = p[3];
            float nm = fmaxf(m, om);
            float ea = fexp(m - nm), eb = fexp(om - nm);
            sw = sw * ea + osw * eb;
            s0 = s0 * ea + os0 * eb;
            s1 = s1 * ea + os1 * eb;
            m = nm;
        }
        out[2 * r]     = s0 / sw;
        out[2 * r + 1] = s1 / sw;
    }
}

// ---------------- 64x64 tf32 GEMM, optional fused prop1 ----------------
#define BM6 64
#define BN6 64

template<bool AVEC16>
__global__ void __launch_bounds__(128)
mma_gemm64(const float* __restrict__ A, int lda,
           const float* __restrict__ B, int ldb,
           const float* __restrict__ bias, float* __restrict__ C, int ldc,
           int M, int N, int K, float scale,
           const float* __restrict__ rou1, const float* __restrict__ rt1,
           float* __restrict__ P)
{
    extern __shared__ float smem_dyn[];
    float* AsB = smem_dyn;
    float* BsB = smem_dyn + STAGES * BM6 * AST;

    const int tid = threadIdx.x;
    const int warp = tid >> 5, lane = tid & 31;
    const int g = lane >> 2, tig = lane & 3;
    const int wm = (warp & 1) * 32;
    const int wn = (warp >> 1) * 32;
    const int m0 = blockIdx.y * BM6, n0 = blockIdx.x * BN6;

    const int KT = (K + BKT - 1) / BKT;

    float acc[2][4][4];
#pragma unroll
    for (int i = 0; i < 2; i++)
#pragma unroll
        for (int j = 0; j < 4; j++)
#pragma unroll
            for (int c = 0; c < 4; c++) acc[i][j][c] = 0.f;

    auto loadStage = [&](int kt, int st) {
        int k0 = kt * BKT;
        float* as = AsB + st * BM6 * AST;
        float* bs = BsB + st * BN6 * AST;
        if (AVEC16) {
#pragma unroll
            for (int p = 0; p < 2; p++) {
                int c = tid + 128 * p;
                int row = c >> 2, kq = (c & 3) * 4;
                cp16(as + row * AST + kq, A + (size_t)(m0 + row) * lda + k0 + kq, (k0 + kq) < K);
            }
#pragma unroll
            for (int p = 0; p < 2; p++) {
                int c = tid + 128 * p;
                int row = c >> 2, kq = (c & 3) * 4;
                bool v = (n0 + row) < N && (k0 + kq) < K;
                cp16(bs + row * AST + kq, B + (size_t)(n0 + row) * ldb + k0 + kq, v);
            }
        } else {
#pragma unroll
            for (int p = 0; p < 8; p++) {
                int e = tid + 128 * p;
                int row = e >> 4, kk = e & 15;
                cp4(as + row * AST + kk, A + (size_t)(m0 + row) * lda + k0 + kk, (k0 + kk) < K);
            }
#pragma unroll
            for (int p = 0; p < 8; p++) {
                int e = tid + 128 * p;
                int row = e >> 4, kk = e & 15;
                bool v = (n0 + row) < N && (k0 + kk) < K;
                cp4(bs + row * AST + kk, B + (size_t)(n0 + row) * ldb + k0 + kk, v);
            }
        }
        cp_commit();
    };

#pragma unroll
    for (int s = 0; s < STAGES - 1; s++) {
        if (s < KT) loadStage(s, s);
        else cp_commit();
    }

    for (int i = 0; i < KT; i++) {
        cp_wait<STAGES - 2>();
        __syncthreads();
        int j = i + STAGES - 1;
        if (j < KT) loadStage(j, j & (STAGES - 1));
        else cp_commit();
        const int st = i & (STAGES - 1);
        const float* as = AsB + st * BM6 * AST;
        const float* bs = BsB + st * BN6 * AST;

#pragma unroll
        for (int ks = 0; ks < 2; ks++) {
            unsigned af[2][4], bf[4][2];
#pragma unroll
            for (int mi = 0; mi < 2; mi++) {
                const float* pa = as + (wm + mi * 16 + g) * AST + ks * 8 + tig;
                af[mi][0] = f2tf32(pa[0]);
                af[mi][1] = f2tf32(pa[8 * AST]);
                af[mi][2] = f2tf32(pa[4]);
                af[mi][3] = f2tf32(pa[8 * AST + 4]);
            }
#pragma unroll
            for (int ni = 0; ni < 4; ni++) {
                const float* pb = bs + (wn + ni * 8 + g) * AST + ks * 8 + tig;
                bf[ni][0] = f2tf32(pb[0]);
                bf[ni][1] = f2tf32(pb[4]);
            }
#pragma unroll
            for (int mi = 0; mi < 2; mi++)
#pragma unroll
                for (int ni = 0; ni < 4; ni++) {
                    asm volatile(
                        "mma.sync.aligned.m16n8k8.row.col.f32.tf32.tf32.f32 "
                        "{%0,%1,%2,%3}, {%4,%5,%6,%7}, {%8,%9}, {%0,%1,%2,%3};"
                        : "+f"(acc[mi][ni][0]), "+f"(acc[mi][ni][1]),
                          "+f"(acc[mi][ni][2]), "+f"(acc[mi][ni][3])
                        : "r"(af[mi][0]), "r"(af[mi][1]), "r"(af[mi][2]), "r"(af[mi][3]),
                          "r"(bf[ni][0]), "r"(bf[ni][1]));
                }
        }
    }

#pragma unroll
    for (int mi = 0; mi < 2; mi++) {
        int mrow0 = m0 + wm + mi * 16 + g;
#pragma unroll
        for (int ni = 0; ni < 4; ni++) {
            int ncol = n0 + wn + ni * 8 + 2 * tig;
#pragma unroll
            for (int h = 0; h < 2; h++) {
                int mr = mrow0 + h * 8;
#pragma unroll
                for (int w = 0; w < 2; w++) {
                    int nc = ncol + w;
                    if (nc < N) {
                        float bv = bias ? bias[nc] : 0.f;
                        float val = acc[mi][ni][h * 2 + w] * scale + bv;
                        C[(size_t)mr * ldc + nc] = val;
                        if (P) {
                            float rr = rou1[mr];
                            P[(size_t)mr * PD2 + nc] = (val + rr * rt1[nc]) / (1.f + rr + EPSF);
                        }
                    }
                }
            }
        }
    }
}

// ---------------- fused reduce(attr@lmf) + propagation-0 ----------------
__global__ void k_fuse1(const float* __restrict__ part, const float* __restrict__ tg_X) {
    int i = blockIdx.x * blockDim.x + threadIdx.x;
    if (i < N2 * PD2) {
        int r = i / PD2, c = i - r * PD2;
        float s = 0.f;
#pragma unroll
        for (int z = 0; z < 4; z++) s += part[(size_t)z * N2 * PD2 + i];
        float num = s + (c < PD ? tg_X[r * PD + c] : 0.f) + g_rou0[r] * g_router0[c];
        g_P[i] = num / (1.f + g_asum[r] + g_rou0[r] + EPSF);
    }
}

// ---------------- attention 1 softmax ----------------
__global__ void k_attr() {
    __shared__ float red[256];
    int r = blockIdx.x;
    float* s = g_S + (size_t)r * N1;
    int t = threadIdx.x;
    float e[16];
    float m = -1e30f;
#pragma unroll
    for (int i = 0; i < 16; i++) { e[i] = s[t + i * 256]; m = fmaxf(m, e[i]); }
    m = blk_max<256>(m, red);
    float z = 0.f;
#pragma unroll
    for (int i = 0; i < 16; i++) { e[i] = fexp(e[i] - m); z += e[i]; }
    z = blk_sum<256>(z, red);
    float inv = 1.f / z;
    float rs = 0.f;
#pragma unroll
    for (int i = 0; i < 16; i++) {
        float v = fexp(e[i] * inv);
        s[t + i * 256] = v;
        rs += v;
    }
    rs = blk_sum<256>(rs, red);
    if (t == 0) g_asum[r] = rs;
}

// ---------------- router chain ----------------
__global__ void k_routerp() {
    __shared__ float red[256];
    int c = blockIdx.x;
    float s = 0.f;
    for (int r = threadIdx.x; r < N1; r += 256) s += g_delay[r] * g_lmf[r * PD2 + c];
    s = blk_sum<256>(s, red);
    if (threadIdx.x == 0)
        g_routerp[c] = (s + g_router0[c]) / (1.f + g_dsum + EPSF);
}

__global__ void k_router1(const float* __restrict__ w1_w, const float* __restrict__ w1_b) {
    int j = threadIdx.x;
    if (j < PD2) {
        float s = w1_b[j];
        for (int k = 0; k < PD2; k++) s += g_routerp[k] * w1_w[j * PD2 + k];
        g_router1[j] = s;
    }
}

// ---------------- host launch ----------------
static float* sym_addr(const void* s) {
    void* p = nullptr;
    cudaGetSymbolAddress(&p, s);
    return (float*)p;
}

#define SMEM_TT ((STAGES * BM * AST + STAGES * BN * AST) * 4)
#define SMEM_FF ((STAGES * BM * AST + STAGES * BKT * BSTN) * 4)
#define SMEM_64 ((STAGES * BM6 * AST * 2) * 4)

extern "C" void kernel_launch(void* const* d_in, const int* in_sizes, int n_in,
                              void* d_out, int out_size) {
    const float* lm_X    = (const float*)d_in[0];
    const float* lm_Y    = (const float*)d_in[1];
    const float* tg_X    = (const float*)d_in[2];
    const float* lm_delay= (const float*)d_in[4];
    const float* tg_delay= (const float*)d_in[5];
    const float* aq_w    = (const float*)d_in[6];
    const float* aq_b    = (const float*)d_in[7];
    const float* ak_w    = (const float*)d_in[8];
    const float* ak_b    = (const float*)d_in[9];
    const float* w1_w    = (const float*)d_in[10];
    const float* w1_b    = (const float*)d_in[11];
    const float* w2_w    = (const float*)d_in[12];
    const float* w2_b    = (const float*)d_in[13];
    const float* pq_w    = (const float*)d_in[14];
    const float* pq_b    = (const float*)d_in[15];
    const float* pk_w    = (const float*)d_in[16];
    const float* pk_b    = (const float*)d_in[17];
    const float* pv_w    = (const float*)d_in[18];
    const float* pv_b    = (const float*)d_in[19];
    const float* gamma1  = (const float*)d_in[20];
    const float* gamma2  = (const float*)d_in[21];
    const float* gamma3  = (const float*)d_in[22];
    const float* alpha   = (const float*)d_in[23];
    const float* beta    = (const float*)d_in[24];
    float* out = (float*)d_out;

    float* pk12  = sym_addr(g_k12);
    float* pq    = sym_addr(g_q);
    float* pq2   = sym_addr(g_q2);
    float* pS    = sym_addr(g_S);
    float* plmf  = sym_addr(g_lmf);
    float* pP    = sym_addr(g_P);
    float* pPart = sym_addr(g_part);
    float* pwcat = sym_addr(g_wcat);
    float* pbcat = sym_addr(g_bcat);
    float* prou1 = sym_addr(g_rou1);
    float* prt1  = sym_addr(g_router1);

    cudaFuncSetAttribute(mma_gemm<true, true>,  cudaFuncAttributeMaxDynamicSharedMemorySize, SMEM_TT);
    cudaFuncSetAttribute(mma_gemm<false, true>, cudaFuncAttributeMaxDynamicSharedMemorySize, SMEM_FF);
    cudaFuncSetAttribute(k_score2, cudaFuncAttributeMaxDynamicSharedMemorySize, SMEM_TT);
    cudaFuncSetAttribute(mma_gemm64<true>,  cudaFuncAttributeMaxDynamicSharedMemorySize, SMEM_64);
    cudaFuncSetAttribute(mma_gemm64<false>, cudaFuncAttributeMaxDynamicSharedMemorySize, SMEM_64);

    dim3 blk(256), blk64(128);
    auto grd = [](int M, int N, int S) {
        return dim3((N + BN - 1) / BN, (M + BM - 1) / BM, S);
    };
    auto grd64 = [](int M, int N) {
        return dim3((N + BN6 - 1) / BN6, (M + BM6 - 1) / BM6, 1);
    };

    // fused prep
    k_prep_all<<<B_PREP_TOT, blk>>>(lm_X, lm_Y, tg_X, ak_w, pk_w, ak_b, pk_b,
                                    lm_delay, tg_delay, gamma1, gamma2, gamma3,
                                    alpha, beta, pv_w, pv_b, out);
    k_routerp<<<PD2, blk>>>();
    k_router1<<<1, PD2>>>(w1_w, w1_b);

    // projections
    mma_gemm64<true><<<grd64(N1, 2 * DZ), blk64, SMEM_64>>>(lm_X, PD, pwcat, PD, pbcat, pk12, 2 * DZ, N1, 2 * DZ, PD, 1.f, nullptr, nullptr, nullptr);
    mma_gemm64<true><<<grd64(N2, DZ), blk64, SMEM_64>>>(tg_X, PD, aq_w, PD, aq_b, pq, DZ, N2, DZ, PD, 1.f, nullptr, nullptr, nullptr);

    // scores1 = q @ k1^T
    mma_gemm<true, true><<<grd(N2, N1, 1), blk, SMEM_TT>>>(pq, DZ, pk12, 2 * DZ, nullptr, pS, N1, N2, N1, DZ, INV_TEMP);
    k_attr<<<N2, blk>>>();

    // propagation 0: attr @ lm_feature, split-4 + fused reduce/prop0
    mma_gemm<false, true><<<grd(N2, PD2, 4), blk, SMEM_FF>>>(pS, N1, plmf, PD2, nullptr, pPart, PD2, N2, PD2, N1, 1.f);
    k_fuse1<<<(N2 * PD2 + 255) / 256, blk>>>(pPart, tg_X);

    // f1 = P @ w1^T -> out, with fused prop1
    mma_gemm64<false><<<grd64(N2, PD2), blk64, SMEM_64>>>(pP, PD2, w1_w, PD2, w1_b, out + N2 * 2 + PD, FD, N2, PD2, PD2, 1.f, prou1, prt1, pP);

    // f2 = P @ w2^T -> out
    mma_gemm64<false><<<grd64(N2, PD2), blk64, SMEM_64>>>(pP, PD2, w2_w, PD2, w2_b, out + N2 * 2 + PD + PD2, FD, N2, PD2, PD2, 1.f, nullptr, nullptr, nullptr);

    // q2 = final_features @ pq_w^T
    mma_gemm64<true><<<grd64(N2, DZ), blk64, SMEM_64>>>(out + N2 * 2, FD, pq_w, FD, pq_b, pq2, DZ, N2, DZ, FD, 1.f, nullptr, nullptr, nullptr);

    // attention 2: fused scores+softmax partials, then combine
    k_score2<<<dim3(N1 / BN, N2 / BM, 1), blk, SMEM_TT>>>(pq2, DZ, pk12 + DZ, 2 * DZ, pPart, DZ);
    k_comb2<<<(N2 + 255) / 256, blk>>>(pPart, out);
}

// round 8
// speedup vs baseline: 1.1869x; 1.0441x over previous
#include <cuda_runtime.h>
#include <math.h>

// ---------------- problem constants ----------------
#define N1 4096
#define N2 2048
#define PD 256
#define DZ 128
#define PD2 258
#define FD 772
#define EPSF 1e-12f
#define INV_TEMP 0.08838834764831843f   // 1/sqrt(128)

// ---------------- device scratch ----------------
__device__ float g_k12[N1 * 2 * DZ];   // [k1 | k2], row stride 256
__device__ float g_q[N2 * DZ];
__device__ float g_q2[N2 * DZ];
__device__ float g_S[(size_t)N2 * N1];
__device__ float g_lmf[N1 * PD2];
__device__ float g_P[N2 * PD2];
__device__ float g_part[4 * 2048 * 258];   // split-K partials / attn2 partials alias
__device__ float g_wcat[2 * DZ * PD];
__device__ float g_bcat[2 * DZ];
__device__ float g_rp_sx[16 * PD2];        // row-block partial col sums
__device__ float g_rp_sdx[16 * PD2];       // row-block partial delay-weighted col sums
__device__ float g_rp_sd[16];              // row-block partial delay sums
__device__ float g_router0[PD2];
__device__ float g_routerp[PD2];
__device__ float g_router1[PD2];
__device__ float g_rou0[N2];
__device__ float g_rou1[N2];
__device__ float g_asum[N2];
__device__ float g_v2[N1 * 2];

// ---------------- helpers ----------------
__device__ __forceinline__ float fexp(float x) {
    float y;
    asm("ex2.approx.f32 %0, %1;" : "=f"(y) : "f"(x * 1.4426950408889634f));
    return y;
}
__device__ __forceinline__ unsigned f2tf32(float x) {
    unsigned r;
    asm("cvt.rna.tf32.f32 %0, %1;" : "=r"(r) : "f"(x));
    return r;
}
__device__ __forceinline__ void cp16(float* dst, const float* src, bool valid) {
    unsigned d = (unsigned)__cvta_generic_to_shared(dst);
    int sz = valid ? 16 : 0;
    asm volatile("cp.async.cg.shared.global [%0], [%1], 16, %2;" :: "r"(d), "l"(src), "r"(sz));
}
__device__ __forceinline__ void cp4(float* dst, const float* src, bool valid) {
    unsigned d = (unsigned)__cvta_generic_to_shared(dst);
    int sz = valid ? 4 : 0;
    asm volatile("cp.async.ca.shared.global [%0], [%1], 4, %2;" :: "r"(d), "l"(src), "r"(sz));
}
__device__ __forceinline__ void cp_commit() { asm volatile("cp.async.commit_group;"); }
template<int N_>
__device__ __forceinline__ void cp_wait() {
    asm volatile("cp.async.wait_group %0;" :: "n"(N_));
}

template<int TB>
__device__ __forceinline__ float blk_sum(float v, float* red) {
    int t = threadIdx.x;
    red[t] = v; __syncthreads();
    for (int s = TB >> 1; s > 0; s >>= 1) {
        if (t < s) red[t] += red[t + s];
        __syncthreads();
    }
    float r = red[0]; __syncthreads();
    return r;
}
template<int TB>
__device__ __forceinline__ float blk_max(float v, float* red) {
    int t = threadIdx.x;
    red[t] = v; __syncthreads();
    for (int s = TB >> 1; s > 0; s >>= 1) {
        if (t < s) red[t] = fmaxf(red[t], red[t + s]);
        __syncthreads();
    }
    float r = red[0]; __syncthreads();
    return r;
}

// ---------------- fused prep kernel (block-role dispatch) ----------------
#define B_LMF  4128
#define B_TGX  2048
#define B_WCAT 256
#define B_V2   16
#define B_RPA  16
#define B_ROU  8
#define B_PREP_TOT (B_LMF + B_TGX + B_WCAT + B_V2 + B_RPA + B_ROU)

__global__ void k_prep_all(const float* __restrict__ lm_X, const float* __restrict__ lm_Y,
                           const float* __restrict__ tg_X,
                           const float* __restrict__ ak_w, const float* __restrict__ pk_w,
                           const float* __restrict__ ak_b, const float* __restrict__ pk_b,
                           const float* __restrict__ lm_delay, const float* __restrict__ tg_delay,
                           const float* g1p, const float* g2p, const float* g3p,
                           const float* ap, const float* bp,
                           const float* __restrict__ pv_w, const float* __restrict__ pv_b,
                           float* __restrict__ out) {
    int bid = blockIdx.x, t = threadIdx.x;

    if (bid < B_LMF) {                                    // lm_feature assembly
        int i = bid * 256 + t;
        int r = i / PD2, c = i - r * PD2;
        g_lmf[i] = (c < PD) ? lm_X[r * PD + c] : lm_Y[r * 2 + (c - PD)];
        return;
    }
    bid -= B_LMF;
    if (bid < B_TGX) {                                    // tg_X -> out feature block
        int j = bid * 256 + t;
        int r = j / PD, c = j - r * PD;
        out[N2 * 2 + r * FD + c] = tg_X[j];
        return;
    }
    bid -= B_TGX;
    if (bid < B_WCAT) {                                   // weight concat
        int i = bid * 256 + t;
        g_wcat[i] = (i < DZ * PD) ? ak_w[i] : pk_w[i - DZ * PD];
        if (i < DZ) g_bcat[i] = ak_b[i];
        else if (i < 2 * DZ) g_bcat[i] = pk_b[i - DZ];
        return;
    }
    bid -= B_WCAT;
    if (bid < B_V2) {                                     // v2 projection
        int i = bid * 256 + t;
        float y0 = lm_Y[2 * i], y1 = lm_Y[2 * i + 1];
        g_v2[2 * i]     = pv_w[0] * y0 + pv_w[1] * y1 + pv_b[0];
        g_v2[2 * i + 1] = pv_w[2] * y0 + pv_w[3] * y1 + pv_b[1];
        return;
    }
    bid -= B_V2;
    if (bid < B_RPA) {                                    // row-blocked col sums for router0/routerp
        int r0 = bid * 256;
        int lane = t & 31;
        float a = ap[0], b = bp[0], g1 = g1p[0];
        float accx0 = 0.f, accd0 = 0.f, accx1 = 0.f, accd1 = 0.f, sd = 0.f;
        for (int ch = 0; ch < 256; ch += 32) {
            float dl = fexp(-g1 * (a * lm_delay[r0 + ch + lane] + b));
#pragma unroll
            for (int k2 = 0; k2 < 32; k2++) {
                float d = __shfl_sync(0xffffffff, dl, k2);
                int rr = r0 + ch + k2;
                float x = lm_X[rr * PD + t];
                accx0 += x; accd0 += d * x;
                if (t < 2) {
                    float y = lm_Y[rr * 2 + t];
                    accx1 += y; accd1 += d * y;
                }
                sd += d;
            }
        }
        g_rp_sx[bid * PD2 + t]  = accx0;
        g_rp_sdx[bid * PD2 + t] = accd0;
        if (t < 2) {
            g_rp_sx[bid * PD2 + 256 + t]  = accx1;
            g_rp_sdx[bid * PD2 + 256 + t] = accd1;
        }
        if (t == 0) g_rp_sd[bid] = sd;
        return;
    }
    bid -= B_RPA;
    {                                                     // rou0 / rou1
        int i = bid * 256 + t;
        float a = ap[0], b = bp[0], g2 = g2p[0], g3 = g3p[0];
        float x = a * tg_delay[i] + b;
        g_rou0[i] = fexp(-g2 * x);
        g_rou1[i] = fexp(-g3 * x);
    }
}

// ---------------- GEMM tile config ----------------
#define BM 128
#define BN 128
#define BKT 16
#define AST 20
#define BSTN 132
#define STAGES 4

template<bool BTRANS, bool AVEC16>
__device__ __forceinline__ void load_stage128(
    const float* __restrict__ A, int lda, const float* __restrict__ B, int ldb,
    float* AsB, float* BsB, int m0, int n0, int N, int K, int kt, int st, int tid)
{
    int k0 = kt * BKT;
    float* as = AsB + st * BM * AST;
    if (AVEC16) {
#pragma unroll
        for (int p = 0; p < 2; p++) {
            int c = tid + 256 * p;
            int row = c >> 2, kq = (c & 3) * 4;
            cp16(as + row * AST + kq, A + (size_t)(m0 + row) * lda + k0 + kq, (k0 + kq) < K);
        }
    } else {
#pragma unroll
        for (int p = 0; p < 8; p++) {
            int e = tid + 256 * p;
            int row = e >> 4, kk = e & 15;
            cp4(as + row * AST + kk, A + (size_t)(m0 + row) * lda + k0 + kk, (k0 + kk) < K);
        }
    }
    if (BTRANS) {
        float* bs = BsB + st * BN * AST;
        if (AVEC16) {
#pragma unroll
            for (int p = 0; p < 2; p++) {
                int c = tid + 256 * p;
                int row = c >> 2, kq = (c & 3) * 4;
                bool v = (n0 + row) < N && (k0 + kq) < K;
                cp16(bs + row * AST + kq, B + (size_t)(n0 + row) * ldb + k0 + kq, v);
            }
        } else {
#pragma unroll
            for (int p = 0; p < 8; p++) {
                int e = tid + 256 * p;
                int row = e >> 4, kk = e & 15;
                bool v = (n0 + row) < N && (k0 + kk) < K;
                cp4(bs + row * AST + kk, B + (size_t)(n0 + row) * ldb + k0 + kk, v);
            }
        }
    } else {
        float* bs = BsB + st * BKT * BSTN;
#pragma unroll
        for (int p = 0; p < 8; p++) {
            int e = tid + 256 * p;
            int kk = e >> 7, n = e & 127;
            bool v = (k0 + kk) < K && (n0 + n) < N;
            cp4(bs + kk * BSTN + n, B + (size_t)(k0 + kk) * ldb + n0 + n, v);
        }
    }
    cp_commit();
}

template<bool BTRANS>
__device__ __forceinline__ void mma_ktile(
    const float* as, const float* bsT, const float* bsN,
    int wm, int wn, int g, int tig, float acc[4][4][4])
{
#pragma unroll
    for (int ks = 0; ks < 2; ks++) {
        unsigned af[4][4], bf[4][2];
#pragma unroll
        for (int mi = 0; mi < 4; mi++) {
            const float* pa = as + (wm + mi * 16 + g) * AST + ks * 8 + tig;
            af[mi][0] = f2tf32(pa[0]);
            af[mi][1] = f2tf32(pa[8 * AST]);
            af[mi][2] = f2tf32(pa[4]);
            af[mi][3] = f2tf32(pa[8 * AST + 4]);
        }
#pragma unroll
        for (int ni = 0; ni < 4; ni++) {
            if (BTRANS) {
                const float* pb = bsT + (wn + ni * 8 + g) * AST + ks * 8 + tig;
                bf[ni][0] = f2tf32(pb[0]);
                bf[ni][1] = f2tf32(pb[4]);
            } else {
                const float* pb = bsN + (ks * 8 + tig) * BSTN + wn + ni * 8 + g;
                bf[ni][0] = f2tf32(pb[0]);
                bf[ni][1] = f2tf32(pb[4 * BSTN]);
            }
        }
#pragma unroll
        for (int mi = 0; mi < 4; mi++)
#pragma unroll
            for (int ni = 0; ni < 4; ni++) {
                asm volatile(
                    "mma.sync.aligned.m16n8k8.row.col.f32.tf32.tf32.f32 "
                    "{%0,%1,%2,%3}, {%4,%5,%6,%7}, {%8,%9}, {%0,%1,%2,%3};"
                    : "+f"(acc[mi][ni][0]), "+f"(acc[mi][ni][1]),
                      "+f"(acc[mi][ni][2]), "+f"(acc[mi][ni][3])
                    : "r"(af[mi][0]), "r"(af[mi][1]), "r"(af[mi][2]), "r"(af[mi][3]),
                      "r"(bf[ni][0]), "r"(bf[ni][1]));
            }
    }
}

// ---------------- 128x128 tf32 GEMM ----------------
template<bool BTRANS, bool AVEC16>
__global__ void __launch_bounds__(256)
mma_gemm(const float* __restrict__ A, int lda,
         const float* __restrict__ B, int ldb,
         const float* __restrict__ bias, float* __restrict__ C, int ldc,
         int M, int N, int K, float scale)
{
    extern __shared__ float smem_dyn[];
    float* AsB = smem_dyn;
    float* BsB = smem_dyn + STAGES * BM * AST;

    const int tid = threadIdx.x;
    const int warp = tid >> 5, lane = tid & 31;
    const int g = lane >> 2, tig = lane & 3;
    const int wm = (warp & 1) * 64;
    const int wn = (warp >> 1) * 32;
    const int m0 = blockIdx.y * BM, n0 = blockIdx.x * BN;

    const int KT = (K + BKT - 1) / BKT;
    const int SPLIT = gridDim.z;
    const int KTs = (KT + SPLIT - 1) / SPLIT;
    const int kt0 = blockIdx.z * KTs;
    const int kt1 = min(KT, kt0 + KTs);
    const int nk = kt1 - kt0;

    float acc[4][4][4];
#pragma unroll
    for (int i = 0; i < 4; i++)
#pragma unroll
        for (int j = 0; j < 4; j++)
#pragma unroll
            for (int c = 0; c < 4; c++) acc[i][j][c] = 0.f;

#pragma unroll
    for (int s = 0; s < STAGES - 1; s++) {
        if (s < nk) load_stage128<BTRANS, AVEC16>(A, lda, B, ldb, AsB, BsB, m0, n0, N, K, kt0 + s, s, tid);
        else cp_commit();
    }

    for (int i = 0; i < nk; i++) {
        cp_wait<STAGES - 2>();
        __syncthreads();
        int j = i + STAGES - 1;
        if (j < nk) load_stage128<BTRANS, AVEC16>(A, lda, B, ldb, AsB, BsB, m0, n0, N, K, kt0 + j, j & (STAGES - 1), tid);
        else cp_commit();
        const int st = i & (STAGES - 1);
        mma_ktile<BTRANS>(AsB + st * BM * AST, BsB + st * BN * AST, BsB + st * BKT * BSTN,
                          wm, wn, g, tig, acc);
    }

    const bool split = (gridDim.z > 1);
    float* outp = split ? (C + (size_t)blockIdx.z * M * N) : C;
#pragma unroll
    for (int mi = 0; mi < 4; mi++) {
        int mrow0 = m0 + wm + mi * 16 + g;
#pragma unroll
        for (int ni = 0; ni < 4; ni++) {
            int ncol = n0 + wn + ni * 8 + 2 * tig;
#pragma unroll
            for (int h = 0; h < 2; h++) {
                int mr = mrow0 + h * 8;
                if (split) {
                    if (ncol < N)     outp[(size_t)mr * ldc + ncol]     = acc[mi][ni][h*2+0];
                    if (ncol + 1 < N) outp[(size_t)mr * ldc + ncol + 1] = acc[mi][ni][h*2+1];
                } else {
                    if (ncol < N) {
                        float bv = bias ? bias[ncol] : 0.f;
                        outp[(size_t)mr * ldc + ncol] = acc[mi][ni][h*2+0] * scale + bv;
                    }
                    if (ncol + 1 < N) {
                        float bv = bias ? bias[ncol + 1] : 0.f;
                        outp[(size_t)mr * ldc + ncol + 1] = acc[mi][ni][h*2+1] * scale + bv;
                    }
                }
            }
        }
    }
}

// ---------------- scores2 GEMM + split softmax*v epilogue ----------------
__global__ void __launch_bounds__(256)
k_score2(const float* __restrict__ A, int lda,
         const float* __restrict__ B, int ldb,
         float* __restrict__ part, int K)
{
    extern __shared__ float smem_dyn[];
    float* AsB = smem_dyn;
    float* BsB = smem_dyn + STAGES * BM * AST;

    const int tid = threadIdx.x;
    const int warp = tid >> 5, lane = tid & 31;
    const int g = lane >> 2, tig = lane & 3;
    const int wm = (warp & 1) * 64;
    const int wn = (warp >> 1) * 32;
    const int m0 = blockIdx.y * BM, n0 = blockIdx.x * BN;
    const int KT = K / BKT;

    float acc[4][4][4];
#pragma unroll
    for (int i = 0; i < 4; i++)
#pragma unroll
        for (int j = 0; j < 4; j++)
#pragma unroll
            for (int c = 0; c < 4; c++) acc[i][j][c] = 0.f;

#pragma unroll
    for (int s = 0; s < STAGES - 1; s++) {
        if (s < KT) load_stage128<true, true>(A, lda, B, ldb, AsB, BsB, m0, n0, N1, K, s, s, tid);
        else cp_commit();
    }
    for (int i = 0; i < KT; i++) {
        cp_wait<STAGES - 2>();
        __syncthreads();
        int j = i + STAGES - 1;
        if (j < KT) load_stage128<true, true>(A, lda, B, ldb, AsB, BsB, m0, n0, N1, K, j, j & (STAGES - 1), tid);
        else cp_commit();
        const int st = i & (STAGES - 1);
        mma_ktile<true>(AsB + st * BM * AST, BsB + st * BN * AST, nullptr, wm, wn, g, tig, acc);
    }

    float v2x[4][2], v2y[4][2];
#pragma unroll
    for (int ni = 0; ni < 4; ni++) {
#pragma unroll
        for (int w = 0; w < 2; w++) {
            int gc = n0 + wn + ni * 8 + 2 * tig + w;
            v2x[ni][w] = g_v2[2 * gc];
            v2y[ni][w] = g_v2[2 * gc + 1];
        }
    }

    __syncthreads();
    float* sred = smem_dyn;

    const int w2 = warp >> 1;
#pragma unroll
    for (int mi = 0; mi < 4; mi++) {
#pragma unroll
        for (int h = 0; h < 2; h++) {
            int rloc = wm + mi * 16 + g + 8 * h;
            float m = -1e30f;
#pragma unroll
            for (int ni = 0; ni < 4; ni++)
#pragma unroll
                for (int w = 0; w < 2; w++)
                    m = fmaxf(m, acc[mi][ni][h * 2 + w] * INV_TEMP);
            float sw = 0.f, s0 = 0.f, s1 = 0.f;
#pragma unroll
            for (int ni = 0; ni < 4; ni++)
#pragma unroll
                for (int w = 0; w < 2; w++) {
                    float e = fexp(acc[mi][ni][h * 2 + w] * INV_TEMP - m);
                    sw += e;
                    s0 += e * v2x[ni][w];
                    s1 += e * v2y[ni][w];
                }
#pragma unroll
            for (int off = 1; off < 4; off <<= 1) {
                float om  = __shfl_xor_sync(0xffffffff, m,  off);
                float osw = __shfl_xor_sync(0xffffffff, sw, off);
                float os0 = __shfl_xor_sync(0xffffffff, s0, off);
                float os1 = __shfl_xor_sync(0xffffffff, s1, off);
                float nm = fmaxf(m, om);
                float ea = fexp(m - nm), eb = fexp(om - nm);
                sw = sw * ea + osw * eb;
                s0 = s0 * ea + os0 * eb;
                s1 = s1 * ea + os1 * eb;
                m = nm;
            }
            if (tig == 0) {
                float* p = sred + ((w2 * BM) + rloc) * 4;
                p[0] = m; p[1] = sw; p[2] = s0; p[3] = s1;
            }
        }
    }
    __syncthreads();

    if (tid < BM) {
        float m = -1e30f, sw = 0.f, s0 = 0.f, s1 = 0.f;
#pragma unroll
        for (int w = 0; w < 4; w++) {
            const float* p = sred + ((w * BM) + tid) * 4;
            float om = p[0], osw = p[1], os0 = p[2], os1 = p[3];
            float nm = fmaxf(m, om);
            float ea = fexp(m - nm), eb = fexp(om - nm);
            sw = sw * ea + osw * eb;
            s0 = s0 * ea + os0 * eb;
            s1 = s1 * ea + os1 * eb;
            m = nm;
        }
        float* p = part + ((size_t)blockIdx.x * N2 + (m0 + tid)) * 4;
        p[0] = m; p[1] = sw; p[2] = s0; p[3] = s1;
    }
}

__global__ void k_comb2(const float* __restrict__ part, float* __restrict__ out) {
    int r = blockIdx.x * blockDim.x + threadIdx.x;
    if (r < N2) {
        float m = -1e30f, sw = 0.f, s0 = 0.f, s1 = 0.f;
        for (int cb = 0; cb < 32; cb++) {
            const float* p = part + ((size_t)cb * N2 + r) * 4;
            float om = p[0], osw = p[1], os0 = p[2], os1 = p[3];
            float nm = fmaxf(m, om);
            float ea = fexp(m - nm), eb = fexp(om - nm);
            sw = sw * ea + osw * eb;
            s0 = s0 * ea + os0 * eb;
            s1 = s1 * ea + os1 * eb;
            m = nm;
        }
        out[2 * r]     = s0 / sw;
        out[2 * r + 1] = s1 / sw;
    }
}

// ---------------- 64x64 tf32 GEMM body (device function) ----------------
#define BM6 64
#define BN6 64

template<bool AVEC16>
__device__ __forceinline__ void gemm64_body(
    const float* __restrict__ A, int lda,
    const float* __restrict__ B, int ldb,
    const float* __restrict__ bias, float* __restrict__ C, int ldc,
    int M, int N, int K, float scale,
    const float* __restrict__ rou1, const float* __restrict__ rt1,
    float* __restrict__ P, int bx, int by, float* smem)
{
    float* AsB = smem;
    float* BsB = smem + STAGES * BM6 * AST;

    const int tid = threadIdx.x;
    const int warp = tid >> 5, lane = tid & 31;
    const int g = lane >> 2, tig = lane & 3;
    const int wm = (warp & 1) * 32;
    const int wn = (warp >> 1) * 32;
    const int m0 = by * BM6, n0 = bx * BN6;

    const int KT = (K + BKT - 1) / BKT;

    float acc[2][4][4];
#pragma unroll
    for (int i = 0; i < 2; i++)
#pragma unroll
        for (int j = 0; j < 4; j++)
#pragma unroll
            for (int c = 0; c < 4; c++) acc[i][j][c] = 0.f;

    auto loadStage = [&](int kt, int st) {
        int k0 = kt * BKT;
        float* as = AsB + st * BM6 * AST;
        float* bs = BsB + st * BN6 * AST;
        if (AVEC16) {
#pragma unroll
            for (int p = 0; p < 2; p++) {
                int c = tid + 128 * p;
                int row = c >> 2, kq = (c & 3) * 4;
                cp16(as + row * AST + kq, A + (size_t)(m0 + row) * lda + k0 + kq, (k0 + kq) < K);
            }
#pragma unroll
            for (int p = 0; p < 2; p++) {
                int c = tid + 128 * p;
                int row = c >> 2, kq = (c & 3) * 4;
                bool v = (n0 + row) < N && (k0 + kq) < K;
                cp16(bs + row * AST + kq, B + (size_t)(n0 + row) * ldb + k0 + kq, v);
            }
        } else {
#pragma unroll
            for (int p = 0; p < 8; p++) {
                int e = tid + 128 * p;
                int row = e >> 4, kk = e & 15;
                cp4(as + row * AST + kk, A + (size_t)(m0 + row) * lda + k0 + kk, (k0 + kk) < K);
            }
#pragma unroll
            for (int p = 0; p < 8; p++) {
                int e = tid + 128 * p;
                int row = e >> 4, kk = e & 15;
                bool v = (n0 + row) < N && (k0 + kk) < K;
                cp4(bs + row * AST + kk, B + (size_t)(n0 + row) * ldb + k0 + kk, v);
            }
        }
        cp_commit();
    };

#pragma unroll
    for (int s = 0; s < STAGES - 1; s++) {
        if (s < KT) loadStage(s, s);
        else cp_commit();
    }

    for (int i = 0; i < KT; i++) {
        cp_wait<STAGES - 2>();
        __syncthreads();
        int j = i + STAGES - 1;
        if (j < KT) loadStage(j, j & (STAGES - 1));
        else cp_commit();
        const int st = i & (STAGES - 1);
        const float* as = AsB + st * BM6 * AST;
        const float* bs = BsB + st * BN6 * AST;

#pragma unroll
        for (int ks = 0; ks < 2; ks++) {
            unsigned af[2][4], bf[4][2];
#pragma unroll
            for (int mi = 0; mi < 2; mi++) {
                const float* pa = as + (wm + mi * 16 + g) * AST + ks * 8 + tig;
                af[mi][0] = f2tf32(pa[0]);
                af[mi][1] = f2tf32(pa[8 * AST]);
                af[mi][2] = f2tf32(pa[4]);
                af[mi][3] = f2tf32(pa[8 * AST + 4]);
            }
#pragma unroll
            for (int ni = 0; ni < 4; ni++) {
                const float* pb = bs + (wn + ni * 8 + g) * AST + ks * 8 + tig;
                bf[ni][0] = f2tf32(pb[0]);
                bf[ni][1] = f2tf32(pb[4]);
            }
#pragma unroll
            for (int mi = 0; mi < 2; mi++)
#pragma unroll
                for (int ni = 0; ni < 4; ni++) {
                    asm volatile(
                        "mma.sync.aligned.m16n8k8.row.col.f32.tf32.tf32.f32 "
                        "{%0,%1,%2,%3}, {%4,%5,%6,%7}, {%8,%9}, {%0,%1,%2,%3};"
                        : "+f"(acc[mi][ni][0]), "+f"(acc[mi][ni][1]),
                          "+f"(acc[mi][ni][2]), "+f"(acc[mi][ni][3])
                        : "r"(af[mi][0]), "r"(af[mi][1]), "r"(af[mi][2]), "r"(af[mi][3]),
                          "r"(bf[ni][0]), "r"(bf[ni][1]));
                }
        }
    }

#pragma unroll
    for (int mi = 0; mi < 2; mi++) {
        int mrow0 = m0 + wm + mi * 16 + g;
#pragma unroll
        for (int ni = 0; ni < 4; ni++) {
            int ncol = n0 + wn + ni * 8 + 2 * tig;
#pragma unroll
            for (int h = 0; h < 2; h++) {
                int mr = mrow0 + h * 8;
#pragma unroll
                for (int w = 0; w < 2; w++) {
                    int nc = ncol + w;
                    if (nc < N) {
                        float bv = bias ? bias[nc] : 0.f;
                        float val = acc[mi][ni][h * 2 + w] * scale + bv;
                        C[(size_t)mr * ldc + nc] = val;
                        if (P) {
                            float rr = rou1[mr];
                            P[(size_t)mr * PD2 + nc] = (val + rr * rt1[nc]) / (1.f + rr + EPSF);
                        }
                    }
                }
            }
        }
    }
}

template<bool AVEC16>
__global__ void __launch_bounds__(128)
mma_gemm64(const float* __restrict__ A, int lda,
           const float* __restrict__ B, int ldb,
           const float* __restrict__ bias, float* __restrict__ C, int ldc,
           int M, int N, int K, float scale,
           const float* __restrict__ rou1, const float* __restrict__ rt1,
           float* __restrict__ P)
{
    extern __shared__ float smem_dyn[];
    gemm64_body<AVEC16>(A, lda, B, ldb, bias, C, ldc, M, N, K, scale,
                        rou1, rt1, P, blockIdx.x, blockIdx.y, smem_dyn);
}

// batched head projections: blocks [0,256) -> k12, [256,320) -> q
__global__ void __launch_bounds__(128)
k_proj_dual(const float* __restrict__ lm_X, const float* __restrict__ tg_X,
            const float* __restrict__ aq_w, const float* __restrict__ aq_b)
{
    extern __shared__ float smem_dyn[];
    if (blockIdx.x < 256) {
        gemm64_body<true>(lm_X, PD, g_wcat, PD, g_bcat, g_k12, 2 * DZ,
                          N1, 2 * DZ, PD, 1.f, nullptr, nullptr, nullptr,
                          blockIdx.x & 3, blockIdx.x >> 2, smem_dyn);
    } else {
        int b = blockIdx.x - 256;
        gemm64_body<true>(tg_X, PD, aq_w, PD, aq_b, g_q, DZ,
                          N2, DZ, PD, 1.f, nullptr, nullptr, nullptr,
                          b & 1, b >> 1, smem_dyn);
    }
}

// ---------------- fused reduce(attr@lmf) + prop0; extra block computes router1 ----
__global__ void k_fuse1(const float* __restrict__ part, const float* __restrict__ tg_X,
                        const float* __restrict__ w1_w, const float* __restrict__ w1_b) {
    if (blockIdx.x == 2064) {            // router1 = routerp @ w1^T + b1 (warp per row)
        int t = threadIdx.x;
        int warp = t >> 5, lane = t & 31;
        for (int j = warp; j < PD2; j += 8) {
            float s = 0.f;
            for (int k = lane; k < PD2; k += 32) s += g_routerp[k] * w1_w[j * PD2 + k];
#pragma unroll
            for (int off = 16; off > 0; off >>= 1) s += __shfl_xor_sync(0xffffffff, s, off);
            if (lane == 0) g_router1[j] = s + w1_b[j];
        }
        return;
    }
    int i = blockIdx.x * blockDim.x + threadIdx.x;
    if (i < N2 * PD2) {
        int r = i / PD2, c = i - r * PD2;
        float s = 0.f;
#pragma unroll
        for (int z = 0; z < 3; z++) s += part[(size_t)z * N2 * PD2 + i];
        float num = s + (c < PD ? tg_X[r * PD + c] : 0.f) + g_rou0[r] * g_router0[c];
        g_P[i] = num / (1.f + g_asum[r] + g_rou0[r] + EPSF);
    }
}

// ---------------- attention 1 softmax (+ router partial combine block) --------
__global__ void k_attr() {
    __shared__ float red[256];
    int t = threadIdx.x;
    if (blockIdx.x == N2) {              // combine row-block partials -> router0, routerp
        float sd = 0.f;
#pragma unroll
        for (int rb = 0; rb < 16; rb++) sd += g_rp_sd[rb];
        for (int c = t; c < PD2; c += 256) {
            float sx = 0.f, sdx = 0.f;
#pragma unroll
            for (int rb = 0; rb < 16; rb++) {
                sx  += g_rp_sx[rb * PD2 + c];
                sdx += g_rp_sdx[rb * PD2 + c];
            }
            float r0v = sx * (1.0f / N1);
            g_router0[c] = r0v;
            g_routerp[c] = (sdx + r0v) / (1.f + sd + EPSF);
        }
        return;
    }
    int r = blockIdx.x;
    float* s = g_S + (size_t)r * N1;
    float e[16];
    float m = -1e30f;
#pragma unroll
    for (int i = 0; i < 16; i++) { e[i] = s[t + i * 256]; m = fmaxf(m, e[i]); }
    m = blk_max<256>(m, red);
    float z = 0.f;
#pragma unroll
    for (int i = 0; i < 16; i++) { e[i] = fexp(e[i] - m); z += e[i]; }
    z = blk_sum<256>(z, red);
    float inv = 1.f / z;
    float rs = 0.f;
#pragma unroll
    for (int i = 0; i < 16; i++) {
        float v = fexp(e[i] * inv);
        s[t + i * 256] = v;
        rs += v;
    }
    rs = blk_sum<256>(rs, red);
    if (t == 0) g_asum[r] = rs;
}

// ---------------- host launch ----------------
static float* sym_addr(const void* s) {
    void* p = nullptr;
    cudaGetSymbolAddress(&p, s);
    return (float*)p;
}

#define SMEM_TT ((STAGES * BM * AST + STAGES * BN * AST) * 4)
#define SMEM_FF ((STAGES * BM * AST + STAGES * BKT * BSTN) * 4)
#define SMEM_64 ((STAGES * BM6 * AST * 2) * 4)

extern "C" void kernel_launch(void* const* d_in, const int* in_sizes, int n_in,
                              void* d_out, int out_size) {
    const float* lm_X    = (const float*)d_in[0];
    const float* lm_Y    = (const float*)d_in[1];
    const float* tg_X    = (const float*)d_in[2];
    const float* lm_delay= (const float*)d_in[4];
    const float* tg_delay= (const float*)d_in[5];
    const float* aq_w    = (const float*)d_in[6];
    const float* aq_b    = (const float*)d_in[7];
    const float* ak_w    = (const float*)d_in[8];
    const float* ak_b    = (const float*)d_in[9];
    const float* w1_w    = (const float*)d_in[10];
    const float* w1_b    = (const float*)d_in[11];
    const float* w2_w    = (const float*)d_in[12];
    const float* w2_b    = (const float*)d_in[13];
    const float* pq_w    = (const float*)d_in[14];
    const float* pq_b    = (const float*)d_in[15];
    const float* pk_w    = (const float*)d_in[16];
    const float* pk_b    = (const float*)d_in[17];
    const float* pv_w    = (const float*)d_in[18];
    const float* pv_b    = (const float*)d_in[19];
    const float* gamma1  = (const float*)d_in[20];
    const float* gamma2  = (const float*)d_in[21];
    const float* gamma3  = (const float*)d_in[22];
    const float* alpha   = (const float*)d_in[23];
    const float* beta    = (const float*)d_in[24];
    float* out = (float*)d_out;

    float* pk12  = sym_addr(g_k12);
    float* pq    = sym_addr(g_q);
    float* pq2   = sym_addr(g_q2);
    float* pS    = sym_addr(g_S);
    float* plmf  = sym_addr(g_lmf);
    float* pP    = sym_addr(g_P);
    float* pPart = sym_addr(g_part);
    float* prou1 = sym_addr(g_rou1);
    float* prt1  = sym_addr(g_router1);

    cudaFuncSetAttribute(mma_gemm<true, true>,  cudaFuncAttributeMaxDynamicSharedMemorySize, SMEM_TT);
    cudaFuncSetAttribute(mma_gemm<false, true>, cudaFuncAttributeMaxDynamicSharedMemorySize, SMEM_FF);
    cudaFuncSetAttribute(k_score2, cudaFuncAttributeMaxDynamicSharedMemorySize, SMEM_TT);
    cudaFuncSetAttribute(mma_gemm64<true>,  cudaFuncAttributeMaxDynamicSharedMemorySize, SMEM_64);
    cudaFuncSetAttribute(mma_gemm64<false>, cudaFuncAttributeMaxDynamicSharedMemorySize, SMEM_64);
    cudaFuncSetAttribute(k_proj_dual, cudaFuncAttributeMaxDynamicSharedMemorySize, SMEM_64);

    dim3 blk(256), blk64(128);
    auto grd = [](int M, int N, int S) {
        return dim3((N + BN - 1) / BN, (M + BM - 1) / BM, S);
    };
    auto grd64 = [](int M, int N) {
        return dim3((N + BN6 - 1) / BN6, (M + BM6 - 1) / BM6, 1);
    };

    // 1. fused prep (lmf, tgX->out, wcat, v2, router col-partials, rou)
    k_prep_all<<<B_PREP_TOT, blk>>>(lm_X, lm_Y, tg_X, ak_w, pk_w, ak_b, pk_b,
                                    lm_delay, tg_delay, gamma1, gamma2, gamma3,
                                    alpha, beta, pv_w, pv_b, out);

    // 2. batched head projections (k12 + q)
    k_proj_dual<<<320, blk64, SMEM_64>>>(lm_X, tg_X, aq_w, aq_b);

    // 3. scores1 = q @ k1^T
    mma_gemm<true, true><<<grd(N2, N1, 1), blk, SMEM_TT>>>(pq, DZ, pk12, 2 * DZ, nullptr, pS, N1, N2, N1, DZ, INV_TEMP);

    // 4. softmax->attr (+ router partial combine)
    k_attr<<<N2 + 1, blk>>>();

    // 5. attr @ lm_feature, split-3 (one wave)
    mma_gemm<false, true><<<grd(N2, PD2, 3), blk, SMEM_FF>>>(pS, N1, plmf, PD2, nullptr, pPart, PD2, N2, PD2, N1, 1.f);

    // 6. fused reduce + prop0 (+ router1 block)
    k_fuse1<<<2065, blk>>>(pPart, tg_X, w1_w, w1_b);

    // 7. f1 = P @ w1^T -> out, fused prop1
    mma_gemm64<false><<<grd64(N2, PD2), blk64, SMEM_64>>>(pP, PD2, w1_w, PD2, w1_b, out + N2 * 2 + PD, FD, N2, PD2, PD2, 1.f, prou1, prt1, pP);

    // 8. f2 = P @ w2^T -> out
    mma_gemm64<false><<<grd64(N2, PD2), blk64, SMEM_64>>>(pP, PD2, w2_w, PD2, w2_b, out + N2 * 2 + PD + PD2, FD, N2, PD2, PD2, 1.f, nullptr, nullptr, nullptr);

    // 9. q2 = final_features @ pq_w^T
    mma_gemm64<true><<<grd64(N2, DZ), blk64, SMEM_64>>>(out + N2 * 2, FD, pq_w, FD, pq_b, pq2, DZ, N2, DZ, FD, 1.f, nullptr, nullptr, nullptr);

    // 10-11. attention 2: fused scores+softmax partials, then combine
    k_score2<<<dim3(N1 / BN, N2 / BM, 1), blk, SMEM_TT>>>(pq2, DZ, pk12 + DZ, 2 * DZ, pPart, DZ);
    k_comb2<<<(N2 + 255) / 256, blk>>>(pPart, out);
}

// round 9
// speedup vs baseline: 1.3457x; 1.1338x over previous
#include <cuda_runtime.h>
#include <math.h>

// ---------------- problem constants ----------------
#define N1 4096
#define N2 2048
#define PD 256
#define DZ 128
#define PD2 258
#define FD 772
#define EPSF 1e-12f
#define INV_TEMP 0.08838834764831843f   // 1/sqrt(128)

// ---------------- device scratch ----------------
__device__ float g_k12[N1 * 2 * DZ];   // [k1 | k2], row stride 256
__device__ float g_q[N2 * DZ];
__device__ float g_q2[N2 * DZ];
__device__ float g_q2a[N2 * DZ];
__device__ float g_q2b[N2 * DZ];
__device__ float g_S[(size_t)N2 * N1];
__device__ float g_lmf[N1 * PD2];
__device__ float g_P[N2 * PD2];
__device__ float g_part[4 * 2048 * 258];   // split-K partials / attn2 partials alias
__device__ float g_rp_sx[16 * PD2];
__device__ float g_rp_sdx[16 * PD2];
__device__ float g_rp_sd[16];
__device__ float g_router0[PD2];
__device__ float g_routerp[PD2];
__device__ float g_router1[PD2];
__device__ float g_rou0[N2];
__device__ float g_rou1[N2];
__device__ float g_asum[N2];
__device__ float g_v2[N1 * 2];

// ---------------- helpers ----------------
__device__ __forceinline__ float fexp(float x) {
    float y;
    asm("ex2.approx.f32 %0, %1;" : "=f"(y) : "f"(x * 1.4426950408889634f));
    return y;
}
__device__ __forceinline__ unsigned f2tf32(float x) {
    unsigned r;
    asm("cvt.rna.tf32.f32 %0, %1;" : "=r"(r) : "f"(x));
    return r;
}
__device__ __forceinline__ void cp16(float* dst, const float* src, bool valid) {
    unsigned d = (unsigned)__cvta_generic_to_shared(dst);
    int sz = valid ? 16 : 0;
    asm volatile("cp.async.cg.shared.global [%0], [%1], 16, %2;" :: "r"(d), "l"(src), "r"(sz));
}
__device__ __forceinline__ void cp4(float* dst, const float* src, bool valid) {
    unsigned d = (unsigned)__cvta_generic_to_shared(dst);
    int sz = valid ? 4 : 0;
    asm volatile("cp.async.ca.shared.global [%0], [%1], 4, %2;" :: "r"(d), "l"(src), "r"(sz));
}
__device__ __forceinline__ void cp_commit() { asm volatile("cp.async.commit_group;"); }
template<int N_>
__device__ __forceinline__ void cp_wait() {
    asm volatile("cp.async.wait_group %0;" :: "n"(N_));
}

template<int TB>
__device__ __forceinline__ float blk_sum(float v, float* red) {
    int t = threadIdx.x;
    red[t] = v; __syncthreads();
    for (int s = TB >> 1; s > 0; s >>= 1) {
        if (t < s) red[t] += red[t + s];
        __syncthreads();
    }
    float r = red[0]; __syncthreads();
    return r;
}
template<int TB>
__device__ __forceinline__ float blk_max(float v, float* red) {
    int t = threadIdx.x;
    red[t] = v; __syncthreads();
    for (int s = TB >> 1; s > 0; s >>= 1) {
        if (t < s) red[t] = fmaxf(red[t], red[t + s]);
        __syncthreads();
    }
    float r = red[0]; __syncthreads();
    return r;
}

// ---------------- GEMM tile configs ----------------
#define BM 128
#define BN 128
#define BKT 16
#define AST 20
#define BSTN 132
#define STAGES 4
#define BM6 64
#define BN6 64

// ---------------- 64x64 tf32 GEMM body ----------------
template<bool AVEC16>
__device__ __forceinline__ void gemm64_body(
    const float* __restrict__ A, int lda,
    const float* __restrict__ B, int ldb,
    const float* __restrict__ bias, float* __restrict__ C, int ldc,
    int N, int K, float scale,
    const float* __restrict__ rou1, const float* __restrict__ rt1,
    float* __restrict__ P,
    const float* __restrict__ add1, const float* __restrict__ add2,
    int bx, int by, float* smem)
{
    float* AsB = smem;
    float* BsB = smem + STAGES * BM6 * AST;

    const int tid = threadIdx.x;
    const int warp = tid >> 5, lane = tid & 31;
    const int g = lane >> 2, tig = lane & 3;
    const int wm = (warp & 1) * 32;
    const int wn = (warp >> 1) * 32;
    const int m0 = by * BM6, n0 = bx * BN6;

    const int KT = (K + BKT - 1) / BKT;

    float acc[2][4][4];
#pragma unroll
    for (int i = 0; i < 2; i++)
#pragma unroll
        for (int j = 0; j < 4; j++)
#pragma unroll
            for (int c = 0; c < 4; c++) acc[i][j][c] = 0.f;

    auto loadStage = [&](int kt, int st) {
        int k0 = kt * BKT;
        float* as = AsB + st * BM6 * AST;
        float* bs = BsB + st * BN6 * AST;
        if (AVEC16) {
#pragma unroll
            for (int p = 0; p < 2; p++) {
                int c = tid + 128 * p;
                int row = c >> 2, kq = (c & 3) * 4;
                cp16(as + row * AST + kq, A + (size_t)(m0 + row) * lda + k0 + kq, (k0 + kq) < K);
            }
#pragma unroll
            for (int p = 0; p < 2; p++) {
                int c = tid + 128 * p;
                int row = c >> 2, kq = (c & 3) * 4;
                bool v = (n0 + row) < N && (k0 + kq) < K;
                cp16(bs + row * AST + kq, B + (size_t)(n0 + row) * ldb + k0 + kq, v);
            }
        } else {
#pragma unroll
            for (int p = 0; p < 8; p++) {
                int e = tid + 128 * p;
                int row = e >> 4, kk = e & 15;
                cp4(as + row * AST + kk, A + (size_t)(m0 + row) * lda + k0 + kk, (k0 + kk) < K);
            }
#pragma unroll
            for (int p = 0; p < 8; p++) {
                int e = tid + 128 * p;
                int row = e >> 4, kk = e & 15;
                bool v = (n0 + row) < N && (k0 + kk) < K;
                cp4(bs + row * AST + kk, B + (size_t)(n0 + row) * ldb + k0 + kk, v);
            }
        }
        cp_commit();
    };

#pragma unroll
    for (int s = 0; s < STAGES - 1; s++) {
        if (s < KT) loadStage(s, s);
        else cp_commit();
    }

    for (int i = 0; i < KT; i++) {
        cp_wait<STAGES - 2>();
        __syncthreads();
        int j = i + STAGES - 1;
        if (j < KT) loadStage(j, j & (STAGES - 1));
        else cp_commit();
        const int st = i & (STAGES - 1);
        const float* as = AsB + st * BM6 * AST;
        const float* bs = BsB + st * BN6 * AST;

#pragma unroll
        for (int ks = 0; ks < 2; ks++) {
            unsigned af[2][4], bf[4][2];
#pragma unroll
            for (int mi = 0; mi < 2; mi++) {
                const float* pa = as + (wm + mi * 16 + g) * AST + ks * 8 + tig;
                af[mi][0] = f2tf32(pa[0]);
                af[mi][1] = f2tf32(pa[8 * AST]);
                af[mi][2] = f2tf32(pa[4]);
                af[mi][3] = f2tf32(pa[8 * AST + 4]);
            }
#pragma unroll
            for (int ni = 0; ni < 4; ni++) {
                const float* pb = bs + (wn + ni * 8 + g) * AST + ks * 8 + tig;
                bf[ni][0] = f2tf32(pb[0]);
                bf[ni][1] = f2tf32(pb[4]);
            }
#pragma unroll
            for (int mi = 0; mi < 2; mi++)
#pragma unroll
                for (int ni = 0; ni < 4; ni++) {
                    asm volatile(
                        "mma.sync.aligned.m16n8k8.row.col.f32.tf32.tf32.f32 "
                        "{%0,%1,%2,%3}, {%4,%5,%6,%7}, {%8,%9}, {%0,%1,%2,%3};"
                        : "+f"(acc[mi][ni][0]), "+f"(acc[mi][ni][1]),
                          "+f"(acc[mi][ni][2]), "+f"(acc[mi][ni][3])
                        : "r"(af[mi][0]), "r"(af[mi][1]), "r"(af[mi][2]), "r"(af[mi][3]),
                          "r"(bf[ni][0]), "r"(bf[ni][1]));
                }
        }
    }

#pragma unroll
    for (int mi = 0; mi < 2; mi++) {
        int mrow0 = m0 + wm + mi * 16 + g;
#pragma unroll
        for (int ni = 0; ni < 4; ni++) {
            int ncol = n0 + wn + ni * 8 + 2 * tig;
#pragma unroll
            for (int h = 0; h < 2; h++) {
                int mr = mrow0 + h * 8;
                if (ncol < N) {        // N even, pairs valid together
                    float2 bv = bias ? *(const float2*)(bias + ncol) : make_float2(0.f, 0.f);
                    float v0 = acc[mi][ni][h * 2 + 0] * scale + bv.x;
                    float v1 = acc[mi][ni][h * 2 + 1] * scale + bv.y;
                    if (add1) {
                        float2 a1 = *(const float2*)(add1 + (size_t)mr * ldc + ncol);
                        v0 += a1.x; v1 += a1.y;
                    }
                    if (add2) {
                        float2 a2 = *(const float2*)(add2 + (size_t)mr * ldc + ncol);
                        v0 += a2.x; v1 += a2.y;
                    }
                    *(float2*)(C + (size_t)mr * ldc + ncol) = make_float2(v0, v1);
                    if (P) {
                        float rr = rou1[mr];
                        float inv = 1.f / (1.f + rr + EPSF);
                        *(float2*)(P + (size_t)mr * PD2 + ncol) =
                            make_float2((v0 + rr * rt1[ncol]) * inv,
                                        (v1 + rr * rt1[ncol + 1]) * inv);
                    }
                }
            }
        }
    }
}

// ---------------- front mega-kernel: projections + prep, 128-thread blocks ----
#define BF_GEMM 384     // 128 ak + 128 pk + 64 q + 64 q2a
#define BF_LMF  8256    // N1*PD2/128
#define BF_TGX  4096    // N2*PD/128
#define BF_V2   32
#define BF_RPA  16
#define BF_ROU  16
#define BF_TOT (BF_GEMM + BF_LMF + BF_TGX + BF_V2 + BF_RPA + BF_ROU)

__global__ void __launch_bounds__(128)
k_front(const float* __restrict__ lm_X, const float* __restrict__ lm_Y,
        const float* __restrict__ tg_X,
        const float* __restrict__ ak_w, const float* __restrict__ ak_b,
        const float* __restrict__ pk_w, const float* __restrict__ pk_b,
        const float* __restrict__ aq_w, const float* __restrict__ aq_b,
        const float* __restrict__ pq_w, const float* __restrict__ pq_b,
        const float* __restrict__ lm_delay, const float* __restrict__ tg_delay,
        const float* g1p, const float* g2p, const float* g3p,
        const float* ap, const float* bp,
        const float* __restrict__ pv_w, const float* __restrict__ pv_b,
        float* __restrict__ out)
{
    extern __shared__ float smem_dyn[];
    int bid = blockIdx.x, t = threadIdx.x;

    if (bid < 128) {            // k1 = lm_X @ ak_w^T  (cols 0..127 of k12)
        gemm64_body<true>(lm_X, PD, ak_w, PD, ak_b, g_k12, 2 * DZ, DZ, PD, 1.f,
                          nullptr, nullptr, nullptr, nullptr, nullptr,
                          bid & 1, bid >> 1, smem_dyn);
        return;
    }
    bid -= 128;
    if (bid < 128) {            // k2 = lm_X @ pk_w^T  (cols 128..255 of k12)
        gemm64_body<true>(lm_X, PD, pk_w, PD, pk_b, g_k12 + DZ, 2 * DZ, DZ, PD, 1.f,
                          nullptr, nullptr, nullptr, nullptr, nullptr,
                          bid & 1, bid >> 1, smem_dyn);
        return;
    }
    bid -= 128;
    if (bid < 64) {             // q = tg_X @ aq_w^T
        gemm64_body<true>(tg_X, PD, aq_w, PD, aq_b, g_q, DZ, DZ, PD, 1.f,
                          nullptr, nullptr, nullptr, nullptr, nullptr,
                          bid & 1, bid >> 1, smem_dyn);
        return;
    }
    bid -= 64;
    if (bid < 64) {             // q2a = tg_X @ pq_w[:, :256]^T + pq_b
        gemm64_body<true>(tg_X, PD, pq_w, FD, pq_b, g_q2a, DZ, DZ, PD, 1.f,
                          nullptr, nullptr, nullptr, nullptr, nullptr,
                          bid & 1, bid >> 1, smem_dyn);
        return;
    }
    bid -= 64;
    if (bid < BF_LMF) {         // lm_feature assembly
        int i = bid * 128 + t;
        int r = i / PD2, c = i - r * PD2;
        g_lmf[i] = (c < PD) ? lm_X[r * PD + c] : lm_Y[r * 2 + (c - PD)];
        return;
    }
    bid -= BF_LMF;
    if (bid < BF_TGX) {         // tg_X -> out feature block
        int j = bid * 128 + t;
        int r = j >> 8, c = j & 255;
        out[N2 * 2 + r * FD + c] = tg_X[j];
        return;
    }
    bid -= BF_TGX;
    if (bid < BF_V2) {          // v2 projection
        int i = bid * 128 + t;
        float y0 = lm_Y[2 * i], y1 = lm_Y[2 * i + 1];
        g_v2[2 * i]     = pv_w[0] * y0 + pv_w[1] * y1 + pv_b[0];
        g_v2[2 * i + 1] = pv_w[2] * y0 + pv_w[3] * y1 + pv_b[1];
        return;
    }
    bid -= BF_V2;
    if (bid < BF_RPA) {         // row-blocked col sums (router0 / routerp partials)
        int r0 = bid * 256;
        int lane = t & 31;
        float a = ap[0], b = bp[0], g1 = g1p[0];
        float ax0 = 0.f, ad0 = 0.f, ax1 = 0.f, ad1 = 0.f, ay = 0.f, ady = 0.f, sd = 0.f;
        for (int ch = 0; ch < 256; ch += 32) {
            float dl = fexp(-g1 * (a * lm_delay[r0 + ch + lane] + b));
#pragma unroll
            for (int k2 = 0; k2 < 32; k2++) {
                float d = __shfl_sync(0xffffffff, dl, k2);
                int rr = r0 + ch + k2;
                float x0 = lm_X[rr * PD + t];
                float x1 = lm_X[rr * PD + t + 128];
                ax0 += x0; ad0 += d * x0;
                ax1 += x1; ad1 += d * x1;
                if (t < 2) {
                    float y = lm_Y[rr * 2 + t];
                    ay += y; ady += d * y;
                }
                sd += d;
            }
        }
        g_rp_sx[bid * PD2 + t]        = ax0;
        g_rp_sdx[bid * PD2 + t]       = ad0;
        g_rp_sx[bid * PD2 + t + 128]  = ax1;
        g_rp_sdx[bid * PD2 + t + 128] = ad1;
        if (t < 2) {
            g_rp_sx[bid * PD2 + 256 + t]  = ay;
            g_rp_sdx[bid * PD2 + 256 + t] = ady;
        }
        if (t == 0) g_rp_sd[bid] = sd;
        return;
    }
    bid -= BF_RPA;
    {                           // rou0 / rou1
        int i = bid * 128 + t;
        float a = ap[0], b = bp[0], g2 = g2p[0], g3 = g3p[0];
        float x = a * tg_delay[i] + b;
        g_rou0[i] = fexp(-g2 * x);
        g_rou1[i] = fexp(-g3 * x);
    }
}

// ---------------- 128x128 machinery ----------------
template<bool BTRANS, bool AVEC16>
__device__ __forceinline__ void load_stage128(
    const float* __restrict__ A, int lda, const float* __restrict__ B, int ldb,
    float* AsB, float* BsB, int m0, int n0, int N, int K, int kt, int st, int tid)
{
    int k0 = kt * BKT;
    float* as = AsB + st * BM * AST;
    if (AVEC16) {
#pragma unroll
        for (int p = 0; p < 2; p++) {
            int c = tid + 256 * p;
            int row = c >> 2, kq = (c & 3) * 4;
            cp16(as + row * AST + kq, A + (size_t)(m0 + row) * lda + k0 + kq, (k0 + kq) < K);
        }
    } else {
#pragma unroll
        for (int p = 0; p < 8; p++) {
            int e = tid + 256 * p;
            int row = e >> 4, kk = e & 15;
            cp4(as + row * AST + kk, A + (size_t)(m0 + row) * lda + k0 + kk, (k0 + kk) < K);
        }
    }
    if (BTRANS) {
        float* bs = BsB + st * BN * AST;
        if (AVEC16) {
#pragma unroll
            for (int p = 0; p < 2; p++) {
                int c = tid + 256 * p;
                int row = c >> 2, kq = (c & 3) * 4;
                bool v = (n0 + row) < N && (k0 + kq) < K;
                cp16(bs + row * AST + kq, B + (size_t)(n0 + row) * ldb + k0 + kq, v);
            }
        } else {
#pragma unroll
            for (int p = 0; p < 8; p++) {
                int e = tid + 256 * p;
                int row = e >> 4, kk = e & 15;
                bool v = (n0 + row) < N && (k0 + kk) < K;
                cp4(bs + row * AST + kk, B + (size_t)(n0 + row) * ldb + k0 + kk, v);
            }
        }
    } else {
        float* bs = BsB + st * BKT * BSTN;
#pragma unroll
        for (int p = 0; p < 8; p++) {
            int e = tid + 256 * p;
            int kk = e >> 7, n = e & 127;
            bool v = (k0 + kk) < K && (n0 + n) < N;
            cp4(bs + kk * BSTN + n, B + (size_t)(k0 + kk) * ldb + n0 + n, v);
        }
    }
    cp_commit();
}

template<bool BTRANS>
__device__ __forceinline__ void mma_ktile(
    const float* as, const float* bsT, const float* bsN,
    int wm, int wn, int g, int tig, float acc[4][4][4])
{
#pragma unroll
    for (int ks = 0; ks < 2; ks++) {
        unsigned af[4][4], bf[4][2];
#pragma unroll
        for (int mi = 0; mi < 4; mi++) {
            const float* pa = as + (wm + mi * 16 + g) * AST + ks * 8 + tig;
            af[mi][0] = f2tf32(pa[0]);
            af[mi][1] = f2tf32(pa[8 * AST]);
            af[mi][2] = f2tf32(pa[4]);
            af[mi][3] = f2tf32(pa[8 * AST + 4]);
        }
#pragma unroll
        for (int ni = 0; ni < 4; ni++) {
            if (BTRANS) {
                const float* pb = bsT + (wn + ni * 8 + g) * AST + ks * 8 + tig;
                bf[ni][0] = f2tf32(pb[0]);
                bf[ni][1] = f2tf32(pb[4]);
            } else {
                const float* pb = bsN + (ks * 8 + tig) * BSTN + wn + ni * 8 + g;
                bf[ni][0] = f2tf32(pb[0]);
                bf[ni][1] = f2tf32(pb[4 * BSTN]);
            }
        }
#pragma unroll
        for (int mi = 0; mi < 4; mi++)
#pragma unroll
            for (int ni = 0; ni < 4; ni++) {
                asm volatile(
                    "mma.sync.aligned.m16n8k8.row.col.f32.tf32.tf32.f32 "
                    "{%0,%1,%2,%3}, {%4,%5,%6,%7}, {%8,%9}, {%0,%1,%2,%3};"
                    : "+f"(acc[mi][ni][0]), "+f"(acc[mi][ni][1]),
                      "+f"(acc[mi][ni][2]), "+f"(acc[mi][ni][3])
                    : "r"(af[mi][0]), "r"(af[mi][1]), "r"(af[mi][2]), "r"(af[mi][3]),
                      "r"(bf[ni][0]), "r"(bf[ni][1]));
            }
    }
}

template<bool BTRANS, bool AVEC16>
__global__ void __launch_bounds__(256)
mma_gemm(const float* __restrict__ A, int lda,
         const float* __restrict__ B, int ldb,
         float* __restrict__ C, int ldc,
         int M, int N, int K, float scale)
{
    extern __shared__ float smem_dyn[];
    float* AsB = smem_dyn;
    float* BsB = smem_dyn + STAGES * BM * AST;

    const int tid = threadIdx.x;
    const int warp = tid >> 5, lane = tid & 31;
    const int g = lane >> 2, tig = lane & 3;
    const int wm = (warp & 1) * 64;
    const int wn = (warp >> 1) * 32;
    const int m0 = blockIdx.y * BM, n0 = blockIdx.x * BN;

    const int KT = (K + BKT - 1) / BKT;
    const int SPLIT = gridDim.z;
    const int KTs = (KT + SPLIT - 1) / SPLIT;
    const int kt0 = blockIdx.z * KTs;
    const int kt1 = min(KT, kt0 + KTs);
    const int nk = kt1 - kt0;

    float acc[4][4][4];
#pragma unroll
    for (int i = 0; i < 4; i++)
#pragma unroll
        for (int j = 0; j < 4; j++)
#pragma unroll
            for (int c = 0; c < 4; c++) acc[i][j][c] = 0.f;

#pragma unroll
    for (int s = 0; s < STAGES - 1; s++) {
        if (s < nk) load_stage128<BTRANS, AVEC16>(A, lda, B, ldb, AsB, BsB, m0, n0, N, K, kt0 + s, s, tid);
        else cp_commit();
    }

    for (int i = 0; i < nk; i++) {
        cp_wait<STAGES - 2>();
        __syncthreads();
        int j = i + STAGES - 1;
        if (j < nk) load_stage128<BTRANS, AVEC16>(A, lda, B, ldb, AsB, BsB, m0, n0, N, K, kt0 + j, j & (STAGES - 1), tid);
        else cp_commit();
        const int st = i & (STAGES - 1);
        mma_ktile<BTRANS>(AsB + st * BM * AST, BsB + st * BN * AST, BsB + st * BKT * BSTN,
                          wm, wn, g, tig, acc);
    }

    float* outp = (gridDim.z > 1) ? (C + (size_t)blockIdx.z * M * N) : C;
#pragma unroll
    for (int mi = 0; mi < 4; mi++) {
        int mrow0 = m0 + wm + mi * 16 + g;
#pragma unroll
        for (int ni = 0; ni < 4; ni++) {
            int ncol = n0 + wn + ni * 8 + 2 * tig;
#pragma unroll
            for (int h = 0; h < 2; h++) {
                int mr = mrow0 + h * 8;
                if (ncol < N) {    // N even -> pair valid
                    *(float2*)(outp + (size_t)mr * ldc + ncol) =
                        make_float2(acc[mi][ni][h*2+0] * scale, acc[mi][ni][h*2+1] * scale);
                }
            }
        }
    }
}

// ---------------- scores2 GEMM + split softmax*v epilogue ----------------
__global__ void __launch_bounds__(256)
k_score2(const float* __restrict__ A, int lda,
         const float* __restrict__ B, int ldb,
         float* __restrict__ part, int K)
{
    extern __shared__ float smem_dyn[];
    float* AsB = smem_dyn;
    float* BsB = smem_dyn + STAGES * BM * AST;

    const int tid = threadIdx.x;
    const int warp = tid >> 5, lane = tid & 31;
    const int g = lane >> 2, tig = lane & 3;
    const int wm = (warp & 1) * 64;
    const int wn = (warp >> 1) * 32;
    const int m0 = blockIdx.y * BM, n0 = blockIdx.x * BN;
    const int KT = K / BKT;

    float acc[4][4][4];
#pragma unroll
    for (int i = 0; i < 4; i++)
#pragma unroll
        for (int j = 0; j < 4; j++)
#pragma unroll
            for (int c = 0; c < 4; c++) acc[i][j][c] = 0.f;

#pragma unroll
    for (int s = 0; s < STAGES - 1; s++) {
        if (s < KT) load_stage128<true, true>(A, lda, B, ldb, AsB, BsB, m0, n0, N1, K, s, s, tid);
        else cp_commit();
    }
    for (int i = 0; i < KT; i++) {
        cp_wait<STAGES - 2>();
        __syncthreads();
        int j = i + STAGES - 1;
        if (j < KT) load_stage128<true, true>(A, lda, B, ldb, AsB, BsB, m0, n0, N1, K, j, j & (STAGES - 1), tid);
        else cp_commit();
        const int st = i & (STAGES - 1);
        mma_ktile<true>(AsB + st * BM * AST, BsB + st * BN * AST, nullptr, wm, wn, g, tig, acc);
    }

    float v2x[4][2], v2y[4][2];
#pragma unroll
    for (int ni = 0; ni < 4; ni++) {
#pragma unroll
        for (int w = 0; w < 2; w++) {
            int gc = n0 + wn + ni * 8 + 2 * tig + w;
            v2x[ni][w] = g_v2[2 * gc];
            v2y[ni][w] = g_v2[2 * gc + 1];
        }
    }

    __syncthreads();
    float* sred = smem_dyn;
    const int w2 = warp >> 1;
#pragma unroll
    for (int mi = 0; mi < 4; mi++) {
#pragma unroll
        for (int h = 0; h < 2; h++) {
            int rloc = wm + mi * 16 + g + 8 * h;
            float m = -1e30f;
#pragma unroll
            for (int ni = 0; ni < 4; ni++)
#pragma unroll
                for (int w = 0; w < 2; w++)
                    m = fmaxf(m, acc[mi][ni][h * 2 + w] * INV_TEMP);
            float sw = 0.f, s0 = 0.f, s1 = 0.f;
#pragma unroll
            for (int ni = 0; ni < 4; ni++)
#pragma unroll
                for (int w = 0; w < 2; w++) {
                    float e = fexp(acc[mi][ni][h * 2 + w] * INV_TEMP - m);
                    sw += e;
                    s0 += e * v2x[ni][w];
                    s1 += e * v2y[ni][w];
                }
#pragma unroll
            for (int off = 1; off < 4; off <<= 1) {
                float om  = __shfl_xor_sync(0xffffffff, m,  off);
                float osw = __shfl_xor_sync(0xffffffff, sw, off);
                float os0 = __shfl_xor_sync(0xffffffff, s0, off);
                float os1 = __shfl_xor_sync(0xffffffff, s1, off);
                float nm = fmaxf(m, om);
                float ea = fexp(m - nm), eb = fexp(om - nm);
                sw = sw * ea + osw * eb;
                s0 = s0 * ea + os0 * eb;
                s1 = s1 * ea + os1 * eb;
                m = nm;
            }
            if (tig == 0) {
                float* p = sred + ((w2 * BM) + rloc) * 4;
                p[0] = m; p[1] = sw; p[2] = s0; p[3] = s1;
            }
        }
    }
    __syncthreads();

    if (tid < BM) {
        float m = -1e30f, sw = 0.f, s0 = 0.f, s1 = 0.f;
#pragma unroll
        for (int w = 0; w < 4; w++) {
            const float* p = sred + ((w * BM) + tid) * 4;
            float om = p[0], osw = p[1], os0 = p[2], os1 = p[3];
            float nm = fmaxf(m, om);
            float ea = fexp(m - nm), eb = fexp(om - nm);
            sw = sw * ea + osw * eb;
            s0 = s0 * ea + os0 * eb;
            s1 = s1 * ea + os1 * eb;
            m = nm;
        }
        float* p = part + ((size_t)blockIdx.x * N2 + (m0 + tid)) * 4;
        p[0] = m; p[1] = sw; p[2] = s0; p[3] = s1;
    }
}

__global__ void k_comb2(const float* __restrict__ part, float* __restrict__ out) {
    int r = blockIdx.x * blockDim.x + threadIdx.x;
    if (r < N2) {
        float m = -1e30f, sw = 0.f, s0 = 0.f, s1 = 0.f;
        for (int cb = 0; cb < 32; cb++) {
            const float* p = part + ((size_t)cb * N2 + r) * 4;
            float om = p[0], osw = p[1], os0 = p[2], os1 = p[3];
            float nm = fmaxf(m, om);
            float ea = fexp(m - nm), eb = fexp(om - nm);
            sw = sw * ea + osw * eb;
            s0 = s0 * ea + os0 * eb;
            s1 = s1 * ea + os1 * eb;
            m = nm;
        }
        out[2 * r]     = s0 / sw;
        out[2 * r + 1] = s1 / sw;
    }
}

// ---------------- attention 1 softmax (+ router partial combine block) --------
__global__ void k_attr() {
    __shared__ float red[256];
    int t = threadIdx.x;
    if (blockIdx.x == N2) {
        float sd = 0.f;
#pragma unroll
        for (int rb = 0; rb < 16; rb++) sd += g_rp_sd[rb];
        for (int c = t; c < PD2; c += 256) {
            float sx = 0.f, sdx = 0.f;
#pragma unroll
            for (int rb = 0; rb < 16; rb++) {
                sx  += g_rp_sx[rb * PD2 + c];
                sdx += g_rp_sdx[rb * PD2 + c];
            }
            float r0v = sx * (1.0f / N1);
            g_router0[c] = r0v;
            g_routerp[c] = (sdx + r0v) / (1.f + sd + EPSF);
        }
        return;
    }
    int r = blockIdx.x;
    float* s = g_S + (size_t)r * N1;
    float e[16];
    float m = -1e30f;
#pragma unroll
    for (int i = 0; i < 4; i++) {
        float4 v = *(const float4*)(s + t * 4 + i * 1024);
        e[i*4+0] = v.x; e[i*4+1] = v.y; e[i*4+2] = v.z; e[i*4+3] = v.w;
        m = fmaxf(fmaxf(fmaxf(m, v.x), fmaxf(v.y, v.z)), v.w);
    }
    m = blk_max<256>(m, red);
    float z = 0.f;
#pragma unroll
    for (int i = 0; i < 16; i++) { e[i] = fexp(e[i] - m); z += e[i]; }
    z = blk_sum<256>(z, red);
    float inv = 1.f / z;
    float rs = 0.f;
#pragma unroll
    for (int i = 0; i < 4; i++) {
        float4 v;
        v.x = fexp(e[i*4+0] * inv);
        v.y = fexp(e[i*4+1] * inv);
        v.z = fexp(e[i*4+2] * inv);
        v.w = fexp(e[i*4+3] * inv);
        *(float4*)(s + t * 4 + i * 1024) = v;
        rs += v.x + v.y + v.z + v.w;
    }
    rs = blk_sum<256>(rs, red);
    if (t == 0) g_asum[r] = rs;
}

// ---------------- fused reduce(attr@lmf) + prop0 (+router1 block) ----------------
__global__ void k_fuse1(const float* __restrict__ part, const float* __restrict__ tg_X,
                        const float* __restrict__ w1_w, const float* __restrict__ w1_b) {
    if (blockIdx.x == 2064) {
        int t = threadIdx.x;
        int warp = t >> 5, lane = t & 31;
        for (int j = warp; j < PD2; j += 8) {
            float s = 0.f;
            for (int k = lane; k < PD2; k += 32) s += g_routerp[k] * w1_w[j * PD2 + k];
#pragma unroll
            for (int off = 16; off > 0; off >>= 1) s += __shfl_xor_sync(0xffffffff, s, off);
            if (lane == 0) g_router1[j] = s + w1_b[j];
        }
        return;
    }
    int i = blockIdx.x * blockDim.x + threadIdx.x;
    if (i < N2 * PD2) {
        int r = i / PD2, c = i - r * PD2;
        float s = 0.f;
#pragma unroll
        for (int z = 0; z < 3; z++) s += part[(size_t)z * N2 * PD2 + i];
        float num = s + (c < PD ? tg_X[r * PD + c] : 0.f) + g_rou0[r] * g_router0[c];
        g_P[i] = num / (1.f + g_asum[r] + g_rou0[r] + EPSF);
    }
}

// ---------------- 64-tile wrappers ----------------
__global__ void __launch_bounds__(128)
k_f1(const float* __restrict__ w1_w, const float* __restrict__ w1_b, float* __restrict__ out) {
    extern __shared__ float smem_dyn[];
    int bx = blockIdx.x % 5, by = blockIdx.x / 5;
    gemm64_body<false>(g_P, PD2, w1_w, PD2, w1_b, out + N2 * 2 + PD, FD, PD2, PD2, 1.f,
                       g_rou1, g_router1, g_P, nullptr, nullptr, bx, by, smem_dyn);
}

// batched: f2 (blocks 0-159) + q2b = f1 @ pq_w[:,256:514]^T (blocks 160-223)
__global__ void __launch_bounds__(128)
k_mid(const float* __restrict__ w2_w, const float* __restrict__ w2_b,
      const float* __restrict__ pq_w, float* __restrict__ out) {
    extern __shared__ float smem_dyn[];
    if (blockIdx.x < 160) {
        int bx = blockIdx.x % 5, by = blockIdx.x / 5;
        gemm64_body<false>(g_P, PD2, w2_w, PD2, w2_b, out + N2 * 2 + PD + PD2, FD, PD2, PD2, 1.f,
                           nullptr, nullptr, nullptr, nullptr, nullptr, bx, by, smem_dyn);
    } else {
        int b = blockIdx.x - 160;
        gemm64_body<false>(out + N2 * 2 + PD, FD, pq_w + PD, FD, nullptr, g_q2b, DZ, DZ, PD2, 1.f,
                           nullptr, nullptr, nullptr, nullptr, nullptr, b & 1, b >> 1, smem_dyn);
    }
}

// q2 = q2a + q2b + f2 @ pq_w[:,514:772]^T
__global__ void __launch_bounds__(128)
k_q2fin(const float* __restrict__ pq_w, const float* __restrict__ out) {
    extern __shared__ float smem_dyn[];
    gemm64_body<false>(out + N2 * 2 + PD + PD2, FD, pq_w + PD + PD2, FD, nullptr, g_q2, DZ, DZ, PD2, 1.f,
                       nullptr, nullptr, nullptr, g_q2a, g_q2b, blockIdx.x & 1, blockIdx.x >> 1, smem_dyn);
}

// ---------------- host launch ----------------
static float* sym_addr(const void* s) {
    void* p = nullptr;
    cudaGetSymbolAddress(&p, s);
    return (float*)p;
}

#define SMEM_TT ((STAGES * BM * AST + STAGES * BN * AST) * 4)
#define SMEM_FF ((STAGES * BM * AST + STAGES * BKT * BSTN) * 4)
#define SMEM_64 ((STAGES * BM6 * AST * 2) * 4)

extern "C" void kernel_launch(void* const* d_in, const int* in_sizes, int n_in,
                              void* d_out, int out_size) {
    const float* lm_X    = (const float*)d_in[0];
    const float* lm_Y    = (const float*)d_in[1];
    const float* tg_X    = (const float*)d_in[2];
    const float* lm_delay= (const float*)d_in[4];
    const float* tg_delay= (const float*)d_in[5];
    const float* aq_w    = (const float*)d_in[6];
    const float* aq_b    = (const float*)d_in[7];
    const float* ak_w    = (const float*)d_in[8];
    const float* ak_b    = (const float*)d_in[9];
    const float* w1_w    = (const float*)d_in[10];
    const float* w1_b    = (const float*)d_in[11];
    const float* w2_w    = (const float*)d_in[12];
    const float* w2_b    = (const float*)d_in[13];
    const float* pq_w    = (const float*)d_in[14];
    const float* pq_b    = (const float*)d_in[15];
    const float* pk_w    = (const float*)d_in[16];
    const float* pk_b    = (const float*)d_in[17];
    const float* pv_w    = (const float*)d_in[18];
    const float* pv_b    = (const float*)d_in[19];
    const float* gamma1  = (const float*)d_in[20];
    const float* gamma2  = (const float*)d_in[21];
    const float* gamma3  = (const float*)d_in[22];
    const float* alpha   = (const float*)d_in[23];
    const float* beta    = (const float*)d_in[24];
    float* out = (float*)d_out;

    float* pk12  = sym_addr(g_k12);
    float* pq    = sym_addr(g_q);
    float* pq2   = sym_addr(g_q2);
    float* pS    = sym_addr(g_S);
    float* plmf  = sym_addr(g_lmf);
    float* pPart = sym_addr(g_part);

    cudaFuncSetAttribute(mma_gemm<true, true>,  cudaFuncAttributeMaxDynamicSharedMemorySize, SMEM_TT);
    cudaFuncSetAttribute(mma_gemm<false, true>, cudaFuncAttributeMaxDynamicSharedMemorySize, SMEM_FF);
    cudaFuncSetAttribute(k_score2, cudaFuncAttributeMaxDynamicSharedMemorySize, SMEM_TT);
    cudaFuncSetAttribute(k_front,  cudaFuncAttributeMaxDynamicSharedMemorySize, SMEM_64);
    cudaFuncSetAttribute(k_f1,     cudaFuncAttributeMaxDynamicSharedMemorySize, SMEM_64);
    cudaFuncSetAttribute(k_mid,    cudaFuncAttributeMaxDynamicSharedMemorySize, SMEM_64);
    cudaFuncSetAttribute(k_q2fin,  cudaFuncAttributeMaxDynamicSharedMemorySize, SMEM_64);

    dim3 blk(256), blk64(128);

    // 1. front mega-kernel: projections (k1,k2,q,q2a) + all prep
    k_front<<<BF_TOT, blk64, SMEM_64>>>(lm_X, lm_Y, tg_X, ak_w, ak_b, pk_w, pk_b,
                                        aq_w, aq_b, pq_w, pq_b, lm_delay, tg_delay,
                                        gamma1, gamma2, gamma3, alpha, beta,
                                        pv_w, pv_b, out);

    // 2. scores1 = q @ k1^T
    mma_gemm<true, true><<<dim3(32, 16, 1), blk, SMEM_TT>>>(pq, DZ, pk12, 2 * DZ, pS, N1, N2, N1, DZ, INV_TEMP);

    // 3. softmax -> attr (+ router partial combine)
    k_attr<<<N2 + 1, blk>>>();

    // 4. attr @ lm_feature, split-3
    mma_gemm<false, true><<<dim3(3, 16, 3), blk, SMEM_FF>>>(pS, N1, plmf, PD2, pPart, PD2, N2, PD2, N1, 1.f);

    // 5. fused reduce + prop0 (+ router1 block)
    k_fuse1<<<2065, blk>>>(pPart, tg_X, w1_w, w1_b);

    // 6. f1 -> out, fused prop1
    k_f1<<<160, blk64, SMEM_64>>>(w1_w, w1_b, out);

    // 7. batched f2 + q2b
    k_mid<<<224, blk64, SMEM_64>>>(w2_w, w2_b, pq_w, out);

    // 8. q2 = q2a + q2b + q2c
    k_q2fin<<<64, blk64, SMEM_64>>>(pq_w, out);

    // 9-10. attention 2 fused
    k_score2<<<dim3(32, 16, 1), blk, SMEM_TT>>>(pq2, DZ, pk12 + DZ, 2 * DZ, pPart, DZ);
    k_comb2<<<8, blk>>>(pPart, out);
}

// round 10
// speedup vs baseline: 1.4720x; 1.0939x over previous
#include <cuda_runtime.h>
#include <math.h>

// ---------------- problem constants ----------------
#define N1 4096
#define N2 2048
#define PD 256
#define DZ 128
#define PD2 258
#define FD 772
#define EPSF 1e-12f
#define INV_TEMP 0.08838834764831843f   // 1/sqrt(128)

// ---------------- device scratch ----------------
__device__ float g_k12[N1 * 2 * DZ];   // [k1 | k2], row stride 256
__device__ float g_q[N2 * DZ];
__device__ float g_q2[N2 * DZ];
__device__ float g_q2a[N2 * DZ];
__device__ float g_q2b[N2 * DZ];
__device__ float g_S[(size_t)N2 * N1];
__device__ float g_lmfT[PD2 * N1];     // lm_feature^T [258, 4096]
__device__ float g_P[N2 * PD2];
__device__ float g_part[4 * 2048 * 258];   // split-K partials / attn2 partials alias
__device__ float g_ry[N2 * 2];             // attr @ lm_Y (cols 256,257 of prop0 numerator)
__device__ float g_rp_sx[16 * PD2];
__device__ float g_rp_sdx[16 * PD2];
__device__ float g_rp_sd[16];
__device__ float g_router0[PD2];
__device__ float g_routerp[PD2];
__device__ float g_router1[PD2];
__device__ float g_rou0[N2];
__device__ float g_rou1[N2];
__device__ float g_asum[N2];
__device__ float g_v2[N1 * 2];

// ---------------- helpers ----------------
__device__ __forceinline__ float fexp(float x) {
    float y;
    asm("ex2.approx.f32 %0, %1;" : "=f"(y) : "f"(x * 1.4426950408889634f));
    return y;
}
__device__ __forceinline__ unsigned f2tf32(float x) {
    unsigned r;
    asm("cvt.rna.tf32.f32 %0, %1;" : "=r"(r) : "f"(x));
    return r;
}
__device__ __forceinline__ void cp16(float* dst, const float* src, bool valid) {
    unsigned d = (unsigned)__cvta_generic_to_shared(dst);
    int sz = valid ? 16 : 0;
    asm volatile("cp.async.cg.shared.global [%0], [%1], 16, %2;" :: "r"(d), "l"(src), "r"(sz));
}
__device__ __forceinline__ void cp4(float* dst, const float* src, bool valid) {
    unsigned d = (unsigned)__cvta_generic_to_shared(dst);
    int sz = valid ? 4 : 0;
    asm volatile("cp.async.ca.shared.global [%0], [%1], 4, %2;" :: "r"(d), "l"(src), "r"(sz));
}
__device__ __forceinline__ void cp_commit() { asm volatile("cp.async.commit_group;"); }
template<int N_>
__device__ __forceinline__ void cp_wait() {
    asm volatile("cp.async.wait_group %0;" :: "n"(N_));
}

template<int TB>
__device__ __forceinline__ float blk_sum(float v, float* red) {
    int t = threadIdx.x;
    red[t] = v; __syncthreads();
    for (int s = TB >> 1; s > 0; s >>= 1) {
        if (t < s) red[t] += red[t + s];
        __syncthreads();
    }
    float r = red[0]; __syncthreads();
    return r;
}
template<int TB>
__device__ __forceinline__ float blk_max(float v, float* red) {
    int t = threadIdx.x;
    red[t] = v; __syncthreads();
    for (int s = TB >> 1; s > 0; s >>= 1) {
        if (t < s) red[t] = fmaxf(red[t], red[t + s]);
        __syncthreads();
    }
    float r = red[0]; __syncthreads();
    return r;
}

// ---------------- GEMM tile configs ----------------
#define BM 128
#define BN 128
#define BKT 16
#define AST 20
#define STAGES 4
#define BM6 64
#define BN6 64

// ---------------- 64x64 tf32 GEMM body ----------------
template<bool AVEC16>
__device__ __forceinline__ void gemm64_body(
    const float* __restrict__ A, int lda,
    const float* __restrict__ B, int ldb,
    const float* __restrict__ bias, float* __restrict__ C, int ldc,
    int N, int K, float scale,
    const float* __restrict__ rou1, const float* __restrict__ rt1,
    float* __restrict__ P,
    const float* __restrict__ add1, const float* __restrict__ add2,
    int bx, int by, float* smem)
{
    float* AsB = smem;
    float* BsB = smem + STAGES * BM6 * AST;

    const int tid = threadIdx.x;
    const int warp = tid >> 5, lane = tid & 31;
    const int g = lane >> 2, tig = lane & 3;
    const int wm = (warp & 1) * 32;
    const int wn = (warp >> 1) * 32;
    const int m0 = by * BM6, n0 = bx * BN6;

    const int KT = (K + BKT - 1) / BKT;

    float acc[2][4][4];
#pragma unroll
    for (int i = 0; i < 2; i++)
#pragma unroll
        for (int j = 0; j < 4; j++)
#pragma unroll
            for (int c = 0; c < 4; c++) acc[i][j][c] = 0.f;

    auto loadStage = [&](int kt, int st) {
        int k0 = kt * BKT;
        float* as = AsB + st * BM6 * AST;
        float* bs = BsB + st * BN6 * AST;
        if (AVEC16) {
#pragma unroll
            for (int p = 0; p < 2; p++) {
                int c = tid + 128 * p;
                int row = c >> 2, kq = (c & 3) * 4;
                cp16(as + row * AST + kq, A + (size_t)(m0 + row) * lda + k0 + kq, (k0 + kq) < K);
            }
#pragma unroll
            for (int p = 0; p < 2; p++) {
                int c = tid + 128 * p;
                int row = c >> 2, kq = (c & 3) * 4;
                bool v = (n0 + row) < N && (k0 + kq) < K;
                cp16(bs + row * AST + kq, B + (size_t)(n0 + row) * ldb + k0 + kq, v);
            }
        } else {
#pragma unroll
            for (int p = 0; p < 8; p++) {
                int e = tid + 128 * p;
                int row = e >> 4, kk = e & 15;
                cp4(as + row * AST + kk, A + (size_t)(m0 + row) * lda + k0 + kk, (k0 + kk) < K);
            }
#pragma unroll
            for (int p = 0; p < 8; p++) {
                int e = tid + 128 * p;
                int row = e >> 4, kk = e & 15;
                bool v = (n0 + row) < N && (k0 + kk) < K;
                cp4(bs + row * AST + kk, B + (size_t)(n0 + row) * ldb + k0 + kk, v);
            }
        }
        cp_commit();
    };

#pragma unroll
    for (int s = 0; s < STAGES - 1; s++) {
        if (s < KT) loadStage(s, s);
        else cp_commit();
    }

    for (int i = 0; i < KT; i++) {
        cp_wait<STAGES - 2>();
        __syncthreads();
        int j = i + STAGES - 1;
        if (j < KT) loadStage(j, j & (STAGES - 1));
        else cp_commit();
        const int st = i & (STAGES - 1);
        const float* as = AsB + st * BM6 * AST;
        const float* bs = BsB + st * BN6 * AST;

#pragma unroll
        for (int ks = 0; ks < 2; ks++) {
            unsigned af[2][4], bf[4][2];
#pragma unroll
            for (int mi = 0; mi < 2; mi++) {
                const float* pa = as + (wm + mi * 16 + g) * AST + ks * 8 + tig;
                af[mi][0] = f2tf32(pa[0]);
                af[mi][1] = f2tf32(pa[8 * AST]);
                af[mi][2] = f2tf32(pa[4]);
                af[mi][3] = f2tf32(pa[8 * AST + 4]);
            }
#pragma unroll
            for (int ni = 0; ni < 4; ni++) {
                const float* pb = bs + (wn + ni * 8 + g) * AST + ks * 8 + tig;
                bf[ni][0] = f2tf32(pb[0]);
                bf[ni][1] = f2tf32(pb[4]);
            }
#pragma unroll
            for (int mi = 0; mi < 2; mi++)
#pragma unroll
                for (int ni = 0; ni < 4; ni++) {
                    asm volatile(
                        "mma.sync.aligned.m16n8k8.row.col.f32.tf32.tf32.f32 "
                        "{%0,%1,%2,%3}, {%4,%5,%6,%7}, {%8,%9}, {%0,%1,%2,%3};"
                        : "+f"(acc[mi][ni][0]), "+f"(acc[mi][ni][1]),
                          "+f"(acc[mi][ni][2]), "+f"(acc[mi][ni][3])
                        : "r"(af[mi][0]), "r"(af[mi][1]), "r"(af[mi][2]), "r"(af[mi][3]),
                          "r"(bf[ni][0]), "r"(bf[ni][1]));
                }
        }
    }

#pragma unroll
    for (int mi = 0; mi < 2; mi++) {
        int mrow0 = m0 + wm + mi * 16 + g;
#pragma unroll
        for (int ni = 0; ni < 4; ni++) {
            int ncol = n0 + wn + ni * 8 + 2 * tig;
#pragma unroll
            for (int h = 0; h < 2; h++) {
                int mr = mrow0 + h * 8;
                if (ncol < N) {
                    float2 bv = bias ? *(const float2*)(bias + ncol) : make_float2(0.f, 0.f);
                    float v0 = acc[mi][ni][h * 2 + 0] * scale + bv.x;
                    float v1 = acc[mi][ni][h * 2 + 1] * scale + bv.y;
                    if (add1) {
                        float2 a1 = *(const float2*)(add1 + (size_t)mr * ldc + ncol);
                        v0 += a1.x; v1 += a1.y;
                    }
                    if (add2) {
                        float2 a2 = *(const float2*)(add2 + (size_t)mr * ldc + ncol);
                        v0 += a2.x; v1 += a2.y;
                    }
                    *(float2*)(C + (size_t)mr * ldc + ncol) = make_float2(v0, v1);
                    if (P) {
                        float rr = rou1[mr];
                        float inv = 1.f / (1.f + rr + EPSF);
                        *(float2*)(P + (size_t)mr * PD2 + ncol) =
                            make_float2((v0 + rr * rt1[ncol]) * inv,
                                        (v1 + rr * rt1[ncol + 1]) * inv);
                    }
                }
            }
        }
    }
}

// ---------------- front mega-kernel ----------------
#define BF_GEMM 384     // 128 ak + 128 pk + 64 q + 64 q2a
#define BF_TRX  256     // lm_X transpose 64x64 tiles
#define BF_TRY  64      // lm_Y -> lmfT rows 256,257
#define BF_TGX  1024    // tg_X -> out (float4)
#define BF_V2   32
#define BF_RPA  16
#define BF_ROU  16
#define BF_TOT (BF_GEMM + BF_TRX + BF_TRY + BF_TGX + BF_V2 + BF_RPA + BF_ROU)

__global__ void __launch_bounds__(128)
k_front(const float* __restrict__ lm_X, const float* __restrict__ lm_Y,
        const float* __restrict__ tg_X,
        const float* __restrict__ ak_w, const float* __restrict__ ak_b,
        const float* __restrict__ pk_w, const float* __restrict__ pk_b,
        const float* __restrict__ aq_w, const float* __restrict__ aq_b,
        const float* __restrict__ pq_w, const float* __restrict__ pq_b,
        const float* __restrict__ lm_delay, const float* __restrict__ tg_delay,
        const float* g1p, const float* g2p, const float* g3p,
        const float* ap, const float* bp,
        const float* __restrict__ pv_w, const float* __restrict__ pv_b,
        float* __restrict__ out)
{
    extern __shared__ float smem_dyn[];
    int bid = blockIdx.x, t = threadIdx.x;

    if (bid < 128) {            // k1
        gemm64_body<true>(lm_X, PD, ak_w, PD, ak_b, g_k12, 2 * DZ, DZ, PD, 1.f,
                          nullptr, nullptr, nullptr, nullptr, nullptr,
                          bid & 1, bid >> 1, smem_dyn);
        return;
    }
    bid -= 128;
    if (bid < 128) {            // k2
        gemm64_body<true>(lm_X, PD, pk_w, PD, pk_b, g_k12 + DZ, 2 * DZ, DZ, PD, 1.f,
                          nullptr, nullptr, nullptr, nullptr, nullptr,
                          bid & 1, bid >> 1, smem_dyn);
        return;
    }
    bid -= 128;
    if (bid < 64) {             // q
        gemm64_body<true>(tg_X, PD, aq_w, PD, aq_b, g_q, DZ, DZ, PD, 1.f,
                          nullptr, nullptr, nullptr, nullptr, nullptr,
                          bid & 1, bid >> 1, smem_dyn);
        return;
    }
    bid -= 64;
    if (bid < 64) {             // q2a
        gemm64_body<true>(tg_X, PD, pq_w, FD, pq_b, g_q2a, DZ, DZ, PD, 1.f,
                          nullptr, nullptr, nullptr, nullptr, nullptr,
                          bid & 1, bid >> 1, smem_dyn);
        return;
    }
    bid -= 64;
    if (bid < BF_TRX) {         // lm_X -> lmfT transpose (64x64 tiles via smem)
        float* sm = smem_dyn;   // [64][65]
        int tr = bid >> 2, tc = bid & 3;
        int r0 = tr * 64, c0 = tc * 64;
#pragma unroll
        for (int p = 0; p < 32; p++) {
            int e = t + 128 * p;
            int i = e >> 6, j = e & 63;
            sm[i * 65 + j] = lm_X[(size_t)(r0 + i) * PD + c0 + j];
        }
        __syncthreads();
#pragma unroll
        for (int p = 0; p < 32; p++) {
            int e = t + 128 * p;
            int i = e >> 6, j = e & 63;
            g_lmfT[(size_t)(c0 + i) * N1 + r0 + j] = sm[j * 65 + i];
        }
        return;
    }
    bid -= BF_TRX;
    if (bid < BF_TRY) {         // lm_Y -> lmfT rows 256,257
        int e = bid * 128 + t;
        int h = e >> 12, k = e & 4095;
        g_lmfT[(size_t)(PD + h) * N1 + k] = lm_Y[k * 2 + h];
        return;
    }
    bid -= BF_TRY;
    if (bid < BF_TGX) {         // tg_X -> out feature block (float4)
        int j4 = (bid * 128 + t) * 4;
        int r = j4 >> 8, c = j4 & 255;
        *(float4*)(out + N2 * 2 + r * FD + c) = *(const float4*)(tg_X + j4);
        return;
    }
    bid -= BF_TGX;
    if (bid < BF_V2) {          // v2 projection
        int i = bid * 128 + t;
        float y0 = lm_Y[2 * i], y1 = lm_Y[2 * i + 1];
        g_v2[2 * i]     = pv_w[0] * y0 + pv_w[1] * y1 + pv_b[0];
        g_v2[2 * i + 1] = pv_w[2] * y0 + pv_w[3] * y1 + pv_b[1];
        return;
    }
    bid -= BF_V2;
    if (bid < BF_RPA) {         // row-blocked col sums (router partials)
        int r0 = bid * 256;
        int lane = t & 31;
        float a = ap[0], b = bp[0], g1 = g1p[0];
        float ax0 = 0.f, ad0 = 0.f, ax1 = 0.f, ad1 = 0.f, ay = 0.f, ady = 0.f, sd = 0.f;
        for (int ch = 0; ch < 256; ch += 32) {
            float dl = fexp(-g1 * (a * lm_delay[r0 + ch + lane] + b));
#pragma unroll
            for (int k2 = 0; k2 < 32; k2++) {
                float d = __shfl_sync(0xffffffff, dl, k2);
                int rr = r0 + ch + k2;
                float x0 = lm_X[rr * PD + t];
                float x1 = lm_X[rr * PD + t + 128];
                ax0 += x0; ad0 += d * x0;
                ax1 += x1; ad1 += d * x1;
                if (t < 2) {
                    float y = lm_Y[rr * 2 + t];
                    ay += y; ady += d * y;
                }
                sd += d;
            }
        }
        g_rp_sx[bid * PD2 + t]        = ax0;
        g_rp_sdx[bid * PD2 + t]       = ad0;
        g_rp_sx[bid * PD2 + t + 128]  = ax1;
        g_rp_sdx[bid * PD2 + t + 128] = ad1;
        if (t < 2) {
            g_rp_sx[bid * PD2 + 256 + t]  = ay;
            g_rp_sdx[bid * PD2 + 256 + t] = ady;
        }
        if (t == 0) g_rp_sd[bid] = sd;
        return;
    }
    bid -= BF_RPA;
    {                           // rou0 / rou1
        int i = bid * 128 + t;
        float a = ap[0], b = bp[0], g2 = g2p[0], g3 = g3p[0];
        float x = a * tg_delay[i] + b;
        g_rou0[i] = fexp(-g2 * x);
        g_rou1[i] = fexp(-g3 * x);
    }
}

// ---------------- 128x128 machinery (BTRANS only) ----------------
__device__ __forceinline__ void load_stage128T(
    const float* __restrict__ A, int lda, const float* __restrict__ B, int ldb,
    float* AsB, float* BsB, int m0, int n0, int N, int K, int kt, int st, int tid)
{
    int k0 = kt * BKT;
    float* as = AsB + st * BM * AST;
#pragma unroll
    for (int p = 0; p < 2; p++) {
        int c = tid + 256 * p;
        int row = c >> 2, kq = (c & 3) * 4;
        cp16(as + row * AST + kq, A + (size_t)(m0 + row) * lda + k0 + kq, (k0 + kq) < K);
    }
    float* bs = BsB + st * BN * AST;
#pragma unroll
    for (int p = 0; p < 2; p++) {
        int c = tid + 256 * p;
        int row = c >> 2, kq = (c & 3) * 4;
        bool v = (n0 + row) < N && (k0 + kq) < K;
        cp16(bs + row * AST + kq, B + (size_t)(n0 + row) * ldb + k0 + kq, v);
    }
    cp_commit();
}

__device__ __forceinline__ void mma_ktileT(
    const float* as, const float* bsT,
    int wm, int wn, int g, int tig, float acc[4][4][4])
{
#pragma unroll
    for (int ks = 0; ks < 2; ks++) {
        unsigned af[4][4], bf[4][2];
#pragma unroll
        for (int mi = 0; mi < 4; mi++) {
            const float* pa = as + (wm + mi * 16 + g) * AST + ks * 8 + tig;
            af[mi][0] = f2tf32(pa[0]);
            af[mi][1] = f2tf32(pa[8 * AST]);
            af[mi][2] = f2tf32(pa[4]);
            af[mi][3] = f2tf32(pa[8 * AST + 4]);
        }
#pragma unroll
        for (int ni = 0; ni < 4; ni++) {
            const float* pb = bsT + (wn + ni * 8 + g) * AST + ks * 8 + tig;
            bf[ni][0] = f2tf32(pb[0]);
            bf[ni][1] = f2tf32(pb[4]);
        }
#pragma unroll
        for (int mi = 0; mi < 4; mi++)
#pragma unroll
            for (int ni = 0; ni < 4; ni++) {
                asm volatile(
                    "mma.sync.aligned.m16n8k8.row.col.f32.tf32.tf32.f32 "
                    "{%0,%1,%2,%3}, {%4,%5,%6,%7}, {%8,%9}, {%0,%1,%2,%3};"
                    : "+f"(acc[mi][ni][0]), "+f"(acc[mi][ni][1]),
                      "+f"(acc[mi][ni][2]), "+f"(acc[mi][ni][3])
                    : "r"(af[mi][0]), "r"(af[mi][1]), "r"(af[mi][2]), "r"(af[mi][3]),
                      "r"(bf[ni][0]), "r"(bf[ni][1]));
            }
    }
}

__global__ void __launch_bounds__(256)
mma_gemm(const float* __restrict__ A, int lda,
         const float* __restrict__ B, int ldb,
         float* __restrict__ C, int ldc,
         int M, int N, int K, float scale)
{
    extern __shared__ float smem_dyn[];
    float* AsB = smem_dyn;
    float* BsB = smem_dyn + STAGES * BM * AST;

    const int tid = threadIdx.x;
    const int warp = tid >> 5, lane = tid & 31;
    const int g = lane >> 2, tig = lane & 3;
    const int wm = (warp & 1) * 64;
    const int wn = (warp >> 1) * 32;
    const int m0 = blockIdx.y * BM, n0 = blockIdx.x * BN;

    const int KT = (K + BKT - 1) / BKT;
    const int SPLIT = gridDim.z;
    const int KTs = (KT + SPLIT - 1) / SPLIT;
    const int kt0 = blockIdx.z * KTs;
    const int kt1 = min(KT, kt0 + KTs);
    const int nk = kt1 - kt0;

    float acc[4][4][4];
#pragma unroll
    for (int i = 0; i < 4; i++)
#pragma unroll
        for (int j = 0; j < 4; j++)
#pragma unroll
            for (int c = 0; c < 4; c++) acc[i][j][c] = 0.f;

#pragma unroll
    for (int s = 0; s < STAGES - 1; s++) {
        if (s < nk) load_stage128T(A, lda, B, ldb, AsB, BsB, m0, n0, N, K, kt0 + s, s, tid);
        else cp_commit();
    }

    for (int i = 0; i < nk; i++) {
        cp_wait<STAGES - 2>();
        __syncthreads();
        int j = i + STAGES - 1;
        if (j < nk) load_stage128T(A, lda, B, ldb, AsB, BsB, m0, n0, N, K, kt0 + j, j & (STAGES - 1), tid);
        else cp_commit();
        const int st = i & (STAGES - 1);
        mma_ktileT(AsB + st * BM * AST, BsB + st * BN * AST, wm, wn, g, tig, acc);
    }

    float* outp = (gridDim.z > 1) ? (C + (size_t)blockIdx.z * M * N) : C;
#pragma unroll
    for (int mi = 0; mi < 4; mi++) {
        int mrow0 = m0 + wm + mi * 16 + g;
#pragma unroll
        for (int ni = 0; ni < 4; ni++) {
            int ncol = n0 + wn + ni * 8 + 2 * tig;
#pragma unroll
            for (int h = 0; h < 2; h++) {
                int mr = mrow0 + h * 8;
                if (ncol < N) {
                    *(float2*)(outp + (size_t)mr * ldc + ncol) =
                        make_float2(acc[mi][ni][h*2+0] * scale, acc[mi][ni][h*2+1] * scale);
                }
            }
        }
    }
}

// ---------------- scores2 GEMM + split softmax*v epilogue ----------------
__global__ void __launch_bounds__(256)
k_score2(const float* __restrict__ A, int lda,
         const float* __restrict__ B, int ldb,
         float* __restrict__ part, int K)
{
    extern __shared__ float smem_dyn[];
    float* AsB = smem_dyn;
    float* BsB = smem_dyn + STAGES * BM * AST;

    const int tid = threadIdx.x;
    const int warp = tid >> 5, lane = tid & 31;
    const int g = lane >> 2, tig = lane & 3;
    const int wm = (warp & 1) * 64;
    const int wn = (warp >> 1) * 32;
    const int m0 = blockIdx.y * BM, n0 = blockIdx.x * BN;
    const int KT = K / BKT;

    float acc[4][4][4];
#pragma unroll
    for (int i = 0; i < 4; i++)
#pragma unroll
        for (int j = 0; j < 4; j++)
#pragma unroll
            for (int c = 0; c < 4; c++) acc[i][j][c] = 0.f;

#pragma unroll
    for (int s = 0; s < STAGES - 1; s++) {
        if (s < KT) load_stage128T(A, lda, B, ldb, AsB, BsB, m0, n0, N1, K, s, s, tid);
        else cp_commit();
    }
    for (int i = 0; i < KT; i++) {
        cp_wait<STAGES - 2>();
        __syncthreads();
        int j = i + STAGES - 1;
        if (j < KT) load_stage128T(A, lda, B, ldb, AsB, BsB, m0, n0, N1, K, j, j & (STAGES - 1), tid);
        else cp_commit();
        const int st = i & (STAGES - 1);
        mma_ktileT(AsB + st * BM * AST, BsB + st * BN * AST, wm, wn, g, tig, acc);
    }

    float v2x[4][2], v2y[4][2];
#pragma unroll
    for (int ni = 0; ni < 4; ni++) {
#pragma unroll
        for (int w = 0; w < 2; w++) {
            int gc = n0 + wn + ni * 8 + 2 * tig + w;
            v2x[ni][w] = g_v2[2 * gc];
            v2y[ni][w] = g_v2[2 * gc + 1];
        }
    }

    __syncthreads();
    float* sred = smem_dyn;
    const int w2 = warp >> 1;
#pragma unroll
    for (int mi = 0; mi < 4; mi++) {
#pragma unroll
        for (int h = 0; h < 2; h++) {
            int rloc = wm + mi * 16 + g + 8 * h;
            float m = -1e30f;
#pragma unroll
            for (int ni = 0; ni < 4; ni++)
#pragma unroll
                for (int w = 0; w < 2; w++)
                    m = fmaxf(m, acc[mi][ni][h * 2 + w] * INV_TEMP);
            float sw = 0.f, s0 = 0.f, s1 = 0.f;
#pragma unroll
            for (int ni = 0; ni < 4; ni++)
#pragma unroll
                for (int w = 0; w < 2; w++) {
                    float e = fexp(acc[mi][ni][h * 2 + w] * INV_TEMP - m);
                    sw += e;
                    s0 += e * v2x[ni][w];
                    s1 += e * v2y[ni][w];
                }
#pragma unroll
            for (int off = 1; off < 4; off <<= 1) {
                float om  = __shfl_xor_sync(0xffffffff, m,  off);
                float osw = __shfl_xor_sync(0xffffffff, sw, off);
                float os0 = __shfl_xor_sync(0xffffffff, s0, off);
                float os1 = __shfl_xor_sync(0xffffffff, s1, off);
                float nm = fmaxf(m, om);
                float ea = fexp(m - nm), eb = fexp(om - nm);
                sw = sw * ea + osw * eb;
                s0 = s0 * ea + os0 * eb;
                s1 = s1 * ea + os1 * eb;
                m = nm;
            }
            if (tig == 0) {
                float* p = sred + ((w2 * BM) + rloc) * 4;
                p[0] = m; p[1] = sw; p[2] = s0; p[3] = s1;
            }
        }
    }
    __syncthreads();

    if (tid < BM) {
        float m = -1e30f, sw = 0.f, s0 = 0.f, s1 = 0.f;
#pragma unroll
        for (int w = 0; w < 4; w++) {
            const float* p = sred + ((w * BM) + tid) * 4;
            float om = p[0], osw = p[1], os0 = p[2], os1 = p[3];
            float nm = fmaxf(m, om);
            float ea = fexp(m - nm), eb = fexp(om - nm);
            sw = sw * ea + osw * eb;
            s0 = s0 * ea + os0 * eb;
            s1 = s1 * ea + os1 * eb;
            m = nm;
        }
        float* p = part + ((size_t)blockIdx.x * N2 + (m0 + tid)) * 4;
        p[0] = m; p[1] = sw; p[2] = s0; p[3] = s1;
    }
}

__global__ void k_comb2(const float* __restrict__ part, float* __restrict__ out) {
    int r = blockIdx.x * blockDim.x + threadIdx.x;
    if (r < N2) {
        float m = -1e30f, sw = 0.f, s0 = 0.f, s1 = 0.f;
        for (int cb = 0; cb < 32; cb++) {
            const float* p = part + ((size_t)cb * N2 + r) * 4;
            float om = p[0], osw = p[1], os0 = p[2], os1 = p[3];
            float nm = fmaxf(m, om);
            float ea = fexp(m - nm), eb = fexp(om - nm);
            sw = sw * ea + osw * eb;
            s0 = s0 * ea + os0 * eb;
            s1 = s1 * ea + os1 * eb;
            m = nm;
        }
        out[2 * r]     = s0 / sw;
        out[2 * r + 1] = s1 / sw;
    }
}

// ---------------- attention 1 softmax + fused attr@lm_Y (+router combine) -----
__global__ void k_attr(const float* __restrict__ lm_Y) {
    __shared__ float red[256];
    int t = threadIdx.x;
    if (blockIdx.x == N2) {
        float sd = 0.f;
#pragma unroll
        for (int rb = 0; rb < 16; rb++) sd += g_rp_sd[rb];
        for (int c = t; c < PD2; c += 256) {
            float sx = 0.f, sdx = 0.f;
#pragma unroll
            for (int rb = 0; rb < 16; rb++) {
                sx  += g_rp_sx[rb * PD2 + c];
                sdx += g_rp_sdx[rb * PD2 + c];
            }
            float r0v = sx * (1.0f / N1);
            g_router0[c] = r0v;
            g_routerp[c] = (sdx + r0v) / (1.f + sd + EPSF);
        }
        return;
    }
    int r = blockIdx.x;
    float* s = g_S + (size_t)r * N1;
    float e[16];
    float m = -1e30f;
#pragma unroll
    for (int i = 0; i < 4; i++) {
        float4 v = *(const float4*)(s + t * 4 + i * 1024);
        e[i*4+0] = v.x; e[i*4+1] = v.y; e[i*4+2] = v.z; e[i*4+3] = v.w;
        m = fmaxf(fmaxf(fmaxf(m, v.x), fmaxf(v.y, v.z)), v.w);
    }
    m = blk_max<256>(m, red);
    float z = 0.f;
#pragma unroll
    for (int i = 0; i < 16; i++) { e[i] = fexp(e[i] - m); z += e[i]; }
    z = blk_sum<256>(z, red);
    float inv = 1.f / z;
    float rs = 0.f, ry0 = 0.f, ry1 = 0.f;
#pragma unroll
    for (int i = 0; i < 4; i++) {
        int base = t * 4 + i * 1024;
        float4 v;
        v.x = fexp(e[i*4+0] * inv);
        v.y = fexp(e[i*4+1] * inv);
        v.z = fexp(e[i*4+2] * inv);
        v.w = fexp(e[i*4+3] * inv);
        *(float4*)(s + base) = v;
        rs += v.x + v.y + v.z + v.w;
        float4 y01 = *(const float4*)(lm_Y + base * 2);       // y0[k],y1[k],y0[k+1],y1[k+1]
        float4 y23 = *(const float4*)(lm_Y + base * 2 + 4);
        ry0 += v.x * y01.x + v.y * y01.z + v.z * y23.x + v.w * y23.z;
        ry1 += v.x * y01.y + v.y * y01.w + v.z * y23.y + v.w * y23.w;
    }
    rs  = blk_sum<256>(rs, red);
    ry0 = blk_sum<256>(ry0, red);
    ry1 = blk_sum<256>(ry1, red);
    if (t == 0) {
        g_asum[r] = rs;
        g_ry[2 * r]     = ry0;
        g_ry[2 * r + 1] = ry1;
    }
}

// ---------------- fused reduce(attr@lmfT) + prop0 (+router1 block) -------------
__global__ void k_fuse1(const float* __restrict__ part, const float* __restrict__ tg_X,
                        const float* __restrict__ w1_w, const float* __restrict__ w1_b) {
    if (blockIdx.x == 2064) {
        int t = threadIdx.x;
        int warp = t >> 5, lane = t & 31;
        for (int j = warp; j < PD2; j += 8) {
            float s = 0.f;
            for (int k = lane; k < PD2; k += 32) s += g_routerp[k] * w1_w[j * PD2 + k];
#pragma unroll
            for (int off = 16; off > 0; off >>= 1) s += __shfl_xor_sync(0xffffffff, s, off);
            if (lane == 0) g_router1[j] = s + w1_b[j];
        }
        return;
    }
    int i = blockIdx.x * blockDim.x + threadIdx.x;
    if (i < N2 * PD2) {
        int r = i / PD2, c = i - r * PD2;
        float s;
        if (c < PD) {
            s = 0.f;
#pragma unroll
            for (int z = 0; z < 4; z++) s += part[(size_t)z * N2 * PD + r * PD + c];
            s += tg_X[r * PD + c];
        } else {
            s = g_ry[2 * r + (c - PD)];
        }
        float num = s + g_rou0[r] * g_router0[c];
        g_P[i] = num / (1.f + g_asum[r] + g_rou0[r] + EPSF);
    }
}

// ---------------- 64-tile wrappers ----------------
__global__ void __launch_bounds__(128)
k_f1(const float* __restrict__ w1_w, const float* __restrict__ w1_b, float* __restrict__ out) {
    extern __shared__ float smem_dyn[];
    int bx = blockIdx.x % 5, by = blockIdx.x / 5;
    gemm64_body<false>(g_P, PD2, w1_w, PD2, w1_b, out + N2 * 2 + PD, FD, PD2, PD2, 1.f,
                       g_rou1, g_router1, g_P, nullptr, nullptr, bx, by, smem_dyn);
}

__global__ void __launch_bounds__(128)
k_mid(const float* __restrict__ w2_w, const float* __restrict__ w2_b,
      const float* __restrict__ pq_w, float* __restrict__ out) {
    extern __shared__ float smem_dyn[];
    if (blockIdx.x < 160) {
        int bx = blockIdx.x % 5, by = blockIdx.x / 5;
        gemm64_body<false>(g_P, PD2, w2_w, PD2, w2_b, out + N2 * 2 + PD + PD2, FD, PD2, PD2, 1.f,
                           nullptr, nullptr, nullptr, nullptr, nullptr, bx, by, smem_dyn);
    } else {
        int b = blockIdx.x - 160;
        gemm64_body<false>(out + N2 * 2 + PD, FD, pq_w + PD, FD, nullptr, g_q2b, DZ, DZ, PD2, 1.f,
                           nullptr, nullptr, nullptr, nullptr, nullptr, b & 1, b >> 1, smem_dyn);
    }
}

__global__ void __launch_bounds__(128)
k_q2fin(const float* __restrict__ pq_w, const float* __restrict__ out) {
    extern __shared__ float smem_dyn[];
    gemm64_body<false>(out + N2 * 2 + PD + PD2, FD, pq_w + PD + PD2, FD, nullptr, g_q2, DZ, DZ, PD2, 1.f,
                       nullptr, nullptr, nullptr, g_q2a, g_q2b, blockIdx.x & 1, blockIdx.x >> 1, smem_dyn);
}

// ---------------- host launch ----------------
static float* sym_addr(const void* s) {
    void* p = nullptr;
    cudaGetSymbolAddress(&p, s);
    return (float*)p;
}

#define SMEM_TT ((STAGES * BM * AST + STAGES * BN * AST) * 4)
#define SMEM_64 ((STAGES * BM6 * AST * 2) * 4)

extern "C" void kernel_launch(void* const* d_in, const int* in_sizes, int n_in,
                              void* d_out, int out_size) {
    const float* lm_X    = (const float*)d_in[0];
    const float* lm_Y    = (const float*)d_in[1];
    const float* tg_X    = (const float*)d_in[2];
    const float* lm_delay= (const float*)d_in[4];
    const float* tg_delay= (const float*)d_in[5];
    const float* aq_w    = (const float*)d_in[6];
    const float* aq_b    = (const float*)d_in[7];
    const float* ak_w    = (const float*)d_in[8];
    const float* ak_b    = (const float*)d_in[9];
    const float* w1_w    = (const float*)d_in[10];
    const float* w1_b    = (const float*)d_in[11];
    const float* w2_w    = (const float*)d_in[12];
    const float* w2_b    = (const float*)d_in[13];
    const float* pq_w    = (const float*)d_in[14];
    const float* pq_b    = (const float*)d_in[15];
    const float* pk_w    = (const float*)d_in[16];
    const float* pk_b    = (const float*)d_in[17];
    const float* pv_w    = (const float*)d_in[18];
    const float* pv_b    = (const float*)d_in[19];
    const float* gamma1  = (const float*)d_in[20];
    const float* gamma2  = (const float*)d_in[21];
    const float* gamma3  = (const float*)d_in[22];
    const float* alpha   = (const float*)d_in[23];
    const float* beta    = (const float*)d_in[24];
    float* out = (float*)d_out;

    float* pk12  = sym_addr(g_k12);
    float* pq    = sym_addr(g_q);
    float* pq2   = sym_addr(g_q2);
    float* pS    = sym_addr(g_S);
    float* plmfT = sym_addr(g_lmfT);
    float* pPart = sym_addr(g_part);

    cudaFuncSetAttribute(mma_gemm, cudaFuncAttributeMaxDynamicSharedMemorySize, SMEM_TT);
    cudaFuncSetAttribute(k_score2, cudaFuncAttributeMaxDynamicSharedMemorySize, SMEM_TT);
    cudaFuncSetAttribute(k_front,  cudaFuncAttributeMaxDynamicSharedMemorySize, SMEM_64);
    cudaFuncSetAttribute(k_f1,     cudaFuncAttributeMaxDynamicSharedMemorySize, SMEM_64);
    cudaFuncSetAttribute(k_mid,    cudaFuncAttributeMaxDynamicSharedMemorySize, SMEM_64);
    cudaFuncSetAttribute(k_q2fin,  cudaFuncAttributeMaxDynamicSharedMemorySize, SMEM_64);

    dim3 blk(256), blk64(128);

    // 1. front mega-kernel: projections (k1,k2,q,q2a) + transpose + prep
    k_front<<<BF_TOT, blk64, SMEM_64>>>(lm_X, lm_Y, tg_X, ak_w, ak_b, pk_w, pk_b,
                                        aq_w, aq_b, pq_w, pq_b, lm_delay, tg_delay,
                                        gamma1, gamma2, gamma3, alpha, beta,
                                        pv_w, pv_b, out);

    // 2. scores1 = q @ k1^T
    mma_gemm<<<dim3(32, 16, 1), blk, SMEM_TT>>>(pq, DZ, pk12, 2 * DZ, pS, N1, N2, N1, DZ, INV_TEMP);

    // 3. softmax -> attr + fused attr@lm_Y (+ router combine)
    k_attr<<<N2 + 1, blk>>>(lm_Y);

    // 4. attr @ lmfT[:256] (BTRANS, vectorized), split-4
    mma_gemm<<<dim3(2, 16, 4), blk, SMEM_TT>>>(pS, N1, plmfT, N1, pPart, PD, N2, PD, N1, 1.f);

    // 5. fused reduce + prop0 (+ router1 block)
    k_fuse1<<<2065, blk>>>(pPart, tg_X, w1_w, w1_b);

    // 6. f1 -> out, fused prop1
    k_f1<<<160, blk64, SMEM_64>>>(w1_w, w1_b, out);

    // 7. batched f2 + q2b
    k_mid<<<224, blk64, SMEM_64>>>(w2_w, w2_b, pq_w, out);

    // 8. q2 = q2a + q2b + q2c
    k_q2fin<<<64, blk64, SMEM_64>>>(pq_w, out);

    // 9-10. attention 2 fused
    k_score2<<<dim3(32, 16, 1), blk, SMEM_TT>>>(pq2, DZ, pk12 + DZ, 2 * DZ, pPart, DZ);
    k_comb2<<<8, blk>>>(pPart, out);
}